// round 1
// baseline (speedup 1.0000x reference)
#include <cuda_runtime.h>
#include <math.h>

namespace {
constexpr int Bn  = 16;
constexpr int Cn  = 256;
constexpr int HWn = 4096;
constexpr int NHn = 8;
constexpr int Mn  = Bn * HWn;          // 65536 rows
constexpr float EPSF  = 1e-5f;
constexpr float SCALE = 0.17677669529663687f;  // 32^-0.5
}

// ---------------- workspace (device globals; no allocation allowed) --------
__device__ float g_T1 [(size_t)Mn * Cn];
__device__ float g_T2 [(size_t)Mn * Cn];
__device__ float g_P1 [(size_t)Mn * 2 * Cn];
__device__ float g_P2 [(size_t)Mn * 2 * Cn];
__device__ float g_KV1[(size_t)Mn * 2 * Cn];
__device__ float g_KV2[(size_t)Mn * 2 * Cn];
__device__ float g_MRG[(size_t)Mn * 2 * Cn];
__device__ float g_RES[(size_t)Mn * Cn];
__device__ float g_E1 [(size_t)Mn * Cn];
__device__ float g_E2 [(size_t)Mn * Cn];
__device__ float g_PART[(size_t)Bn * NHn * 8 * 32 * 32];
__device__ float g_CTX1[(size_t)Bn * NHn * 32 * 32];
__device__ float g_CTX2[(size_t)Bn * NHn * 32 * 32];
__device__ float g_SC1[Cn];
__device__ float g_SH1[Cn];
__device__ float g_SC2[Cn];
__device__ float g_SH2[Cn];

// ---------------- transpose: x [B,C,HW] -> T [B,HW,C] ----------------------
__global__ void transpose_k(const float* __restrict__ x, float* __restrict__ t)
{
    __shared__ float s[32][33];
    const int b  = blockIdx.z;
    const int c0 = blockIdx.y * 32;
    const int n0 = blockIdx.x * 32;
    const float* xb = x + (size_t)b * Cn * HWn;
    float*       tb = t + (size_t)b * HWn * Cn;
    const int tx = threadIdx.x, ty = threadIdx.y;  // 32 x 8
    #pragma unroll
    for (int i = 0; i < 32; i += 8)
        s[ty + i][tx] = xb[(size_t)(c0 + ty + i) * HWn + n0 + tx];
    __syncthreads();
    #pragma unroll
    for (int i = 0; i < 32; i += 8)
        tb[(size_t)(n0 + ty + i) * Cn + c0 + tx] = s[tx][ty + i];
}

// ---------------- generic fp32 GEMM: out = X @ W^T (+bias)(+relu) ----------
// X: [M=65536, K] row-major (row stride ldx, column offset xco), or NCHW
//    ([b, k, hw] with b=m>>12, hw=m&4095) when IN_NCHW.
// W: [Nout, K] row-major.  out: row-major [M, ldout] or NCHW [b, n, hw].
template<bool IN_NCHW, bool OUT_NCHW, bool BIAS, bool RELU>
__global__ void __launch_bounds__(256)
gemm_k(const float* __restrict__ X, int ldx, int xco,
       const float* __restrict__ W, const float* __restrict__ bias,
       float* __restrict__ out, int ldout, int K, int Nout)
{
    __shared__ float As[8][128];
    __shared__ float Bs[8][128];
    const int t   = threadIdx.x;
    const int m0  = blockIdx.y * 128;
    const int n0  = blockIdx.x * 128;
    const int tm0 = (t >> 4) * 8;
    const int tn0 = (t & 15) * 8;

    float acc[8][8];
    #pragma unroll
    for (int i = 0; i < 8; i++)
        #pragma unroll
        for (int j = 0; j < 8; j++) acc[i][j] = 0.f;

    for (int k0 = 0; k0 < K; k0 += 8) {
        if (IN_NCHW) {
            const int kk = t >> 5;
            const int mm = (t & 31) * 4;
            const int m  = m0 + mm;
            const int bb = m >> 12, hw = m & 4095;
            float4 v = *reinterpret_cast<const float4*>(
                &X[((size_t)bb * K + (k0 + kk)) * HWn + hw]);
            *reinterpret_cast<float4*>(&As[kk][mm]) = v;
        } else {
            const int mm = t >> 1;
            const int kq = (t & 1) * 4;
            float4 v = *reinterpret_cast<const float4*>(
                &X[(size_t)(m0 + mm) * ldx + xco + k0 + kq]);
            As[kq + 0][mm] = v.x; As[kq + 1][mm] = v.y;
            As[kq + 2][mm] = v.z; As[kq + 3][mm] = v.w;
        }
        {
            const int nn = t >> 1;
            const int kq = (t & 1) * 4;
            float4 v = *reinterpret_cast<const float4*>(
                &W[(size_t)(n0 + nn) * K + k0 + kq]);
            Bs[kq + 0][nn] = v.x; Bs[kq + 1][nn] = v.y;
            Bs[kq + 2][nn] = v.z; Bs[kq + 3][nn] = v.w;
        }
        __syncthreads();
        #pragma unroll
        for (int k = 0; k < 8; k++) {
            float a[8], b[8];
            *reinterpret_cast<float4*>(&a[0]) = *reinterpret_cast<float4*>(&As[k][tm0]);
            *reinterpret_cast<float4*>(&a[4]) = *reinterpret_cast<float4*>(&As[k][tm0 + 4]);
            *reinterpret_cast<float4*>(&b[0]) = *reinterpret_cast<float4*>(&Bs[k][tn0]);
            *reinterpret_cast<float4*>(&b[4]) = *reinterpret_cast<float4*>(&Bs[k][tn0 + 4]);
            #pragma unroll
            for (int i = 0; i < 8; i++)
                #pragma unroll
                for (int j = 0; j < 8; j++)
                    acc[i][j] = fmaf(a[i], b[j], acc[i][j]);
        }
        __syncthreads();
    }

    #pragma unroll
    for (int i = 0; i < 8; i++) {
        const int m = m0 + tm0 + i;
        #pragma unroll
        for (int j = 0; j < 8; j += 4) {
            float v[4];
            #pragma unroll
            for (int q = 0; q < 4; q++) {
                float z = acc[i][j + q];
                const int n = n0 + tn0 + j + q;
                if (BIAS) z += bias[n];
                if (RELU) z = fmaxf(z, 0.f);
                v[q] = z;
            }
            if (OUT_NCHW) {
                const int bb = m >> 12, hw = m & 4095;
                #pragma unroll
                for (int q = 0; q < 4; q++) {
                    const int n = n0 + tn0 + j + q;
                    out[((size_t)bb * Nout + n) * HWn + hw] = v[q];
                }
            } else {
                float4 f4 = make_float4(v[0], v[1], v[2], v[3]);
                *reinterpret_cast<float4*>(&out[(size_t)m * ldout + n0 + tn0 + j]) = f4;
            }
        }
    }
}

// ------------- ctx partial: per (chunk,h,b) compute K^T V over 512 rows ----
__global__ void __launch_bounds__(64)
ctx_partial_k(const float* __restrict__ KV, float* __restrict__ part)
{
    __shared__ float Ks[64][32];
    __shared__ float Vs[64][32];
    const int chunk = blockIdx.x, h = blockIdx.y, b = blockIdx.z;
    const int t = threadIdx.x, lane = t & 31, w = t >> 5;
    const float* base = KV + (size_t)b * HWn * 512;
    const int d0 = (t >> 3) * 4, e0 = (t & 7) * 4;
    float acc[4][4] = {};
    for (int nb = 0; nb < 512; nb += 64) {
        const int row0 = chunk * 512 + nb;
        for (int r = w; r < 64; r += 2) {
            const float* rp = base + (size_t)(row0 + r) * 512 + h * 32;
            Ks[r][lane] = rp[lane];
            Vs[r][lane] = rp[256 + lane];
        }
        __syncthreads();
        #pragma unroll 8
        for (int n = 0; n < 64; n++) {
            float4 k4 = *reinterpret_cast<float4*>(&Ks[n][d0]);
            float4 v4 = *reinterpret_cast<float4*>(&Vs[n][e0]);
            const float kk[4] = {k4.x, k4.y, k4.z, k4.w};
            const float vv[4] = {v4.x, v4.y, v4.z, v4.w};
            #pragma unroll
            for (int i = 0; i < 4; i++)
                #pragma unroll
                for (int j = 0; j < 4; j++)
                    acc[i][j] = fmaf(kk[i], vv[j], acc[i][j]);
        }
        __syncthreads();
    }
    float* p = part + ((size_t)(b * NHn + h) * 8 + chunk) * 1024;
    #pragma unroll
    for (int i = 0; i < 4; i++)
        #pragma unroll
        for (int j = 0; j < 4; j++)
            p[(d0 + i) * 32 + e0 + j] = acc[i][j];
}

// ------------- ctx finalize: sum partials, scale, softmax over d -----------
__global__ void ctx_final_k(const float* __restrict__ part, float* __restrict__ ctx)
{
    __shared__ float S[32][33];
    const int bh = blockIdx.x;
    const int t  = threadIdx.x;
    const float* p = part + (size_t)bh * 8 * 1024;
    for (int idx = t; idx < 1024; idx += 256) {
        float s = 0.f;
        #pragma unroll
        for (int c = 0; c < 8; c++) s += p[c * 1024 + idx];
        S[idx >> 5][idx & 31] = s * SCALE;
    }
    __syncthreads();
    if (t < 32) {
        float mx = -1e30f;
        #pragma unroll
        for (int d = 0; d < 32; d++) mx = fmaxf(mx, S[d][t]);
        float e[32], sum = 0.f;
        #pragma unroll
        for (int d = 0; d < 32; d++) { e[d] = expf(S[d][t] - mx); sum += e[d]; }
        const float inv = 1.f / sum;
        float* o = ctx + (size_t)bh * 1024;
        #pragma unroll
        for (int d = 0; d < 32; d++) o[d * 32 + t] = e[d] * inv;
    }
}

// ------------- apply ctx in-place: P[:,256:512] = heads(u) @ ctx -----------
__global__ void __launch_bounds__(256)
apply_ctx_k(float* __restrict__ P, const float* __restrict__ ctx)
{
    __shared__ float Us[8][257];
    __shared__ float Cx[8][32][32];
    const int b   = blockIdx.y;
    const int r0g = blockIdx.x * 8;
    float* Pb = P + ((size_t)b * HWn + r0g) * 512;
    const float* cb = ctx + (size_t)b * 8192;
    for (int i = threadIdx.x; i < 8192; i += 256)
        (&Cx[0][0][0])[i] = cb[i];
    for (int i = threadIdx.x; i < 8 * 256; i += 256) {
        const int r = i >> 8, c = i & 255;
        Us[r][c] = Pb[(size_t)r * 512 + 256 + c];
    }
    __syncthreads();
    const int t = threadIdx.x;
    const int h = t >> 5, sub = t & 31;
    const int r0 = (sub >> 3) * 2;
    const int e0 = (sub & 7) * 4;
    float acc[2][4] = {};
    #pragma unroll
    for (int d = 0; d < 32; d++) {
        float4 c4 = *reinterpret_cast<float4*>(&Cx[h][d][e0]);
        #pragma unroll
        for (int i = 0; i < 2; i++) {
            const float u = Us[r0 + i][h * 32 + d];
            acc[i][0] = fmaf(u, c4.x, acc[i][0]);
            acc[i][1] = fmaf(u, c4.y, acc[i][1]);
            acc[i][2] = fmaf(u, c4.z, acc[i][2]);
            acc[i][3] = fmaf(u, c4.w, acc[i][3]);
        }
    }
    #pragma unroll
    for (int i = 0; i < 2; i++) {
        float4 v = make_float4(acc[i][0], acc[i][1], acc[i][2], acc[i][3]);
        *reinterpret_cast<float4*>(&Pb[(size_t)(r0 + i) * 512 + 256 + h * 32 + e0]) = v;
    }
}

// ------------- LayerNorm: merge[:,mco:mco+256] = LN(T + EP)*g + b ----------
__global__ void __launch_bounds__(256)
ln_k(const float* __restrict__ T, const float* __restrict__ EP,
     const float* __restrict__ g, const float* __restrict__ be,
     float* __restrict__ merge, int mco)
{
    const int w    = blockIdx.x * 8 + (threadIdx.x >> 5);
    const int lane = threadIdx.x & 31;
    const float* tr = T  + (size_t)w * 256;
    const float* er = EP + (size_t)w * 256;
    float v[8], sum = 0.f, sq = 0.f;
    #pragma unroll
    for (int i = 0; i < 8; i++) {
        const float x = tr[lane + i * 32] + er[lane + i * 32];
        v[i] = x; sum += x; sq += x * x;
    }
    #pragma unroll
    for (int o = 16; o; o >>= 1) {
        sum += __shfl_xor_sync(0xffffffffu, sum, o);
        sq  += __shfl_xor_sync(0xffffffffu, sq,  o);
    }
    const float mean = sum * (1.f / 256.f);
    const float var  = sq * (1.f / 256.f) - mean * mean;
    const float rs   = rsqrtf(var + EPSF);
    float* mr = merge + (size_t)w * 512 + mco;
    #pragma unroll
    for (int i = 0; i < 8; i++) {
        const int c = lane + i * 32;
        mr[c] = (v[i] - mean) * rs * g[c] + be[c];
    }
}

// ------------- 3x3 depthwise conv (SAME, zero pad) + bias + relu -----------
__global__ void __launch_bounds__(256)
dw_k(const float* __restrict__ X, const float* __restrict__ w9,
     const float* __restrict__ db, float* __restrict__ Y)
{
    __shared__ float s[66][66];
    const int bc = blockIdx.x;
    const int c  = bc % Cn;
    const float* in = X + (size_t)bc * HWn;
    for (int i = threadIdx.x; i < 66 * 66; i += 256) {
        const int yy = i / 66 - 1, xx = i % 66 - 1;
        s[i / 66][i % 66] =
            (yy >= 0 && yy < 64 && xx >= 0 && xx < 64) ? in[yy * 64 + xx] : 0.f;
    }
    float k[9];
    #pragma unroll
    for (int j = 0; j < 9; j++) k[j] = w9[c * 9 + j];
    const float bias = db[c];
    __syncthreads();
    float* outp = Y + (size_t)bc * HWn;
    for (int idx = threadIdx.x; idx < 4096; idx += 256) {
        const int y = idx >> 6, x = idx & 63;
        float a = 0.f;
        #pragma unroll
        for (int ky = 0; ky < 3; ky++)
            #pragma unroll
            for (int kx = 0; kx < 3; kx++)
                a = fmaf(s[y + ky][x + kx], k[ky * 3 + kx], a);
        outp[idx] = fmaxf(a + bias, 0.f);
    }
}

// ------------- BN stats: per-channel mean/var over (B,HW), training mode ---
__global__ void __launch_bounds__(256)
bn_stats_k(const float* __restrict__ X, const float* __restrict__ g,
           const float* __restrict__ be, float* __restrict__ scale,
           float* __restrict__ shift)
{
    const int c = blockIdx.x;
    const int t = threadIdx.x;
    double s = 0.0, sq = 0.0;
    for (int b = 0; b < Bn; b++) {
        const float* p = X + ((size_t)b * Cn + c) * HWn;
        for (int i = t; i < HWn; i += 256) {
            const float x = p[i];
            s += x; sq += (double)x * x;
        }
    }
    __shared__ double sm[256];
    __shared__ double sm2[256];
    sm[t] = s; sm2[t] = sq;
    __syncthreads();
    for (int o = 128; o; o >>= 1) {
        if (t < o) { sm[t] += sm[t + o]; sm2[t] += sm2[t + o]; }
        __syncthreads();
    }
    if (t == 0) {
        const double inv = 1.0 / (double)(Bn * HWn);
        const double m   = sm[0] * inv;
        const double var = sm2[0] * inv - m * m;
        const float sc = g[c] * rsqrtf((float)var + EPSF);
        scale[c] = sc;
        shift[c] = be[c] - (float)m * sc;
    }
}

// ------------- F = RES + E*scale + shift  (bn1 applied + residual add) -----
__global__ void addbn_k(const float* __restrict__ R, const float* __restrict__ E,
                        const float* __restrict__ sc, const float* __restrict__ sh,
                        float* __restrict__ F)
{
    const int i4 = blockIdx.x * 256 + threadIdx.x;
    const int c  = (i4 >> 10) & 255;
    const float s = sc[c], hh = sh[c];
    const float4 r = reinterpret_cast<const float4*>(R)[i4];
    const float4 e = reinterpret_cast<const float4*>(E)[i4];
    float4 f;
    f.x = fmaf(e.x, s, r.x + hh);
    f.y = fmaf(e.y, s, r.y + hh);
    f.z = fmaf(e.z, s, r.z + hh);
    f.w = fmaf(e.w, s, r.w + hh);
    reinterpret_cast<float4*>(F)[i4] = f;
}

// ------------- out = F*scale + shift  (bn2 applied) -------------------------
__global__ void bn_apply_k(const float* __restrict__ F, const float* __restrict__ sc,
                           const float* __restrict__ sh, float* __restrict__ O)
{
    const int i4 = blockIdx.x * 256 + threadIdx.x;
    const int c  = (i4 >> 10) & 255;
    const float s = sc[c], hh = sh[c];
    const float4 f = reinterpret_cast<const float4*>(F)[i4];
    float4 o;
    o.x = fmaf(f.x, s, hh);
    o.y = fmaf(f.y, s, hh);
    o.z = fmaf(f.z, s, hh);
    o.w = fmaf(f.w, s, hh);
    reinterpret_cast<float4*>(O)[i4] = o;
}

// ===========================================================================
extern "C" void kernel_launch(void* const* d_in, const int* in_sizes, int n_in,
                              void* d_out, int out_size)
{
    (void)in_sizes; (void)n_in; (void)out_size;
    const float* x1    = (const float*)d_in[0];
    const float* x2    = (const float*)d_in[1];
    const float* cp1_w = (const float*)d_in[2];
    const float* cp1_b = (const float*)d_in[3];
    const float* cp2_w = (const float*)d_in[4];
    const float* cp2_b = (const float*)d_in[5];
    const float* kv1_w = (const float*)d_in[6];
    const float* kv2_w = (const float*)d_in[7];
    const float* ep1_w = (const float*)d_in[8];
    const float* ep1_b = (const float*)d_in[9];
    const float* ep2_w = (const float*)d_in[10];
    const float* ep2_b = (const float*)d_in[11];
    const float* ln1_g = (const float*)d_in[12];
    const float* ln1_b = (const float*)d_in[13];
    const float* ln2_g = (const float*)d_in[14];
    const float* ln2_b = (const float*)d_in[15];
    const float* res_w = (const float*)d_in[16];
    const float* ce1_w = (const float*)d_in[17];
    const float* ce1_b = (const float*)d_in[18];
    const float* dw_w  = (const float*)d_in[19];
    const float* dw_b  = (const float*)d_in[20];
    const float* ce3_w = (const float*)d_in[21];
    const float* ce3_b = (const float*)d_in[22];
    const float* bn1_g = (const float*)d_in[23];
    const float* bn1_b = (const float*)d_in[24];
    const float* bn2_g = (const float*)d_in[25];
    const float* bn2_b = (const float*)d_in[26];

    float *T1, *T2, *P1, *P2, *KV1, *KV2, *MRG, *RES, *E1, *E2;
    float *PART, *CTX1, *CTX2, *SC1, *SH1, *SC2, *SH2;
    cudaGetSymbolAddress((void**)&T1,  g_T1);
    cudaGetSymbolAddress((void**)&T2,  g_T2);
    cudaGetSymbolAddress((void**)&P1,  g_P1);
    cudaGetSymbolAddress((void**)&P2,  g_P2);
    cudaGetSymbolAddress((void**)&KV1, g_KV1);
    cudaGetSymbolAddress((void**)&KV2, g_KV2);
    cudaGetSymbolAddress((void**)&MRG, g_MRG);
    cudaGetSymbolAddress((void**)&RES, g_RES);
    cudaGetSymbolAddress((void**)&E1,  g_E1);
    cudaGetSymbolAddress((void**)&E2,  g_E2);
    cudaGetSymbolAddress((void**)&PART, g_PART);
    cudaGetSymbolAddress((void**)&CTX1, g_CTX1);
    cudaGetSymbolAddress((void**)&CTX2, g_CTX2);
    cudaGetSymbolAddress((void**)&SC1, g_SC1);
    cudaGetSymbolAddress((void**)&SH1, g_SH1);
    cudaGetSymbolAddress((void**)&SC2, g_SC2);
    cudaGetSymbolAddress((void**)&SH2, g_SH2);

    const dim3 tpb_t(32, 8);
    transpose_k<<<dim3(128, 8, 16), tpb_t>>>(x1, T1);
    transpose_k<<<dim3(128, 8, 16), tpb_t>>>(x2, T2);

    const dim3 g512(4, 512);   // Nout=512
    const dim3 g256(2, 512);   // Nout=256

    // CrossPath projections: P = relu(T @ cp_w^T + cp_b)   [M,512]
    gemm_k<false, false, true,  true ><<<g512, 256>>>(T1, 256, 0, cp1_w, cp1_b, P1, 512, 256, 512);
    gemm_k<false, false, true,  true ><<<g512, 256>>>(T2, 256, 0, cp2_w, cp2_b, P2, 512, 256, 512);

    // KV = u @ kv_w^T (u = P[:,256:512])                    [M,512]
    gemm_k<false, false, false, false><<<g512, 256>>>(P1, 512, 256, kv1_w, nullptr, KV1, 512, 256, 512);
    gemm_k<false, false, false, false><<<g512, 256>>>(P2, 512, 256, kv2_w, nullptr, KV2, 512, 256, 512);

    // ctx = softmax_d(scale * K^T V)  per (b,h)
    ctx_partial_k<<<dim3(8, 8, 16), 64>>>(KV1, PART);
    ctx_final_k<<<128, 256>>>(PART, CTX1);
    ctx_partial_k<<<dim3(8, 8, 16), 64>>>(KV2, PART);
    ctx_final_k<<<128, 256>>>(PART, CTX2);

    // a = heads(u) @ ctx (cross: P1 uses ctx2, P2 uses ctx1), in-place on u half
    apply_ctx_k<<<dim3(512, 16), 256>>>(P1, CTX2);
    apply_ctx_k<<<dim3(512, 16), 256>>>(P2, CTX1);

    // end projections: EP = [y|a] @ ep_w^T + ep_b           [M,256] (into KV buffers)
    gemm_k<false, false, true,  false><<<g256, 256>>>(P1, 512, 0, ep1_w, ep1_b, KV1, 256, 512, 256);
    gemm_k<false, false, true,  false><<<g256, 256>>>(P2, 512, 0, ep2_w, ep2_b, KV2, 256, 512, 256);

    // o = LN(T + EP)  -> MERGE halves
    ln_k<<<8192, 256>>>(T1, KV1, ln1_g, ln1_b, MRG, 0);
    ln_k<<<8192, 256>>>(T2, KV2, ln2_g, ln2_b, MRG, 256);

    // ChannelEmbed 1x1 convs (outputs in NCHW)
    gemm_k<false, true, false, false><<<g256, 256>>>(MRG, 512, 0, res_w, nullptr, RES, 0, 512, 256);
    gemm_k<false, true, true,  false><<<g256, 256>>>(MRG, 512, 0, ce1_w, ce1_b,   E1,  0, 512, 256);

    // 3x3 depthwise + bias + relu
    dw_k<<<4096, 256>>>(E1, dw_w, dw_b, E2);

    // ce3 1x1 conv (NCHW in/out), writes into E1 (free)
    gemm_k<true, true, true, false><<<g256, 256>>>(E2, 0, 0, ce3_w, ce3_b, E1, 0, 256, 256);

    // bn1 stats + apply fused with residual add; then bn2 stats + apply
    bn_stats_k<<<256, 256>>>(E1, bn1_g, bn1_b, SC1, SH1);
    addbn_k<<<16384, 256>>>(RES, E1, SC1, SH1, E2);
    bn_stats_k<<<256, 256>>>(E2, bn2_g, bn2_b, SC2, SH2);
    bn_apply_k<<<16384, 256>>>(E2, SC2, SH2, (float*)d_out);
}

// round 3
// speedup vs baseline: 2.0968x; 2.0968x over previous
#include <cuda_runtime.h>
#include <cuda_bf16.h>
#include <math.h>
#include <stdint.h>

namespace {
constexpr int Bn  = 16;
constexpr int Cn  = 256;
constexpr int HWn = 4096;
constexpr int NHn = 8;
constexpr int Mn  = Bn * HWn;          // 65536 rows
constexpr float EPSF  = 1e-5f;
constexpr float SCALE = 0.17677669529663687f;  // 32^-0.5

// GEMM tiling: CTA 128x128, K-stage 32, rows padded to 80B for conflict-free ldmatrix
constexpr int ROWB   = 80;             // bytes per 32-bf16 row in smem
constexpr int MATB   = 128 * ROWB;     // 10240 bytes per matrix tile
constexpr int STAGEB = 4 * MATB;       // AH | AL | BH | BL = 40960
constexpr int DYN_SMEM = 2 * STAGEB;   // 81920
}

// ---------------- workspace (device globals; no allocation allowed) --------
__device__ float g_T1 [(size_t)Mn * Cn];
__device__ float g_T2 [(size_t)Mn * Cn];
__device__ __nv_bfloat16 g_T1h[(size_t)Mn * Cn];
__device__ __nv_bfloat16 g_T1l[(size_t)Mn * Cn];
__device__ __nv_bfloat16 g_T2h[(size_t)Mn * Cn];
__device__ __nv_bfloat16 g_T2l[(size_t)Mn * Cn];
__device__ __nv_bfloat16 g_P1h[(size_t)Mn * 2 * Cn];
__device__ __nv_bfloat16 g_P1l[(size_t)Mn * 2 * Cn];
__device__ __nv_bfloat16 g_P2h[(size_t)Mn * 2 * Cn];
__device__ __nv_bfloat16 g_P2l[(size_t)Mn * 2 * Cn];
__device__ float g_KV1[(size_t)Mn * 2 * Cn];
__device__ float g_KV2[(size_t)Mn * 2 * Cn];
__device__ float g_EP1[(size_t)Mn * Cn];
__device__ float g_EP2[(size_t)Mn * Cn];
__device__ __nv_bfloat16 g_MRGh[(size_t)Mn * 2 * Cn];
__device__ __nv_bfloat16 g_MRGl[(size_t)Mn * 2 * Cn];
__device__ float g_RES[(size_t)Mn * Cn];
__device__ float g_CE1[(size_t)Mn * Cn];
__device__ __nv_bfloat16 g_DWh[(size_t)Mn * Cn];
__device__ __nv_bfloat16 g_DWl[(size_t)Mn * Cn];
__device__ float g_E  [(size_t)Mn * Cn];
__device__ float g_F  [(size_t)Mn * Cn];
__device__ __nv_bfloat16 g_WH[1200000];
__device__ __nv_bfloat16 g_WL[1200000];
__device__ float g_PART[(size_t)Bn * NHn * 8 * 32 * 32];
__device__ float g_CTX1[(size_t)Bn * NHn * 32 * 32];
__device__ float g_CTX2[(size_t)Bn * NHn * 32 * 32];
__device__ float g_BNP[256 * 512];
__device__ float g_SC1[Cn];
__device__ float g_SH1[Cn];
__device__ float g_SC2[Cn];
__device__ float g_SH2[Cn];

// ---------------- PTX helpers ----------------------------------------------
__device__ __forceinline__ uint32_t smem_u32(const void* p) {
    uint32_t a;
    asm("{ .reg .u64 t; cvta.to.shared.u64 t, %1; cvt.u32.u64 %0, t; }"
        : "=r"(a) : "l"(p));
    return a;
}

__device__ __forceinline__ void cpasync16(uint32_t dst, const void* src) {
    asm volatile("cp.async.cg.shared.global [%0], [%1], 16;"
                 :: "r"(dst), "l"(src));
}

__device__ __forceinline__ void ldsm4(uint32_t* r, uint32_t addr) {
    asm volatile("ldmatrix.sync.aligned.m8n8.x4.shared.b16 {%0,%1,%2,%3}, [%4];"
                 : "=r"(r[0]), "=r"(r[1]), "=r"(r[2]), "=r"(r[3]) : "r"(addr));
}

__device__ __forceinline__ void mma16816(float* d, const uint32_t* a, const uint32_t* b) {
    asm volatile(
        "mma.sync.aligned.m16n8k16.row.col.f32.bf16.bf16.f32 "
        "{%0,%1,%2,%3}, {%4,%5,%6,%7}, {%8,%9}, {%0,%1,%2,%3};"
        : "+f"(d[0]), "+f"(d[1]), "+f"(d[2]), "+f"(d[3])
        : "r"(a[0]), "r"(a[1]), "r"(a[2]), "r"(a[3]), "r"(b[0]), "r"(b[1]));
}

__device__ __forceinline__ void split2(float v, __nv_bfloat16& h, __nv_bfloat16& l) {
    h = __float2bfloat16(v);
    l = __float2bfloat16(v - __bfloat162float(h));
}

// ---------------- transpose + split: x [B,C,HW] -> T fp32 + hi/lo [B,HW,C] --
__global__ void transpose_split_k(const float* __restrict__ x, float* __restrict__ t,
                                  __nv_bfloat16* __restrict__ th, __nv_bfloat16* __restrict__ tl)
{
    __shared__ float s[32][33];
    const int b  = blockIdx.z;
    const int c0 = blockIdx.y * 32;
    const int n0 = blockIdx.x * 32;
    const float* xb = x + (size_t)b * Cn * HWn;
    const int tx = threadIdx.x, ty = threadIdx.y;  // 32 x 8
    #pragma unroll
    for (int i = 0; i < 32; i += 8)
        s[ty + i][tx] = xb[(size_t)(c0 + ty + i) * HWn + n0 + tx];
    __syncthreads();
    #pragma unroll
    for (int i = 0; i < 32; i += 8) {
        const size_t idx = ((size_t)b * HWn + n0 + ty + i) * Cn + c0 + tx;
        const float v = s[tx][ty + i];
        t[idx] = v;
        __nv_bfloat16 h, l; split2(v, h, l);
        th[idx] = h; tl[idx] = l;
    }
}

// ---------------- weight split: fp32 -> bf16 hi/lo --------------------------
__global__ void wsplit_k(const float* __restrict__ src, __nv_bfloat16* __restrict__ h,
                         __nv_bfloat16* __restrict__ l, int n)
{
    const int i = blockIdx.x * 256 + threadIdx.x;
    if (i < n) {
        __nv_bfloat16 hh, ll; split2(src[i], hh, ll);
        h[i] = hh; l[i] = ll;
    }
}

// ---------------- HMMA split-bf16 GEMM ---------------------------------------
// out[m, n] = sum_k A[m, k] * W[n, k]; A = Ah+Al, W = Wh+Wl (3-product split).
// CTA tile 128x128, K staged 32 (rows padded to 80B), double buffered cp.async.
__device__ __forceinline__ void load_stage(
    uint32_t sb, int m0, int n0, int k0,
    const __nv_bfloat16* Ah, const __nv_bfloat16* Al, int lda,
    const __nv_bfloat16* Wh, const __nv_bfloat16* Wl, int K, int tid)
{
    #pragma unroll
    for (int j = 0; j < 2; j++) {                       // A: 512 16B chunks / matrix
        const int idx = j * 256 + tid;
        const int r = idx >> 2, c = idx & 3;
        const uint32_t dst = sb + r * ROWB + c * 16;
        const size_t so = (size_t)(m0 + r) * lda + k0 + c * 8;
        cpasync16(dst,        Ah + so);
        cpasync16(dst + MATB, Al + so);
    }
    #pragma unroll
    for (int j = 0; j < 2; j++) {                       // B: 512 16B chunks / matrix
        const int idx = j * 256 + tid;
        const int r = idx >> 2, c = idx & 3;
        const uint32_t dst = sb + 2 * MATB + r * ROWB + c * 16;
        const size_t so = (size_t)(n0 + r) * K + k0 + c * 8;
        cpasync16(dst,        Wh + so);
        cpasync16(dst + MATB, Wl + so);
    }
}

template<bool BIAS, bool RELU, bool OUTF, bool OUTB>
__global__ void __launch_bounds__(256, 1)
gemm_tc(const __nv_bfloat16* __restrict__ Ah, const __nv_bfloat16* __restrict__ Al, int lda,
        const __nv_bfloat16* __restrict__ Wh, const __nv_bfloat16* __restrict__ Wl,
        const float* __restrict__ bias,
        float* __restrict__ outF,
        __nv_bfloat16* __restrict__ outH, __nv_bfloat16* __restrict__ outL,
        int K, int Nout)
{
    extern __shared__ char dyn_smem[];
    const int tid  = threadIdx.x;
    const int wid  = tid >> 5;
    const int lane = tid & 31;
    const int m0 = blockIdx.y * 128;
    const int n0 = blockIdx.x * 128;
    const int wm0 = (wid & 1) * 64;    // warp m offset (2 warps over M)
    const int wn0 = (wid >> 1) * 32;   // warp n offset (4 warps over N)

    const uint32_t base = smem_u32(dyn_smem);

    float acc[4][4][4];
    #pragma unroll
    for (int i = 0; i < 4; i++)
        #pragma unroll
        for (int j = 0; j < 4; j++)
            #pragma unroll
            for (int q = 0; q < 4; q++) acc[i][j][q] = 0.f;

    // per-lane ldmatrix base offsets (conflict-free via 80B row stride)
    const uint32_t aOff = (uint32_t)(wm0 + (lane & 15)) * ROWB + ((lane >> 4) * 16);
    const uint32_t bOff = (uint32_t)(wn0 + ((lane >> 4) * 8) + (lane & 7)) * ROWB
                        + (((lane >> 3) & 1) * 16);

    const int S = K / 32;
    load_stage(base, m0, n0, 0, Ah, Al, lda, Wh, Wl, K, tid);
    asm volatile("cp.async.commit_group;" ::: "memory");

    for (int s = 0; s < S; s++) {
        if (s + 1 < S) {
            load_stage(base + ((s + 1) & 1) * STAGEB, m0, n0, (s + 1) * 32,
                       Ah, Al, lda, Wh, Wl, K, tid);
            asm volatile("cp.async.commit_group;" ::: "memory");
            asm volatile("cp.async.wait_group 1;" ::: "memory");
        } else {
            asm volatile("cp.async.wait_group 0;" ::: "memory");
        }
        __syncthreads();
        const uint32_t sb = base + (s & 1) * STAGEB;
        #pragma unroll
        for (int ks = 0; ks < 2; ks++) {
            const uint32_t kb = ks * 32;
            uint32_t aH[4][4], aL[4][4], bH[2][4], bL[2][4];
            #pragma unroll
            for (int mi = 0; mi < 4; mi++) {
                const uint32_t ad = sb + aOff + mi * 16 * ROWB + kb;
                ldsm4(aH[mi], ad);
                ldsm4(aL[mi], ad + MATB);
            }
            #pragma unroll
            for (int np = 0; np < 2; np++) {
                const uint32_t bd = sb + 2 * MATB + bOff + np * 16 * ROWB + kb;
                ldsm4(bH[np], bd);
                ldsm4(bL[np], bd + MATB);
            }
            #pragma unroll
            for (int mi = 0; mi < 4; mi++)
                #pragma unroll
                for (int ni = 0; ni < 4; ni++)
                    mma16816(acc[mi][ni], aH[mi], &bH[ni >> 1][(ni & 1) * 2]);
            #pragma unroll
            for (int mi = 0; mi < 4; mi++)
                #pragma unroll
                for (int ni = 0; ni < 4; ni++)
                    mma16816(acc[mi][ni], aH[mi], &bL[ni >> 1][(ni & 1) * 2]);
            #pragma unroll
            for (int mi = 0; mi < 4; mi++)
                #pragma unroll
                for (int ni = 0; ni < 4; ni++)
                    mma16816(acc[mi][ni], aL[mi], &bH[ni >> 1][(ni & 1) * 2]);
        }
        __syncthreads();
    }

    // epilogue
    #pragma unroll
    for (int ni = 0; ni < 4; ni++) {
        const int cidx = n0 + wn0 + ni * 8 + (lane & 3) * 2;
        float b0 = 0.f, b1 = 0.f;
        if (BIAS) { b0 = bias[cidx]; b1 = bias[cidx + 1]; }
        #pragma unroll
        for (int mi = 0; mi < 4; mi++) {
            const int r0 = m0 + wm0 + mi * 16 + (lane >> 2);
            #pragma unroll
            for (int half = 0; half < 2; half++) {
                const int r = r0 + half * 8;
                float v0 = acc[mi][ni][half * 2 + 0];
                float v1 = acc[mi][ni][half * 2 + 1];
                if (BIAS) { v0 += b0; v1 += b1; }
                if (RELU) { v0 = fmaxf(v0, 0.f); v1 = fmaxf(v1, 0.f); }
                if (OUTF) {
                    float2 f2 = make_float2(v0, v1);
                    *reinterpret_cast<float2*>(outF + (size_t)r * Nout + cidx) = f2;
                }
                if (OUTB) {
                    __nv_bfloat16 h0, l0, h1, l1;
                    split2(v0, h0, l0); split2(v1, h1, l1);
                    __nv_bfloat162 hh; hh.x = h0; hh.y = h1;
                    __nv_bfloat162 ll; ll.x = l0; ll.y = l1;
                    *reinterpret_cast<__nv_bfloat162*>(outH + (size_t)r * Nout + cidx) = hh;
                    *reinterpret_cast<__nv_bfloat162*>(outL + (size_t)r * Nout + cidx) = ll;
                }
            }
        }
    }
}

// ------------- ctx partial: per (chunk,h,b) compute K^T V over 512 rows ----
__global__ void __launch_bounds__(64)
ctx_partial_k(const float* __restrict__ KV, float* __restrict__ part)
{
    __shared__ float Ks[64][32];
    __shared__ float Vs[64][32];
    const int chunk = blockIdx.x, h = blockIdx.y, b = blockIdx.z;
    const int t = threadIdx.x, lane = t & 31, w = t >> 5;
    const float* base = KV + (size_t)b * HWn * 512;
    const int d0 = (t >> 3) * 4, e0 = (t & 7) * 4;
    float acc[4][4] = {};
    for (int nb = 0; nb < 512; nb += 64) {
        const int row0 = chunk * 512 + nb;
        for (int r = w; r < 64; r += 2) {
            const float* rp = base + (size_t)(row0 + r) * 512 + h * 32;
            Ks[r][lane] = rp[lane];
            Vs[r][lane] = rp[256 + lane];
        }
        __syncthreads();
        #pragma unroll 8
        for (int n = 0; n < 64; n++) {
            float4 k4 = *reinterpret_cast<float4*>(&Ks[n][d0]);
            float4 v4 = *reinterpret_cast<float4*>(&Vs[n][e0]);
            const float kk[4] = {k4.x, k4.y, k4.z, k4.w};
            const float vv[4] = {v4.x, v4.y, v4.z, v4.w};
            #pragma unroll
            for (int i = 0; i < 4; i++)
                #pragma unroll
                for (int j = 0; j < 4; j++)
                    acc[i][j] = fmaf(kk[i], vv[j], acc[i][j]);
        }
        __syncthreads();
    }
    float* p = part + ((size_t)(b * NHn + h) * 8 + chunk) * 1024;
    #pragma unroll
    for (int i = 0; i < 4; i++)
        #pragma unroll
        for (int j = 0; j < 4; j++)
            p[(d0 + i) * 32 + e0 + j] = acc[i][j];
}

// ------------- ctx finalize: sum partials, scale, softmax over d -----------
__global__ void ctx_final_k(const float* __restrict__ part, float* __restrict__ ctx)
{
    __shared__ float S[32][33];
    const int bh = blockIdx.x;
    const int t  = threadIdx.x;
    const float* p = part + (size_t)bh * 8 * 1024;
    for (int idx = t; idx < 1024; idx += 256) {
        float s = 0.f;
        #pragma unroll
        for (int c = 0; c < 8; c++) s += p[c * 1024 + idx];
        S[idx >> 5][idx & 31] = s * SCALE;
    }
    __syncthreads();
    if (t < 32) {
        float mx = -1e30f;
        #pragma unroll
        for (int d = 0; d < 32; d++) mx = fmaxf(mx, S[d][t]);
        float e[32], sum = 0.f;
        #pragma unroll
        for (int d = 0; d < 32; d++) { e[d] = expf(S[d][t] - mx); sum += e[d]; }
        const float inv = 1.f / sum;
        float* o = ctx + (size_t)bh * 1024;
        #pragma unroll
        for (int d = 0; d < 32; d++) o[d * 32 + t] = e[d] * inv;
    }
}

// ------------- apply ctx in-place on split P: u half -> a = heads(u) @ ctx --
__global__ void __launch_bounds__(256)
apply_ctx_k(__nv_bfloat16* __restrict__ Ph, __nv_bfloat16* __restrict__ Pl,
            const float* __restrict__ ctx)
{
    __shared__ float Us[8][257];
    __shared__ float Cx[8][32][32];
    const int b   = blockIdx.y;
    const int r0g = blockIdx.x * 8;
    const size_t pb = ((size_t)b * HWn + r0g) * 512;
    const float* cb = ctx + (size_t)b * 8192;
    for (int i = threadIdx.x; i < 8192; i += 256)
        (&Cx[0][0][0])[i] = cb[i];
    for (int i = threadIdx.x; i < 8 * 256; i += 256) {
        const int r = i >> 8, c = i & 255;
        const size_t idx = pb + (size_t)r * 512 + 256 + c;
        Us[r][c] = __bfloat162float(Ph[idx]) + __bfloat162float(Pl[idx]);
    }
    __syncthreads();
    const int t = threadIdx.x;
    const int h = t >> 5, sub = t & 31;
    const int r0 = (sub >> 3) * 2;
    const int e0 = (sub & 7) * 4;
    float acc[2][4] = {};
    #pragma unroll
    for (int d = 0; d < 32; d++) {
        float4 c4 = *reinterpret_cast<float4*>(&Cx[h][d][e0]);
        #pragma unroll
        for (int i = 0; i < 2; i++) {
            const float u = Us[r0 + i][h * 32 + d];
            acc[i][0] = fmaf(u, c4.x, acc[i][0]);
            acc[i][1] = fmaf(u, c4.y, acc[i][1]);
            acc[i][2] = fmaf(u, c4.z, acc[i][2]);
            acc[i][3] = fmaf(u, c4.w, acc[i][3]);
        }
    }
    #pragma unroll
    for (int i = 0; i < 2; i++) {
        #pragma unroll
        for (int j = 0; j < 4; j++) {
            const size_t idx = pb + (size_t)(r0 + i) * 512 + 256 + h * 32 + e0 + j;
            __nv_bfloat16 hh, ll; split2(acc[i][j], hh, ll);
            Ph[idx] = hh; Pl[idx] = ll;
        }
    }
}

// ------------- LayerNorm: MRG[:, mco..] = LN(T + EP)*g + b (split bf16) -----
__global__ void __launch_bounds__(256)
ln_k(const float* __restrict__ T, const float* __restrict__ EP,
     const float* __restrict__ g, const float* __restrict__ be,
     __nv_bfloat16* __restrict__ MH, __nv_bfloat16* __restrict__ ML, int mco)
{
    const int w    = blockIdx.x * 8 + (threadIdx.x >> 5);
    const int lane = threadIdx.x & 31;
    const float* tr = T  + (size_t)w * 256;
    const float* er = EP + (size_t)w * 256;
    float v[8], sum = 0.f, sq = 0.f;
    #pragma unroll
    for (int i = 0; i < 8; i++) {
        const float x = tr[lane + i * 32] + er[lane + i * 32];
        v[i] = x; sum += x; sq += x * x;
    }
    #pragma unroll
    for (int o = 16; o; o >>= 1) {
        sum += __shfl_xor_sync(0xffffffffu, sum, o);
        sq  += __shfl_xor_sync(0xffffffffu, sq,  o);
    }
    const float mean = sum * (1.f / 256.f);
    const float var  = sq * (1.f / 256.f) - mean * mean;
    const float rs   = rsqrtf(var + EPSF);
    const size_t ob = (size_t)w * 512 + mco;
    #pragma unroll
    for (int i = 0; i < 8; i++) {
        const int c = lane + i * 32;
        const float y = (v[i] - mean) * rs * g[c] + be[c];
        __nv_bfloat16 hh, ll; split2(y, hh, ll);
        MH[ob + c] = hh; ML[ob + c] = ll;
    }
}

// ------------- 3x3 depthwise conv on [M,C] layout + bias + relu, split out --
__global__ void __launch_bounds__(256)
dw_k(const float* __restrict__ X, const float* __restrict__ w9,
     const float* __restrict__ db, __nv_bfloat16* __restrict__ Yh,
     __nv_bfloat16* __restrict__ Yl)
{
    __shared__ float s[18 * 18 * 32];
    const int cc   = blockIdx.x;        // channel chunk (8 x 32)
    const int tile = blockIdx.y;        // 16 spatial tiles of 16x16
    const int b    = blockIdx.z;
    const int ty0 = (tile >> 2) * 16, tx0 = (tile & 3) * 16;
    const int c0 = cc * 32;
    const int tid = threadIdx.x;
    for (int i = tid; i < 18 * 18 * 32; i += 256) {
        const int c = i & 31;
        const int sp = i >> 5;
        const int x = sp % 18 - 1 + tx0;
        const int y = sp / 18 - 1 + ty0;
        float v = 0.f;
        if (x >= 0 && x < 64 && y >= 0 && y < 64)
            v = X[((size_t)(b * 4096 + y * 64 + x)) * 256 + c0 + c];
        s[i] = v;
    }
    const int c = tid & 31;
    float kr[9];
    #pragma unroll
    for (int j = 0; j < 9; j++) kr[j] = w9[(c0 + c) * 9 + j];
    const float bb = db[c0 + c];
    __syncthreads();
    for (int o = tid; o < 8192; o += 256) {
        const int sp = o >> 5;
        const int x = sp & 15, y = sp >> 4;
        float a = 0.f;
        #pragma unroll
        for (int dy = 0; dy < 3; dy++)
            #pragma unroll
            for (int dx = 0; dx < 3; dx++)
                a = fmaf(s[((y + dy) * 18 + (x + dx)) * 32 + c], kr[dy * 3 + dx], a);
        a = fmaxf(a + bb, 0.f);
        const size_t idx = ((size_t)(b * 4096 + (ty0 + y) * 64 + tx0 + x)) * 256 + c0 + c;
        __nv_bfloat16 hh, ll; split2(a, hh, ll);
        Yh[idx] = hh; Yl[idx] = ll;
    }
}

// ------------- BN stats on [M,C]: two-stage ---------------------------------
__global__ void __launch_bounds__(256)
bn_part_k(const float* __restrict__ X, float* __restrict__ part)
{
    const int seg = blockIdx.x;          // 256 segments of 256 rows
    const int c   = threadIdx.x;
    const float* p = X + (size_t)seg * 256 * 256;
    float s = 0.f, q = 0.f;
    #pragma unroll 8
    for (int r = 0; r < 256; r++) {
        const float v = p[(size_t)r * 256 + c];
        s += v; q = fmaf(v, v, q);
    }
    part[seg * 512 + c] = s;
    part[seg * 512 + 256 + c] = q;
}

__global__ void bn_fin_k(const float* __restrict__ part, const float* __restrict__ g,
                         const float* __restrict__ be, float* __restrict__ sc,
                         float* __restrict__ sh)
{
    const int c = threadIdx.x;
    float s = 0.f, q = 0.f;
    for (int seg = 0; seg < 256; seg++) {
        s += part[seg * 512 + c];
        q += part[seg * 512 + 256 + c];
    }
    const float inv = 1.f / 65536.f;
    const float m   = s * inv;
    const float var = q * inv - m * m;
    const float scv = g[c] * rsqrtf(var + EPSF);
    sc[c] = scv;
    sh[c] = be[c] - m * scv;
}

// ------------- F = RES + E*sc + sh on [M,C] ---------------------------------
__global__ void addbn_k(const float* __restrict__ R, const float* __restrict__ E,
                        const float* __restrict__ sc, const float* __restrict__ sh,
                        float* __restrict__ F)
{
    const int i4 = blockIdx.x * 256 + threadIdx.x;
    const int c0 = (i4 & 63) * 4;
    const float4 s = *reinterpret_cast<const float4*>(sc + c0);
    const float4 h = *reinterpret_cast<const float4*>(sh + c0);
    const float4 r = reinterpret_cast<const float4*>(R)[i4];
    const float4 e = reinterpret_cast<const float4*>(E)[i4];
    float4 f;
    f.x = fmaf(e.x, s.x, r.x + h.x);
    f.y = fmaf(e.y, s.y, r.y + h.y);
    f.z = fmaf(e.z, s.z, r.z + h.z);
    f.w = fmaf(e.w, s.w, r.w + h.w);
    reinterpret_cast<float4*>(F)[i4] = f;
}

// ------------- final: out NCHW = bn2(F) via transpose ------------------------
__global__ void bn_final_k(const float* __restrict__ F, const float* __restrict__ sc,
                           const float* __restrict__ sh, float* __restrict__ O)
{
    __shared__ float s[32][33];
    const int b  = blockIdx.z;
    const int c0 = blockIdx.y * 32;
    const int n0 = blockIdx.x * 32;
    const int tx = threadIdx.x, ty = threadIdx.y;  // 32 x 8
    #pragma unroll
    for (int i = 0; i < 32; i += 8)
        s[ty + i][tx] = F[((size_t)(b * 4096 + n0 + ty + i)) * 256 + c0 + tx];
    __syncthreads();
    #pragma unroll
    for (int i = 0; i < 32; i += 8) {
        const int c = c0 + ty + i;
        O[((size_t)(b * 256 + c)) * 4096 + n0 + tx] = s[tx][ty + i] * sc[c] + sh[c];
    }
}

// ===========================================================================
extern "C" void kernel_launch(void* const* d_in, const int* in_sizes, int n_in,
                              void* d_out, int out_size)
{
    (void)in_sizes; (void)n_in; (void)out_size;
    const float* x1    = (const float*)d_in[0];
    const float* x2    = (const float*)d_in[1];
    const float* cp1_w = (const float*)d_in[2];
    const float* cp1_b = (const float*)d_in[3];
    const float* cp2_w = (const float*)d_in[4];
    const float* cp2_b = (const float*)d_in[5];
    const float* kv1_w = (const float*)d_in[6];
    const float* kv2_w = (const float*)d_in[7];
    const float* ep1_w = (const float*)d_in[8];
    const float* ep1_b = (const float*)d_in[9];
    const float* ep2_w = (const float*)d_in[10];
    const float* ep2_b = (const float*)d_in[11];
    const float* ln1_g = (const float*)d_in[12];
    const float* ln1_b = (const float*)d_in[13];
    const float* ln2_g = (const float*)d_in[14];
    const float* ln2_b = (const float*)d_in[15];
    const float* res_w = (const float*)d_in[16];
    const float* ce1_w = (const float*)d_in[17];
    const float* ce1_b = (const float*)d_in[18];
    const float* dw_w  = (const float*)d_in[19];
    const float* dw_b  = (const float*)d_in[20];
    const float* ce3_w = (const float*)d_in[21];
    const float* ce3_b = (const float*)d_in[22];
    const float* bn1_g = (const float*)d_in[23];
    const float* bn1_b = (const float*)d_in[24];
    const float* bn2_g = (const float*)d_in[25];
    const float* bn2_b = (const float*)d_in[26];

    float *T1, *T2, *KV1, *KV2, *EP1, *EP2, *RES, *CE1, *E, *F;
    float *PART, *CTX1, *CTX2, *BNP, *SC1, *SH1, *SC2, *SH2;
    __nv_bfloat16 *T1h, *T1l, *T2h, *T2l, *P1h, *P1l, *P2h, *P2l;
    __nv_bfloat16 *MRGh, *MRGl, *DWh, *DWl, *WH, *WL;
    cudaGetSymbolAddress((void**)&T1,  g_T1);
    cudaGetSymbolAddress((void**)&T2,  g_T2);
    cudaGetSymbolAddress((void**)&T1h, g_T1h);
    cudaGetSymbolAddress((void**)&T1l, g_T1l);
    cudaGetSymbolAddress((void**)&T2h, g_T2h);
    cudaGetSymbolAddress((void**)&T2l, g_T2l);
    cudaGetSymbolAddress((void**)&P1h, g_P1h);
    cudaGetSymbolAddress((void**)&P1l, g_P1l);
    cudaGetSymbolAddress((void**)&P2h, g_P2h);
    cudaGetSymbolAddress((void**)&P2l, g_P2l);
    cudaGetSymbolAddress((void**)&KV1, g_KV1);
    cudaGetSymbolAddress((void**)&KV2, g_KV2);
    cudaGetSymbolAddress((void**)&EP1, g_EP1);
    cudaGetSymbolAddress((void**)&EP2, g_EP2);
    cudaGetSymbolAddress((void**)&MRGh, g_MRGh);
    cudaGetSymbolAddress((void**)&MRGl, g_MRGl);
    cudaGetSymbolAddress((void**)&RES, g_RES);
    cudaGetSymbolAddress((void**)&CE1, g_CE1);
    cudaGetSymbolAddress((void**)&DWh, g_DWh);
    cudaGetSymbolAddress((void**)&DWl, g_DWl);
    cudaGetSymbolAddress((void**)&E,   g_E);
    cudaGetSymbolAddress((void**)&F,   g_F);
    cudaGetSymbolAddress((void**)&WH,  g_WH);
    cudaGetSymbolAddress((void**)&WL,  g_WL);
    cudaGetSymbolAddress((void**)&PART, g_PART);
    cudaGetSymbolAddress((void**)&CTX1, g_CTX1);
    cudaGetSymbolAddress((void**)&CTX2, g_CTX2);
    cudaGetSymbolAddress((void**)&BNP, g_BNP);
    cudaGetSymbolAddress((void**)&SC1, g_SC1);
    cudaGetSymbolAddress((void**)&SH1, g_SH1);
    cudaGetSymbolAddress((void**)&SC2, g_SC2);
    cudaGetSymbolAddress((void**)&SH2, g_SH2);

    cudaFuncSetAttribute(gemm_tc<true,  true,  false, true >,
                         cudaFuncAttributeMaxDynamicSharedMemorySize, DYN_SMEM);
    cudaFuncSetAttribute(gemm_tc<false, false, true,  false>,
                         cudaFuncAttributeMaxDynamicSharedMemorySize, DYN_SMEM);
    cudaFuncSetAttribute(gemm_tc<true,  false, true,  false>,
                         cudaFuncAttributeMaxDynamicSharedMemorySize, DYN_SMEM);

    // weight offsets in WH/WL
    const size_t oCP1 = 0,        oCP2 = 131072, oKV1 = 262144, oKV2 = 393216;
    const size_t oEP1 = 524288,   oEP2 = 655360, oRES = 786432, oCE1 = 917504;
    const size_t oCE3 = 1048576;
    wsplit_k<<<512, 256>>>(cp1_w, WH + oCP1, WL + oCP1, 131072);
    wsplit_k<<<512, 256>>>(cp2_w, WH + oCP2, WL + oCP2, 131072);
    wsplit_k<<<512, 256>>>(kv1_w, WH + oKV1, WL + oKV1, 131072);
    wsplit_k<<<512, 256>>>(kv2_w, WH + oKV2, WL + oKV2, 131072);
    wsplit_k<<<512, 256>>>(ep1_w, WH + oEP1, WL + oEP1, 131072);
    wsplit_k<<<512, 256>>>(ep2_w, WH + oEP2, WL + oEP2, 131072);
    wsplit_k<<<512, 256>>>(res_w, WH + oRES, WL + oRES, 131072);
    wsplit_k<<<512, 256>>>(ce1_w, WH + oCE1, WL + oCE1, 131072);
    wsplit_k<<<256, 256>>>(ce3_w, WH + oCE3, WL + oCE3, 65536);

    const dim3 tpb_t(32, 8);
    transpose_split_k<<<dim3(128, 8, 16), tpb_t>>>(x1, T1, T1h, T1l);
    transpose_split_k<<<dim3(128, 8, 16), tpb_t>>>(x2, T2, T2h, T2l);

    const dim3 g512(4, 512);  // Nout=512 -> 4 tiles of 128
    const dim3 g256(2, 512);  // Nout=256 -> 2 tiles of 128

    // CrossPath: P = relu(T @ cp_w^T + b) -> split bf16
    gemm_tc<true, true, false, true><<<g512, 256, DYN_SMEM>>>(
        T1h, T1l, 256, WH + oCP1, WL + oCP1, cp1_b, nullptr, P1h, P1l, 256, 512);
    gemm_tc<true, true, false, true><<<g512, 256, DYN_SMEM>>>(
        T2h, T2l, 256, WH + oCP2, WL + oCP2, cp2_b, nullptr, P2h, P2l, 256, 512);

    // KV = u @ kv_w^T -> fp32
    gemm_tc<false, false, true, false><<<g512, 256, DYN_SMEM>>>(
        P1h + 256, P1l + 256, 512, WH + oKV1, WL + oKV1, nullptr, KV1, nullptr, nullptr, 256, 512);
    gemm_tc<false, false, true, false><<<g512, 256, DYN_SMEM>>>(
        P2h + 256, P2l + 256, 512, WH + oKV2, WL + oKV2, nullptr, KV2, nullptr, nullptr, 256, 512);

    // ctx = softmax_d(scale * K^T V)
    ctx_partial_k<<<dim3(8, 8, 16), 64>>>(KV1, PART);
    ctx_final_k<<<128, 256>>>(PART, CTX1);
    ctx_partial_k<<<dim3(8, 8, 16), 64>>>(KV2, PART);
    ctx_final_k<<<128, 256>>>(PART, CTX2);

    // a = heads(u) @ ctx (cross), in-place on u half of P (split)
    apply_ctx_k<<<dim3(512, 16), 256>>>(P1h, P1l, CTX2);
    apply_ctx_k<<<dim3(512, 16), 256>>>(P2h, P2l, CTX1);

    // EP = [y|a] @ ep_w^T + b -> fp32
    gemm_tc<true, false, true, false><<<g256, 256, DYN_SMEM>>>(
        P1h, P1l, 512, WH + oEP1, WL + oEP1, ep1_b, EP1, nullptr, nullptr, 512, 256);
    gemm_tc<true, false, true, false><<<g256, 256, DYN_SMEM>>>(
        P2h, P2l, 512, WH + oEP2, WL + oEP2, ep2_b, EP2, nullptr, nullptr, 512, 256);

    // LN -> MRG split halves
    ln_k<<<8192, 256>>>(T1, EP1, ln1_g, ln1_b, MRGh, MRGl, 0);
    ln_k<<<8192, 256>>>(T2, EP2, ln2_g, ln2_b, MRGh, MRGl, 256);

    // ChannelEmbed 1x1 convs on [M,C] layout
    gemm_tc<false, false, true, false><<<g256, 256, DYN_SMEM>>>(
        MRGh, MRGl, 512, WH + oRES, WL + oRES, nullptr, RES, nullptr, nullptr, 512, 256);
    gemm_tc<true, false, true, false><<<g256, 256, DYN_SMEM>>>(
        MRGh, MRGl, 512, WH + oCE1, WL + oCE1, ce1_b, CE1, nullptr, nullptr, 512, 256);

    // 3x3 depthwise + bias + relu -> split bf16 [M,C]
    dw_k<<<dim3(8, 16, 16), 256>>>(CE1, dw_w, dw_b, DWh, DWl);

    // ce3 1x1 conv
    gemm_tc<true, false, true, false><<<g256, 256, DYN_SMEM>>>(
        DWh, DWl, 256, WH + oCE3, WL + oCE3, ce3_b, E, nullptr, nullptr, 256, 256);

    // bn1 -> residual add; bn2 -> final NCHW output
    bn_part_k<<<256, 256>>>(E, BNP);
    bn_fin_k<<<1, 256>>>(BNP, bn1_g, bn1_b, SC1, SH1);
    addbn_k<<<16384, 256>>>(RES, E, SC1, SH1, F);
    bn_part_k<<<256, 256>>>(F, BNP);
    bn_fin_k<<<1, 256>>>(BNP, bn2_g, bn2_b, SC2, SH2);
    bn_final_k<<<dim3(128, 8, 16), tpb_t>>>(F, SC2, SH2, (float*)d_out);
}

// round 4
// speedup vs baseline: 2.1732x; 1.0364x over previous
#include <cuda_runtime.h>
#include <cuda_bf16.h>
#include <math.h>
#include <stdint.h>

namespace {
constexpr int Bn  = 16;
constexpr int Cn  = 256;
constexpr int HWn = 4096;
constexpr int NHn = 8;
constexpr int Mn  = Bn * HWn;          // 65536 rows
constexpr float EPSF  = 1e-5f;
constexpr float SCALE = 0.17677669529663687f;  // 32^-0.5

constexpr int ROWB   = 80;             // bytes per 32-bf16 row in smem
constexpr int MATB   = 128 * ROWB;     // 10240 bytes per matrix tile
constexpr int STAGEB = 4 * MATB;       // AH | AL | BH | BL = 40960
constexpr int NSTAGE = 3;
constexpr int DYN_SMEM = NSTAGE * STAGEB;   // 122880
}

// ---------------- workspace (device globals; no allocation allowed) --------
__device__ __nv_bfloat16 g_T1h[(size_t)Mn * Cn];
__device__ __nv_bfloat16 g_T1l[(size_t)Mn * Cn];
__device__ __nv_bfloat16 g_T2h[(size_t)Mn * Cn];
__device__ __nv_bfloat16 g_T2l[(size_t)Mn * Cn];
__device__ __nv_bfloat16 g_P1h[(size_t)Mn * 2 * Cn];
__device__ __nv_bfloat16 g_P1l[(size_t)Mn * 2 * Cn];
__device__ __nv_bfloat16 g_P2h[(size_t)Mn * 2 * Cn];
__device__ __nv_bfloat16 g_P2l[(size_t)Mn * 2 * Cn];
__device__ float g_KV1[(size_t)Mn * 2 * Cn];
__device__ float g_KV2[(size_t)Mn * 2 * Cn];
__device__ float g_EP1[(size_t)Mn * Cn];
__device__ float g_EP2[(size_t)Mn * Cn];
__device__ __nv_bfloat16 g_MRGh[(size_t)Mn * 2 * Cn];
__device__ __nv_bfloat16 g_MRGl[(size_t)Mn * 2 * Cn];
__device__ float g_RC [(size_t)Mn * 2 * Cn];      // cols 0-255 RES, 256-511 CE1
__device__ __nv_bfloat16 g_DWh[(size_t)Mn * Cn];
__device__ __nv_bfloat16 g_DWl[(size_t)Mn * Cn];
__device__ float g_E  [(size_t)Mn * Cn];
__device__ float g_F  [(size_t)Mn * Cn];
__device__ __nv_bfloat16 g_WH[900000];
__device__ __nv_bfloat16 g_WL[900000];
__device__ __nv_bfloat16 g_EPYh[2 * 65536];
__device__ __nv_bfloat16 g_EPYl[2 * 65536];
__device__ __nv_bfloat16 g_MWh[2 * 16 * 65536];
__device__ __nv_bfloat16 g_MWl[2 * 16 * 65536];
__device__ float g_PART[(size_t)2 * Bn * NHn * 8 * 32 * 32];
__device__ float g_CTX1[(size_t)Bn * NHn * 32 * 32];
__device__ float g_CTX2[(size_t)Bn * NHn * 32 * 32];
__device__ float g_CB[512];
__device__ float g_BNP[256 * 512];
__device__ float g_SC1[Cn];
__device__ float g_SH1[Cn];
__device__ float g_SC2[Cn];
__device__ float g_SH2[Cn];

// ---------------- PTX helpers ----------------------------------------------
__device__ __forceinline__ uint32_t smem_u32(const void* p) {
    uint32_t a;
    asm("{ .reg .u64 t; cvta.to.shared.u64 t, %1; cvt.u32.u64 %0, t; }"
        : "=r"(a) : "l"(p));
    return a;
}

__device__ __forceinline__ void cpasync16(uint32_t dst, const void* src) {
    asm volatile("cp.async.cg.shared.global [%0], [%1], 16;"
                 :: "r"(dst), "l"(src));
}

__device__ __forceinline__ void ldsm4(uint32_t* r, uint32_t addr) {
    asm volatile("ldmatrix.sync.aligned.m8n8.x4.shared.b16 {%0,%1,%2,%3}, [%4];"
                 : "=r"(r[0]), "=r"(r[1]), "=r"(r[2]), "=r"(r[3]) : "r"(addr));
}

__device__ __forceinline__ void mma16816(float* d, const uint32_t* a, const uint32_t* b) {
    asm volatile(
        "mma.sync.aligned.m16n8k16.row.col.f32.bf16.bf16.f32 "
        "{%0,%1,%2,%3}, {%4,%5,%6,%7}, {%8,%9}, {%0,%1,%2,%3};"
        : "+f"(d[0]), "+f"(d[1]), "+f"(d[2]), "+f"(d[3])
        : "r"(a[0]), "r"(a[1]), "r"(a[2]), "r"(a[3]), "r"(b[0]), "r"(b[1]));
}

__device__ __forceinline__ void split2(float v, __nv_bfloat16& h, __nv_bfloat16& l) {
    h = __float2bfloat16(v);
    l = __float2bfloat16(v - __bfloat162float(h));
}

// ---------------- weight split: all contiguous weights in one launch --------
struct WsplitArgs {
    const float* src[7];   // cp1, cp2, kv1, kv2, res, ce1, ce3
};
__global__ void wsplit_all_k(WsplitArgs a, __nv_bfloat16* __restrict__ h,
                             __nv_bfloat16* __restrict__ l)
{
    const int i = blockIdx.x * 256 + threadIdx.x;
    if (i >= 851968) return;
    int seg, off;
    if (i < 786432) { seg = i >> 17; off = i & 131071; }
    else            { seg = 6;       off = i - 786432; }
    __nv_bfloat16 hh, ll; split2(a.src[seg][off], hh, ll);
    h[i] = hh; l[i] = ll;
}

// ---------------- ep static (y-part) weight: strided split ------------------
__global__ void wsplit_ep_k(const float* __restrict__ ep1_w, const float* __restrict__ ep2_w,
                            __nv_bfloat16* __restrict__ h, __nv_bfloat16* __restrict__ l)
{
    const int o = blockIdx.x;            // 0..255
    const int path = blockIdx.y;
    const int k = threadIdx.x;           // 0..255
    const float* w = path ? ep2_w : ep1_w;
    __nv_bfloat16 hh, ll; split2(w[o * 512 + k], hh, ll);
    const int idx = path * 65536 + o * 256 + k;
    h[idx] = hh; l[idx] = ll;
}

// ---------------- bias concat for res|ce1 GEMM -------------------------------
__global__ void biascat_k(const float* __restrict__ ce1_b, float* __restrict__ cb)
{
    const int t = threadIdx.x + blockIdx.x * 256;
    cb[t] = (t < 256) ? 0.f : ce1_b[t - 256];
}

// ---------------- transpose + split: x [B,C,HW] -> hi/lo [B,HW,C] -----------
__global__ void transpose_split_k(const float* __restrict__ x1, const float* __restrict__ x2,
                                  __nv_bfloat16* __restrict__ t1h, __nv_bfloat16* __restrict__ t1l,
                                  __nv_bfloat16* __restrict__ t2h, __nv_bfloat16* __restrict__ t2l)
{
    __shared__ float s[32][33];
    const int z = blockIdx.z;
    const int path = z >> 4;
    const int b = z & 15;
    const float* x = path ? x2 : x1;
    __nv_bfloat16* th = path ? t2h : t1h;
    __nv_bfloat16* tl = path ? t2l : t1l;
    const int c0 = blockIdx.y * 32;
    const int n0 = blockIdx.x * 32;
    const float* xb = x + (size_t)b * Cn * HWn;
    const int tx = threadIdx.x, ty = threadIdx.y;  // 32 x 8
    #pragma unroll
    for (int i = 0; i < 32; i += 8)
        s[ty + i][tx] = xb[(size_t)(c0 + ty + i) * HWn + n0 + tx];
    __syncthreads();
    #pragma unroll
    for (int i = 0; i < 32; i += 8) {
        const size_t idx = ((size_t)b * HWn + n0 + ty + i) * Cn + c0 + tx;
        __nv_bfloat16 h, l; split2(s[tx][ty + i], h, l);
        th[idx] = h; tl[idx] = l;
    }
}

// ---------------- HMMA split-bf16 GEMM, 3-stage pipeline ---------------------
template<bool DUALB>
__device__ __forceinline__ void load_stage(
    uint32_t sb, int m0, int n0, int k0,
    const __nv_bfloat16* Ah, const __nv_bfloat16* Al, int lda,
    const __nv_bfloat16* W1h, const __nv_bfloat16* W1l,
    const __nv_bfloat16* W2h, const __nv_bfloat16* W2l,
    int K, int tid)
{
    #pragma unroll
    for (int j = 0; j < 2; j++) {                       // A tiles
        const int idx = j * 256 + tid;
        const int r = idx >> 2, c = idx & 3;
        const uint32_t dst = sb + r * ROWB + c * 16;
        const size_t so = (size_t)(m0 + r) * lda + k0 + c * 8;
        cpasync16(dst,        Ah + so);
        cpasync16(dst + MATB, Al + so);
    }
    #pragma unroll
    for (int j = 0; j < 2; j++) {                       // B tiles
        const int idx = j * 256 + tid;
        const int r = idx >> 2, c = idx & 3;
        const uint32_t dst = sb + 2 * MATB + r * ROWB + c * 16;
        if (!DUALB) {
            const size_t so = (size_t)(n0 + r) * K + k0 + c * 8;
            cpasync16(dst,        W1h + so);
            cpasync16(dst + MATB, W1l + so);
        } else if (k0 < 256) {
            const size_t so = (size_t)(n0 + r) * 256 + k0 + c * 8;
            cpasync16(dst,        W1h + so);
            cpasync16(dst + MATB, W1l + so);
        } else {
            const size_t so = (size_t)(n0 + r) * 256 + (k0 - 256) + c * 8;
            cpasync16(dst,        W2h + so);
            cpasync16(dst + MATB, W2l + so);
        }
    }
}

template<bool BIAS, bool RELU, bool OUTF, bool OUTB, bool DUALB>
__global__ void __launch_bounds__(256, 1)
gemm_tc(const __nv_bfloat16* __restrict__ Ah, const __nv_bfloat16* __restrict__ Al, int lda,
        const __nv_bfloat16* __restrict__ W1h, const __nv_bfloat16* __restrict__ W1l,
        const __nv_bfloat16* __restrict__ W2h, const __nv_bfloat16* __restrict__ W2l,
        const float* __restrict__ bias,
        float* __restrict__ outF,
        __nv_bfloat16* __restrict__ outH, __nv_bfloat16* __restrict__ outL,
        int K, int Nout)
{
    extern __shared__ char dyn_smem[];
    const int tid  = threadIdx.x;
    const int wid  = tid >> 5;
    const int lane = tid & 31;
    const int m0 = blockIdx.y * 128;
    const int n0 = blockIdx.x * 128;
    const int wm0 = (wid & 1) * 64;
    const int wn0 = (wid >> 1) * 32;

    if (DUALB) {
        const size_t boff = (size_t)(m0 >> 12) * 65536;
        W2h += boff; W2l += boff;
    }

    const uint32_t base = smem_u32(dyn_smem);

    float acc[4][4][4];
    #pragma unroll
    for (int i = 0; i < 4; i++)
        #pragma unroll
        for (int j = 0; j < 4; j++)
            #pragma unroll
            for (int q = 0; q < 4; q++) acc[i][j][q] = 0.f;

    const uint32_t aOff = (uint32_t)(wm0 + (lane & 15)) * ROWB + ((lane >> 4) * 16);
    const uint32_t bOff = (uint32_t)(wn0 + ((lane >> 4) * 8) + (lane & 7)) * ROWB
                        + (((lane >> 3) & 1) * 16);

    const int S = K / 32;
    load_stage<DUALB>(base, m0, n0, 0, Ah, Al, lda, W1h, W1l, W2h, W2l, K, tid);
    asm volatile("cp.async.commit_group;" ::: "memory");
    if (S > 1) {
        load_stage<DUALB>(base + STAGEB, m0, n0, 32, Ah, Al, lda, W1h, W1l, W2h, W2l, K, tid);
        asm volatile("cp.async.commit_group;" ::: "memory");
    }

    int buf = 0;
    for (int s = 0; s < S; s++) {
        if (s < S - 1)
            asm volatile("cp.async.wait_group 1;" ::: "memory");
        else
            asm volatile("cp.async.wait_group 0;" ::: "memory");
        __syncthreads();
        if (s + 2 < S) {
            int nb = buf + 2; if (nb >= NSTAGE) nb -= NSTAGE;
            load_stage<DUALB>(base + nb * STAGEB, m0, n0, (s + 2) * 32,
                              Ah, Al, lda, W1h, W1l, W2h, W2l, K, tid);
            asm volatile("cp.async.commit_group;" ::: "memory");
        }
        const uint32_t sb = base + buf * STAGEB;
        #pragma unroll
        for (int ks = 0; ks < 2; ks++) {
            const uint32_t kb = ks * 32;
            uint32_t aH[4][4], aL[4][4], bH[2][4], bL[2][4];
            #pragma unroll
            for (int mi = 0; mi < 4; mi++) {
                const uint32_t ad = sb + aOff + mi * 16 * ROWB + kb;
                ldsm4(aH[mi], ad);
                ldsm4(aL[mi], ad + MATB);
            }
            #pragma unroll
            for (int np = 0; np < 2; np++) {
                const uint32_t bd = sb + 2 * MATB + bOff + np * 16 * ROWB + kb;
                ldsm4(bH[np], bd);
                ldsm4(bL[np], bd + MATB);
            }
            #pragma unroll
            for (int mi = 0; mi < 4; mi++)
                #pragma unroll
                for (int ni = 0; ni < 4; ni++)
                    mma16816(acc[mi][ni], aH[mi], &bH[ni >> 1][(ni & 1) * 2]);
            #pragma unroll
            for (int mi = 0; mi < 4; mi++)
                #pragma unroll
                for (int ni = 0; ni < 4; ni++)
                    mma16816(acc[mi][ni], aH[mi], &bL[ni >> 1][(ni & 1) * 2]);
            #pragma unroll
            for (int mi = 0; mi < 4; mi++)
                #pragma unroll
                for (int ni = 0; ni < 4; ni++)
                    mma16816(acc[mi][ni], aL[mi], &bH[ni >> 1][(ni & 1) * 2]);
        }
        buf++; if (buf >= NSTAGE) buf = 0;
        __syncthreads();
    }

    // epilogue
    #pragma unroll
    for (int ni = 0; ni < 4; ni++) {
        const int cidx = n0 + wn0 + ni * 8 + (lane & 3) * 2;
        float b0 = 0.f, b1 = 0.f;
        if (BIAS) { b0 = bias[cidx]; b1 = bias[cidx + 1]; }
        #pragma unroll
        for (int mi = 0; mi < 4; mi++) {
            const int r0 = m0 + wm0 + mi * 16 + (lane >> 2);
            #pragma unroll
            for (int half = 0; half < 2; half++) {
                const int r = r0 + half * 8;
                float v0 = acc[mi][ni][half * 2 + 0];
                float v1 = acc[mi][ni][half * 2 + 1];
                if (BIAS) { v0 += b0; v1 += b1; }
                if (RELU) { v0 = fmaxf(v0, 0.f); v1 = fmaxf(v1, 0.f); }
                if (OUTF) {
                    float2 f2 = make_float2(v0, v1);
                    *reinterpret_cast<float2*>(outF + (size_t)r * Nout + cidx) = f2;
                }
                if (OUTB) {
                    __nv_bfloat16 h0, l0, h1, l1;
                    split2(v0, h0, l0); split2(v1, h1, l1);
                    __nv_bfloat162 hh; hh.x = h0; hh.y = h1;
                    __nv_bfloat162 ll; ll.x = l0; ll.y = l1;
                    *reinterpret_cast<__nv_bfloat162*>(outH + (size_t)r * Nout + cidx) = hh;
                    *reinterpret_cast<__nv_bfloat162*>(outL + (size_t)r * Nout + cidx) = ll;
                }
            }
        }
    }
}

// ------------- ctx partial: per (chunk,h,b,path) K^T V over 512 rows --------
__global__ void __launch_bounds__(64)
ctx_partial_k(const float* __restrict__ KV1, const float* __restrict__ KV2,
              float* __restrict__ part)
{
    __shared__ float Ks[64][32];
    __shared__ float Vs[64][32];
    const int chunk = blockIdx.x, h = blockIdx.y, z = blockIdx.z;
    const int b = z & 15;
    const float* KV = (z < 16) ? KV1 : KV2;
    const int t = threadIdx.x, lane = t & 31, w = t >> 5;
    const float* base = KV + (size_t)b * HWn * 512;
    const int d0 = (t >> 3) * 4, e0 = (t & 7) * 4;
    float acc[4][4] = {};
    for (int nb = 0; nb < 512; nb += 64) {
        const int row0 = chunk * 512 + nb;
        for (int r = w; r < 64; r += 2) {
            const float* rp = base + (size_t)(row0 + r) * 512 + h * 32;
            Ks[r][lane] = rp[lane];
            Vs[r][lane] = rp[256 + lane];
        }
        __syncthreads();
        #pragma unroll 8
        for (int n = 0; n < 64; n++) {
            float4 k4 = *reinterpret_cast<float4*>(&Ks[n][d0]);
            float4 v4 = *reinterpret_cast<float4*>(&Vs[n][e0]);
            const float kk[4] = {k4.x, k4.y, k4.z, k4.w};
            const float vv[4] = {v4.x, v4.y, v4.z, v4.w};
            #pragma unroll
            for (int i = 0; i < 4; i++)
                #pragma unroll
                for (int j = 0; j < 4; j++)
                    acc[i][j] = fmaf(kk[i], vv[j], acc[i][j]);
        }
        __syncthreads();
    }
    float* p = part + ((size_t)(z * NHn + h) * 8 + chunk) * 1024;
    #pragma unroll
    for (int i = 0; i < 4; i++)
        #pragma unroll
        for (int j = 0; j < 4; j++)
            p[(d0 + i) * 32 + e0 + j] = acc[i][j];
}

// ------------- ctx finalize: sum partials, scale, softmax over d -----------
__global__ void ctx_final_k(const float* __restrict__ part, float* __restrict__ ctx1,
                            float* __restrict__ ctx2)
{
    __shared__ float S[32][33];
    const int bhg = blockIdx.x;        // [0,256): path*128 + bh
    float* ctx = (bhg < 128) ? ctx1 : ctx2;
    const int bh = bhg & 127;
    const int t  = threadIdx.x;
    const float* p = part + (size_t)bhg * 8 * 1024;
    for (int idx = t; idx < 1024; idx += 256) {
        float s = 0.f;
        #pragma unroll
        for (int c = 0; c < 8; c++) s += p[c * 1024 + idx];
        S[idx >> 5][idx & 31] = s * SCALE;
    }
    __syncthreads();
    if (t < 32) {
        float mx = -1e30f;
        #pragma unroll
        for (int d = 0; d < 32; d++) mx = fmaxf(mx, S[d][t]);
        float e[32], sum = 0.f;
        #pragma unroll
        for (int d = 0; d < 32; d++) { e[d] = expf(S[d][t] - mx); sum += e[d]; }
        const float inv = 1.f / sum;
        float* o = ctx + (size_t)bh * 1024;
        #pragma unroll
        for (int d = 0; d < 32; d++) o[d * 32 + t] = e[d] * inv;
    }
}

// ------------- build per-batch ep "M" weights: M[o, j] (split bf16) ---------
// path0 (ep1) uses ctx2; path1 (ep2) uses ctx1.
__global__ void __launch_bounds__(256)
ctxw_k(const float* __restrict__ ctx1, const float* __restrict__ ctx2,
       const float* __restrict__ ep1_w, const float* __restrict__ ep2_w,
       __nv_bfloat16* __restrict__ mwh, __nv_bfloat16* __restrict__ mwl)
{
    __shared__ float cs[8192];
    const int z = blockIdx.x;                 // path*16 + b
    const int path = z >> 4;
    const int b = z & 15;
    const float* ctx = path ? ctx1 : ctx2;
    const float* epw = path ? ep2_w : ep1_w;
    const int j = threadIdx.x;                // u-column 0..255
    for (int i = j; i < 8192; i += 256)
        cs[i] = ctx[(size_t)b * 8192 + i];
    __syncthreads();
    const int h = j >> 5, d = j & 31;
    float c[32];
    #pragma unroll
    for (int e = 0; e < 32; e++) c[e] = cs[h * 1024 + d * 32 + e];
    __nv_bfloat16* oh = mwh + (size_t)z * 65536;
    __nv_bfloat16* ol = mwl + (size_t)z * 65536;
    for (int o = 0; o < 256; o++) {
        const float* wr = epw + (size_t)o * 512 + 256 + h * 32;
        float a = 0.f;
        #pragma unroll
        for (int e = 0; e < 32; e++) a = fmaf(c[e], __ldg(wr + e), a);
        __nv_bfloat16 hh, ll; split2(a, hh, ll);
        oh[o * 256 + j] = hh; ol[o * 256 + j] = ll;
    }
}

// ------------- LayerNorm: MRG[:, mco..] = LN((Th+Tl) + EP)*g + b -------------
__global__ void __launch_bounds__(256)
ln_k(const __nv_bfloat16* __restrict__ T1h, const __nv_bfloat16* __restrict__ T1l,
     const __nv_bfloat16* __restrict__ T2h, const __nv_bfloat16* __restrict__ T2l,
     const float* __restrict__ EP1, const float* __restrict__ EP2,
     const float* __restrict__ g1, const float* __restrict__ b1,
     const float* __restrict__ g2, const float* __restrict__ b2,
     __nv_bfloat16* __restrict__ MH, __nv_bfloat16* __restrict__ ML)
{
    const int path = blockIdx.y;
    const __nv_bfloat16* Th = path ? T2h : T1h;
    const __nv_bfloat16* Tl = path ? T2l : T1l;
    const float* EP = path ? EP2 : EP1;
    const float* g  = path ? g2 : g1;
    const float* be = path ? b2 : b1;
    const int mco = path * 256;
    const int w    = blockIdx.x * 8 + (threadIdx.x >> 5);
    const int lane = threadIdx.x & 31;
    const __nv_bfloat16* th = Th + (size_t)w * 256;
    const __nv_bfloat16* tl = Tl + (size_t)w * 256;
    const float* er = EP + (size_t)w * 256;
    float v[8], sum = 0.f, sq = 0.f;
    #pragma unroll
    for (int i = 0; i < 8; i++) {
        const int c = lane + i * 32;
        const float x = __bfloat162float(th[c]) + __bfloat162float(tl[c]) + er[c];
        v[i] = x; sum += x; sq += x * x;
    }
    #pragma unroll
    for (int o = 16; o; o >>= 1) {
        sum += __shfl_xor_sync(0xffffffffu, sum, o);
        sq  += __shfl_xor_sync(0xffffffffu, sq,  o);
    }
    const float mean = sum * (1.f / 256.f);
    const float var  = sq * (1.f / 256.f) - mean * mean;
    const float rs   = rsqrtf(var + EPSF);
    const size_t ob = (size_t)w * 512 + mco;
    #pragma unroll
    for (int i = 0; i < 8; i++) {
        const int c = lane + i * 32;
        const float y = (v[i] - mean) * rs * g[c] + be[c];
        __nv_bfloat16 hh, ll; split2(y, hh, ll);
        MH[ob + c] = hh; ML[ob + c] = ll;
    }
}

// ------------- 3x3 depthwise conv on [M,ld] layout + bias + relu, split out --
__global__ void __launch_bounds__(256)
dw_k(const float* __restrict__ X, int ldx, const float* __restrict__ w9,
     const float* __restrict__ db, __nv_bfloat16* __restrict__ Yh,
     __nv_bfloat16* __restrict__ Yl)
{
    __shared__ float s[18 * 18 * 32];
    const int cc   = blockIdx.x;
    const int tile = blockIdx.y;
    const int b    = blockIdx.z;
    const int ty0 = (tile >> 2) * 16, tx0 = (tile & 3) * 16;
    const int c0 = cc * 32;
    const int tid = threadIdx.x;
    for (int i = tid; i < 18 * 18 * 32; i += 256) {
        const int c = i & 31;
        const int sp = i >> 5;
        const int x = sp % 18 - 1 + tx0;
        const int y = sp / 18 - 1 + ty0;
        float v = 0.f;
        if (x >= 0 && x < 64 && y >= 0 && y < 64)
            v = X[(size_t)(b * 4096 + y * 64 + x) * ldx + c0 + c];
        s[i] = v;
    }
    const int c = tid & 31;
    float kr[9];
    #pragma unroll
    for (int j = 0; j < 9; j++) kr[j] = w9[(c0 + c) * 9 + j];
    const float bb = db[c0 + c];
    __syncthreads();
    for (int o = tid; o < 8192; o += 256) {
        const int sp = o >> 5;
        const int x = sp & 15, y = sp >> 4;
        float a = 0.f;
        #pragma unroll
        for (int dy = 0; dy < 3; dy++)
            #pragma unroll
            for (int dx = 0; dx < 3; dx++)
                a = fmaf(s[((y + dy) * 18 + (x + dx)) * 32 + c], kr[dy * 3 + dx], a);
        a = fmaxf(a + bb, 0.f);
        const size_t idx = (size_t)(b * 4096 + (ty0 + y) * 64 + tx0 + x) * 256 + c0 + c;
        __nv_bfloat16 hh, ll; split2(a, hh, ll);
        Yh[idx] = hh; Yl[idx] = ll;
    }
}

// ------------- BN stats on [M,256] fp32: two-stage ---------------------------
__global__ void __launch_bounds__(256)
bn_part_k(const float* __restrict__ X, float* __restrict__ part)
{
    const int seg = blockIdx.x;
    const int c   = threadIdx.x;
    const float* p = X + (size_t)seg * 256 * 256;
    float s = 0.f, q = 0.f;
    #pragma unroll 8
    for (int r = 0; r < 256; r++) {
        const float v = p[(size_t)r * 256 + c];
        s += v; q = fmaf(v, v, q);
    }
    part[seg * 512 + c] = s;
    part[seg * 512 + 256 + c] = q;
}

__global__ void bn_fin_k(const float* __restrict__ part, const float* __restrict__ g,
                         const float* __restrict__ be, float* __restrict__ sc,
                         float* __restrict__ sh)
{
    const int c = threadIdx.x;
    float s = 0.f, q = 0.f;
    for (int seg = 0; seg < 256; seg++) {
        s += part[seg * 512 + c];
        q += part[seg * 512 + 256 + c];
    }
    const float inv = 1.f / 65536.f;
    const float m   = s * inv;
    const float var = q * inv - m * m;
    const float scv = g[c] * rsqrtf(var + EPSF);
    sc[c] = scv;
    sh[c] = be[c] - m * scv;
}

// ------------- F = RES(RC col0-255) + E*sc + sh ------------------------------
__global__ void addbn_k(const float* __restrict__ RC, const float* __restrict__ E,
                        const float* __restrict__ sc, const float* __restrict__ sh,
                        float* __restrict__ F)
{
    const int i4 = blockIdx.x * 256 + threadIdx.x;
    const int r  = i4 >> 6;
    const int c0 = (i4 & 63) * 4;
    const float4 s = *reinterpret_cast<const float4*>(sc + c0);
    const float4 h = *reinterpret_cast<const float4*>(sh + c0);
    const float4 rr = *reinterpret_cast<const float4*>(RC + (size_t)r * 512 + c0);
    const float4 e = reinterpret_cast<const float4*>(E)[i4];
    float4 f;
    f.x = fmaf(e.x, s.x, rr.x + h.x);
    f.y = fmaf(e.y, s.y, rr.y + h.y);
    f.z = fmaf(e.z, s.z, rr.z + h.z);
    f.w = fmaf(e.w, s.w, rr.w + h.w);
    reinterpret_cast<float4*>(F)[i4] = f;
}

// ------------- final: out NCHW = bn2(F) via transpose ------------------------
__global__ void bn_final_k(const float* __restrict__ F, const float* __restrict__ sc,
                           const float* __restrict__ sh, float* __restrict__ O)
{
    __shared__ float s[32][33];
    const int b  = blockIdx.z;
    const int c0 = blockIdx.y * 32;
    const int n0 = blockIdx.x * 32;
    const int tx = threadIdx.x, ty = threadIdx.y;
    #pragma unroll
    for (int i = 0; i < 32; i += 8)
        s[ty + i][tx] = F[((size_t)(b * 4096 + n0 + ty + i)) * 256 + c0 + tx];
    __syncthreads();
    #pragma unroll
    for (int i = 0; i < 32; i += 8) {
        const int c = c0 + ty + i;
        O[((size_t)(b * 256 + c)) * 4096 + n0 + tx] = s[tx][ty + i] * sc[c] + sh[c];
    }
}

// ===========================================================================
extern "C" void kernel_launch(void* const* d_in, const int* in_sizes, int n_in,
                              void* d_out, int out_size)
{
    (void)in_sizes; (void)n_in; (void)out_size;
    const float* x1    = (const float*)d_in[0];
    const float* x2    = (const float*)d_in[1];
    const float* cp1_w = (const float*)d_in[2];
    const float* cp1_b = (const float*)d_in[3];
    const float* cp2_w = (const float*)d_in[4];
    const float* cp2_b = (const float*)d_in[5];
    const float* kv1_w = (const float*)d_in[6];
    const float* kv2_w = (const float*)d_in[7];
    const float* ep1_w = (const float*)d_in[8];
    const float* ep1_b = (const float*)d_in[9];
    const float* ep2_w = (const float*)d_in[10];
    const float* ep2_b = (const float*)d_in[11];
    const float* ln1_g = (const float*)d_in[12];
    const float* ln1_b = (const float*)d_in[13];
    const float* ln2_g = (const float*)d_in[14];
    const float* ln2_b = (const float*)d_in[15];
    const float* res_w = (const float*)d_in[16];
    const float* ce1_w = (const float*)d_in[17];
    const float* ce1_b = (const float*)d_in[18];
    const float* dw_w  = (const float*)d_in[19];
    const float* dw_b  = (const float*)d_in[20];
    const float* ce3_w = (const float*)d_in[21];
    const float* ce3_b = (const float*)d_in[22];
    const float* bn1_g = (const float*)d_in[23];
    const float* bn1_b = (const float*)d_in[24];
    const float* bn2_g = (const float*)d_in[25];
    const float* bn2_b = (const float*)d_in[26];

    float *KV1, *KV2, *EP1, *EP2, *RC, *E, *F;
    float *PART, *CTX1, *CTX2, *CB, *BNP, *SC1, *SH1, *SC2, *SH2;
    __nv_bfloat16 *T1h, *T1l, *T2h, *T2l, *P1h, *P1l, *P2h, *P2l;
    __nv_bfloat16 *MRGh, *MRGl, *DWh, *DWl, *WH, *WL, *EPYh, *EPYl, *MWh, *MWl;
    cudaGetSymbolAddress((void**)&T1h, g_T1h);
    cudaGetSymbolAddress((void**)&T1l, g_T1l);
    cudaGetSymbolAddress((void**)&T2h, g_T2h);
    cudaGetSymbolAddress((void**)&T2l, g_T2l);
    cudaGetSymbolAddress((void**)&P1h, g_P1h);
    cudaGetSymbolAddress((void**)&P1l, g_P1l);
    cudaGetSymbolAddress((void**)&P2h, g_P2h);
    cudaGetSymbolAddress((void**)&P2l, g_P2l);
    cudaGetSymbolAddress((void**)&KV1, g_KV1);
    cudaGetSymbolAddress((void**)&KV2, g_KV2);
    cudaGetSymbolAddress((void**)&EP1, g_EP1);
    cudaGetSymbolAddress((void**)&EP2, g_EP2);
    cudaGetSymbolAddress((void**)&MRGh, g_MRGh);
    cudaGetSymbolAddress((void**)&MRGl, g_MRGl);
    cudaGetSymbolAddress((void**)&RC,  g_RC);
    cudaGetSymbolAddress((void**)&DWh, g_DWh);
    cudaGetSymbolAddress((void**)&DWl, g_DWl);
    cudaGetSymbolAddress((void**)&E,   g_E);
    cudaGetSymbolAddress((void**)&F,   g_F);
    cudaGetSymbolAddress((void**)&WH,  g_WH);
    cudaGetSymbolAddress((void**)&WL,  g_WL);
    cudaGetSymbolAddress((void**)&EPYh, g_EPYh);
    cudaGetSymbolAddress((void**)&EPYl, g_EPYl);
    cudaGetSymbolAddress((void**)&MWh, g_MWh);
    cudaGetSymbolAddress((void**)&MWl, g_MWl);
    cudaGetSymbolAddress((void**)&PART, g_PART);
    cudaGetSymbolAddress((void**)&CTX1, g_CTX1);
    cudaGetSymbolAddress((void**)&CTX2, g_CTX2);
    cudaGetSymbolAddress((void**)&CB,  g_CB);
    cudaGetSymbolAddress((void**)&BNP, g_BNP);
    cudaGetSymbolAddress((void**)&SC1, g_SC1);
    cudaGetSymbolAddress((void**)&SH1, g_SH1);
    cudaGetSymbolAddress((void**)&SC2, g_SC2);
    cudaGetSymbolAddress((void**)&SH2, g_SH2);

    cudaFuncSetAttribute(gemm_tc<true,  true,  false, true , false>,
                         cudaFuncAttributeMaxDynamicSharedMemorySize, DYN_SMEM);
    cudaFuncSetAttribute(gemm_tc<false, false, true,  false, false>,
                         cudaFuncAttributeMaxDynamicSharedMemorySize, DYN_SMEM);
    cudaFuncSetAttribute(gemm_tc<true,  false, true,  false, true >,
                         cudaFuncAttributeMaxDynamicSharedMemorySize, DYN_SMEM);
    cudaFuncSetAttribute(gemm_tc<true,  false, true,  false, false>,
                         cudaFuncAttributeMaxDynamicSharedMemorySize, DYN_SMEM);

    // weight slots in WH/WL (851968 total)
    const size_t oCP1 = 0, oCP2 = 131072, oKV1 = 262144, oKV2 = 393216;
    const size_t oRC = 524288, oCE3 = 786432;
    WsplitArgs wa;
    wa.src[0] = cp1_w; wa.src[1] = cp2_w; wa.src[2] = kv1_w; wa.src[3] = kv2_w;
    wa.src[4] = res_w; wa.src[5] = ce1_w; wa.src[6] = ce3_w;

    // 1: all contiguous weight splits
    wsplit_all_k<<<3328, 256>>>(wa, WH, WL);
    // 2: ep y-part (strided) splits
    wsplit_ep_k<<<dim3(256, 2), 256>>>(ep1_w, ep2_w, EPYh, EPYl);
    // 3: input transpose + split (both paths)
    transpose_split_k<<<dim3(128, 8, 32), dim3(32, 8)>>>(x1, x2, T1h, T1l, T2h, T2l);

    const dim3 g512(4, 512);
    const dim3 g256(2, 512);

    // 4,5: CrossPath P = relu(T @ cp_w^T + b) -> split bf16
    gemm_tc<true, true, false, true, false><<<g512, 256, DYN_SMEM>>>(
        T1h, T1l, 256, WH + oCP1, WL + oCP1, nullptr, nullptr, cp1_b,
        nullptr, P1h, P1l, 256, 512);
    gemm_tc<true, true, false, true, false><<<g512, 256, DYN_SMEM>>>(
        T2h, T2l, 256, WH + oCP2, WL + oCP2, nullptr, nullptr, cp2_b,
        nullptr, P2h, P2l, 256, 512);

    // 6,7: KV = u @ kv_w^T -> fp32   (launch #6 gets profiled)
    gemm_tc<false, false, true, false, false><<<g512, 256, DYN_SMEM>>>(
        P1h + 256, P1l + 256, 512, WH + oKV1, WL + oKV1, nullptr, nullptr, nullptr,
        KV1, nullptr, nullptr, 256, 512);
    gemm_tc<false, false, true, false, false><<<g512, 256, DYN_SMEM>>>(
        P2h + 256, P2l + 256, 512, WH + oKV2, WL + oKV2, nullptr, nullptr, nullptr,
        KV2, nullptr, nullptr, 256, 512);

    // 8,9: ctx = softmax_d(scale * K^T V), both paths
    ctx_partial_k<<<dim3(8, 8, 32), 64>>>(KV1, KV2, PART);
    ctx_final_k<<<256, 256>>>(PART, CTX1, CTX2);

    // 10: per-batch M weights for the fused ep GEMM (cross-wired)
    ctxw_k<<<32, 256>>>(CTX1, CTX2, ep1_w, ep2_w, MWh, MWl);

    // 11,12: EP = y @ W1 + u @ M_b + bias (dual-source B)
    gemm_tc<true, false, true, false, true><<<g256, 256, DYN_SMEM>>>(
        P1h, P1l, 512, EPYh, EPYl, MWh, MWl, ep1_b,
        EP1, nullptr, nullptr, 512, 256);
    gemm_tc<true, false, true, false, true><<<g256, 256, DYN_SMEM>>>(
        P2h, P2l, 512, EPYh + 65536, EPYl + 65536, MWh + 16 * 65536, MWl + 16 * 65536,
        ep2_b, EP2, nullptr, nullptr, 512, 256);

    // 13: LN both paths -> MRG split
    ln_k<<<dim3(8192, 2), 256>>>(T1h, T1l, T2h, T2l, EP1, EP2,
                                 ln1_g, ln1_b, ln2_g, ln2_b, MRGh, MRGl);

    // 14: bias concat (0 | ce1_b)
    biascat_k<<<2, 256>>>(ce1_b, CB);

    // 15: res|ce1 concatenated GEMM -> RC [M, 512]
    gemm_tc<true, false, true, false, false><<<g512, 256, DYN_SMEM>>>(
        MRGh, MRGl, 512, WH + oRC, WL + oRC, nullptr, nullptr, CB,
        RC, nullptr, nullptr, 512, 512);

    // 16: 3x3 depthwise (+bias+relu) on CE1 half of RC -> DW split
    dw_k<<<dim3(8, 16, 16), 256>>>(RC + 256, 512, dw_w, dw_b, DWh, DWl);

    // 17: ce3 GEMM -> E
    gemm_tc<true, false, true, false, false><<<g256, 256, DYN_SMEM>>>(
        DWh, DWl, 256, WH + oCE3, WL + oCE3, nullptr, nullptr, ce3_b,
        E, nullptr, nullptr, 256, 256);

    // bn1 -> residual add -> bn2 -> final NCHW
    bn_part_k<<<256, 256>>>(E, BNP);
    bn_fin_k<<<1, 256>>>(BNP, bn1_g, bn1_b, SC1, SH1);
    addbn_k<<<16384, 256>>>(RC, E, SC1, SH1, F);
    bn_part_k<<<256, 256>>>(F, BNP);
    bn_fin_k<<<1, 256>>>(BNP, bn2_g, bn2_b, SC2, SH2);
    bn_final_k<<<dim3(128, 8, 16), dim3(32, 8)>>>(F, SC2, SH2, (float*)d_out);
}

// round 5
// speedup vs baseline: 2.5043x; 1.1524x over previous
#include <cuda_runtime.h>
#include <cuda_bf16.h>
#include <math.h>
#include <stdint.h>

namespace {
constexpr int Bn  = 16;
constexpr int Cn  = 256;
constexpr int HWn = 4096;
constexpr int NHn = 8;
constexpr int Mn  = Bn * HWn;          // 65536 rows
constexpr float EPSF  = 1e-5f;
constexpr float SCALE = 0.17677669529663687f;  // 32^-0.5

constexpr int ROWB   = 80;             // bytes per 32-bf16 row in smem
constexpr int MATB   = 128 * ROWB;     // 10240 bytes per matrix tile
constexpr int STAGEB = 4 * MATB;       // AH | AL | BH | BL = 40960
constexpr int NSTAGE = 2;
constexpr int DYN_SMEM = NSTAGE * STAGEB;   // 81920 -> 2 CTAs/SM
}

// ---------------- workspace (device globals; no allocation allowed) --------
__device__ __nv_bfloat16 g_T1h[(size_t)Mn * Cn];
__device__ __nv_bfloat16 g_T1l[(size_t)Mn * Cn];
__device__ __nv_bfloat16 g_T2h[(size_t)Mn * Cn];
__device__ __nv_bfloat16 g_T2l[(size_t)Mn * Cn];
__device__ __nv_bfloat16 g_P1h[(size_t)Mn * 2 * Cn];
__device__ __nv_bfloat16 g_P1l[(size_t)Mn * 2 * Cn];
__device__ __nv_bfloat16 g_P2h[(size_t)Mn * 2 * Cn];
__device__ __nv_bfloat16 g_P2l[(size_t)Mn * 2 * Cn];
__device__ float g_KV1[(size_t)Mn * 2 * Cn];
__device__ float g_KV2[(size_t)Mn * 2 * Cn];
__device__ float g_EP1[(size_t)Mn * Cn];
__device__ float g_EP2[(size_t)Mn * Cn];
__device__ __nv_bfloat16 g_MRGh[(size_t)Mn * 2 * Cn];
__device__ __nv_bfloat16 g_MRGl[(size_t)Mn * 2 * Cn];
__device__ float g_RC [(size_t)Mn * 2 * Cn];      // cols 0-255 RES, 256-511 CE1
__device__ __nv_bfloat16 g_DWh[(size_t)Mn * Cn];
__device__ __nv_bfloat16 g_DWl[(size_t)Mn * Cn];
__device__ float g_E  [(size_t)Mn * Cn];
__device__ float g_F  [(size_t)Mn * Cn];
__device__ __nv_bfloat16 g_WH[900000];
__device__ __nv_bfloat16 g_WL[900000];
__device__ __nv_bfloat16 g_EPYh[2 * 65536];
__device__ __nv_bfloat16 g_EPYl[2 * 65536];
__device__ __nv_bfloat16 g_MWh[2 * 16 * 65536];
__device__ __nv_bfloat16 g_MWl[2 * 16 * 65536];
__device__ float g_PART[(size_t)2 * Bn * NHn * 8 * 32 * 32];
__device__ float g_CTX1[(size_t)Bn * NHn * 32 * 32];
__device__ float g_CTX2[(size_t)Bn * NHn * 32 * 32];
__device__ float g_CB[512];
__device__ float g_BNP[256 * 512];
__device__ float g_SC1[Cn];
__device__ float g_SH1[Cn];
__device__ float g_SC2[Cn];
__device__ float g_SH2[Cn];

// ---------------- PTX helpers ----------------------------------------------
__device__ __forceinline__ uint32_t smem_u32(const void* p) {
    uint32_t a;
    asm("{ .reg .u64 t; cvta.to.shared.u64 t, %1; cvt.u32.u64 %0, t; }"
        : "=r"(a) : "l"(p));
    return a;
}

__device__ __forceinline__ void cpasync16(uint32_t dst, const void* src) {
    asm volatile("cp.async.cg.shared.global [%0], [%1], 16;"
                 :: "r"(dst), "l"(src));
}

__device__ __forceinline__ void ldsm4(uint32_t* r, uint32_t addr) {
    asm volatile("ldmatrix.sync.aligned.m8n8.x4.shared.b16 {%0,%1,%2,%3}, [%4];"
                 : "=r"(r[0]), "=r"(r[1]), "=r"(r[2]), "=r"(r[3]) : "r"(addr));
}

__device__ __forceinline__ void mma16816(float* d, const uint32_t* a, const uint32_t* b) {
    asm volatile(
        "mma.sync.aligned.m16n8k16.row.col.f32.bf16.bf16.f32 "
        "{%0,%1,%2,%3}, {%4,%5,%6,%7}, {%8,%9}, {%0,%1,%2,%3};"
        : "+f"(d[0]), "+f"(d[1]), "+f"(d[2]), "+f"(d[3])
        : "r"(a[0]), "r"(a[1]), "r"(a[2]), "r"(a[3]), "r"(b[0]), "r"(b[1]));
}

__device__ __forceinline__ void split2(float v, __nv_bfloat16& h, __nv_bfloat16& l) {
    h = __float2bfloat16(v);
    l = __float2bfloat16(v - __bfloat162float(h));
}

// ---------------- weight split: all contiguous weights in one launch --------
struct WsplitArgs {
    const float* src[7];   // cp1, cp2, kv1, kv2, res, ce1, ce3
};
__global__ void wsplit_all_k(WsplitArgs a, __nv_bfloat16* __restrict__ h,
                             __nv_bfloat16* __restrict__ l)
{
    const int i = blockIdx.x * 256 + threadIdx.x;
    if (i >= 851968) return;
    int seg, off;
    if (i < 786432) { seg = i >> 17; off = i & 131071; }
    else            { seg = 6;       off = i - 786432; }
    __nv_bfloat16 hh, ll; split2(a.src[seg][off], hh, ll);
    h[i] = hh; l[i] = ll;
}

// ---------------- ep static (y-part) weight: strided split ------------------
__global__ void wsplit_ep_k(const float* __restrict__ ep1_w, const float* __restrict__ ep2_w,
                            __nv_bfloat16* __restrict__ h, __nv_bfloat16* __restrict__ l)
{
    const int o = blockIdx.x;            // 0..255
    const int path = blockIdx.y;
    const int k = threadIdx.x;           // 0..255
    const float* w = path ? ep2_w : ep1_w;
    __nv_bfloat16 hh, ll; split2(w[o * 512 + k], hh, ll);
    const int idx = path * 65536 + o * 256 + k;
    h[idx] = hh; l[idx] = ll;
}

// ---------------- bias concat for res|ce1 GEMM -------------------------------
__global__ void biascat_k(const float* __restrict__ ce1_b, float* __restrict__ cb)
{
    const int t = threadIdx.x + blockIdx.x * 256;
    cb[t] = (t < 256) ? 0.f : ce1_b[t - 256];
}

// ---------------- transpose + split: x [B,C,HW] -> hi/lo [B,HW,C] -----------
__global__ void transpose_split_k(const float* __restrict__ x1, const float* __restrict__ x2,
                                  __nv_bfloat16* __restrict__ t1h, __nv_bfloat16* __restrict__ t1l,
                                  __nv_bfloat16* __restrict__ t2h, __nv_bfloat16* __restrict__ t2l)
{
    __shared__ float s[32][33];
    const int z = blockIdx.z;
    const int path = z >> 4;
    const int b = z & 15;
    const float* x = path ? x2 : x1;
    __nv_bfloat16* th = path ? t2h : t1h;
    __nv_bfloat16* tl = path ? t2l : t1l;
    const int c0 = blockIdx.y * 32;
    const int n0 = blockIdx.x * 32;
    const float* xb = x + (size_t)b * Cn * HWn;
    const int tx = threadIdx.x, ty = threadIdx.y;  // 32 x 8
    #pragma unroll
    for (int i = 0; i < 32; i += 8)
        s[ty + i][tx] = xb[(size_t)(c0 + ty + i) * HWn + n0 + tx];
    __syncthreads();
    #pragma unroll
    for (int i = 0; i < 32; i += 8) {
        const size_t idx = ((size_t)b * HWn + n0 + ty + i) * Cn + c0 + tx;
        __nv_bfloat16 h, l; split2(s[tx][ty + i], h, l);
        th[idx] = h; tl[idx] = l;
    }
}

// ---------------- HMMA split-bf16 GEMM, 2 CTAs/SM, 1-sync pipeline -----------
template<bool DUALB>
__device__ __forceinline__ void load_stage(
    uint32_t sb, int m0, int n0, int k0,
    const __nv_bfloat16* Ah, const __nv_bfloat16* Al, int lda,
    const __nv_bfloat16* W1h, const __nv_bfloat16* W1l,
    const __nv_bfloat16* W2h, const __nv_bfloat16* W2l,
    int K, int tid)
{
    #pragma unroll
    for (int j = 0; j < 2; j++) {                       // A tiles
        const int idx = j * 256 + tid;
        const int r = idx >> 2, c = idx & 3;
        const uint32_t dst = sb + r * ROWB + c * 16;
        const size_t so = (size_t)(m0 + r) * lda + k0 + c * 8;
        cpasync16(dst,        Ah + so);
        cpasync16(dst + MATB, Al + so);
    }
    #pragma unroll
    for (int j = 0; j < 2; j++) {                       // B tiles
        const int idx = j * 256 + tid;
        const int r = idx >> 2, c = idx & 3;
        const uint32_t dst = sb + 2 * MATB + r * ROWB + c * 16;
        if (!DUALB) {
            const size_t so = (size_t)(n0 + r) * K + k0 + c * 8;
            cpasync16(dst,        W1h + so);
            cpasync16(dst + MATB, W1l + so);
        } else if (k0 < 256) {
            const size_t so = (size_t)(n0 + r) * 256 + k0 + c * 8;
            cpasync16(dst,        W1h + so);
            cpasync16(dst + MATB, W1l + so);
        } else {
            const size_t so = (size_t)(n0 + r) * 256 + (k0 - 256) + c * 8;
            cpasync16(dst,        W2h + so);
            cpasync16(dst + MATB, W2l + so);
        }
    }
}

template<bool BIAS, bool RELU, bool OUTF, bool OUTB, bool DUALB>
__global__ void __launch_bounds__(256, 2)
gemm_tc(const __nv_bfloat16* __restrict__ Ah, const __nv_bfloat16* __restrict__ Al, int lda,
        const __nv_bfloat16* __restrict__ W1h, const __nv_bfloat16* __restrict__ W1l,
        const __nv_bfloat16* __restrict__ W2h, const __nv_bfloat16* __restrict__ W2l,
        const float* __restrict__ bias,
        float* __restrict__ outF,
        __nv_bfloat16* __restrict__ outH, __nv_bfloat16* __restrict__ outL,
        int K, int Nout)
{
    extern __shared__ char dyn_smem[];
    const int tid  = threadIdx.x;
    const int wid  = tid >> 5;
    const int lane = tid & 31;
    const int m0 = blockIdx.y * 128;
    const int n0 = blockIdx.x * 128;
    const int wm0 = (wid & 1) * 64;
    const int wn0 = (wid >> 1) * 32;

    if (DUALB) {
        const size_t boff = (size_t)(m0 >> 12) * 65536;
        W2h += boff; W2l += boff;
    }

    const uint32_t base = smem_u32(dyn_smem);

    float acc[4][4][4];
    #pragma unroll
    for (int i = 0; i < 4; i++)
        #pragma unroll
        for (int j = 0; j < 4; j++)
            #pragma unroll
            for (int q = 0; q < 4; q++) acc[i][j][q] = 0.f;

    const uint32_t aOff = (uint32_t)(wm0 + (lane & 15)) * ROWB + ((lane >> 4) * 16);
    const uint32_t bOff = (uint32_t)(wn0 + ((lane >> 4) * 8) + (lane & 7)) * ROWB
                        + (((lane >> 3) & 1) * 16);

    const int S = K / 32;
    load_stage<DUALB>(base, m0, n0, 0, Ah, Al, lda, W1h, W1l, W2h, W2l, K, tid);
    asm volatile("cp.async.commit_group;" ::: "memory");

    uint32_t buf = 0;
    for (int s = 0; s < S; s++) {
        asm volatile("cp.async.wait_group 0;" ::: "memory");
        __syncthreads();
        // prefetch next stage into the other buffer (safe: that buffer was
        // last read before the barrier above)
        if (s + 1 < S) {
            load_stage<DUALB>(base + (buf ^ 1) * STAGEB, m0, n0, (s + 1) * 32,
                              Ah, Al, lda, W1h, W1l, W2h, W2l, K, tid);
            asm volatile("cp.async.commit_group;" ::: "memory");
        }
        const uint32_t sb = base + buf * STAGEB;
        #pragma unroll
        for (int ks = 0; ks < 2; ks++) {
            const uint32_t kb = ks * 32;
            uint32_t bH[2][4], bL[2][4];
            #pragma unroll
            for (int np = 0; np < 2; np++) {
                const uint32_t bd = sb + 2 * MATB + bOff + np * 16 * ROWB + kb;
                ldsm4(bH[np], bd);
                ldsm4(bL[np], bd + MATB);
            }
            #pragma unroll
            for (int mi = 0; mi < 4; mi++) {
                uint32_t aH[4], aL[4];
                const uint32_t ad = sb + aOff + mi * 16 * ROWB + kb;
                ldsm4(aH, ad);
                ldsm4(aL, ad + MATB);
                #pragma unroll
                for (int ni = 0; ni < 4; ni++)
                    mma16816(acc[mi][ni], aH, &bH[ni >> 1][(ni & 1) * 2]);
                #pragma unroll
                for (int ni = 0; ni < 4; ni++)
                    mma16816(acc[mi][ni], aH, &bL[ni >> 1][(ni & 1) * 2]);
                #pragma unroll
                for (int ni = 0; ni < 4; ni++)
                    mma16816(acc[mi][ni], aL, &bH[ni >> 1][(ni & 1) * 2]);
            }
        }
        buf ^= 1;
    }

    // epilogue
    #pragma unroll
    for (int ni = 0; ni < 4; ni++) {
        const int cidx = n0 + wn0 + ni * 8 + (lane & 3) * 2;
        float b0 = 0.f, b1 = 0.f;
        if (BIAS) { b0 = bias[cidx]; b1 = bias[cidx + 1]; }
        #pragma unroll
        for (int mi = 0; mi < 4; mi++) {
            const int r0 = m0 + wm0 + mi * 16 + (lane >> 2);
            #pragma unroll
            for (int half = 0; half < 2; half++) {
                const int r = r0 + half * 8;
                float v0 = acc[mi][ni][half * 2 + 0];
                float v1 = acc[mi][ni][half * 2 + 1];
                if (BIAS) { v0 += b0; v1 += b1; }
                if (RELU) { v0 = fmaxf(v0, 0.f); v1 = fmaxf(v1, 0.f); }
                if (OUTF) {
                    float2 f2 = make_float2(v0, v1);
                    *reinterpret_cast<float2*>(outF + (size_t)r * Nout + cidx) = f2;
                }
                if (OUTB) {
                    __nv_bfloat16 h0, l0, h1, l1;
                    split2(v0, h0, l0); split2(v1, h1, l1);
                    __nv_bfloat162 hh; hh.x = h0; hh.y = h1;
                    __nv_bfloat162 ll; ll.x = l0; ll.y = l1;
                    *reinterpret_cast<__nv_bfloat162*>(outH + (size_t)r * Nout + cidx) = hh;
                    *reinterpret_cast<__nv_bfloat162*>(outL + (size_t)r * Nout + cidx) = ll;
                }
            }
        }
    }
}

// ------------- ctx partial: per (chunk,h,b,path) K^T V over 512 rows --------
__global__ void __launch_bounds__(64)
ctx_partial_k(const float* __restrict__ KV1, const float* __restrict__ KV2,
              float* __restrict__ part)
{
    __shared__ float Ks[64][32];
    __shared__ float Vs[64][32];
    const int chunk = blockIdx.x, h = blockIdx.y, z = blockIdx.z;
    const int b = z & 15;
    const float* KV = (z < 16) ? KV1 : KV2;
    const int t = threadIdx.x, lane = t & 31, w = t >> 5;
    const float* base = KV + (size_t)b * HWn * 512;
    const int d0 = (t >> 3) * 4, e0 = (t & 7) * 4;
    float acc[4][4] = {};
    for (int nb = 0; nb < 512; nb += 64) {
        const int row0 = chunk * 512 + nb;
        for (int r = w; r < 64; r += 2) {
            const float* rp = base + (size_t)(row0 + r) * 512 + h * 32;
            Ks[r][lane] = rp[lane];
            Vs[r][lane] = rp[256 + lane];
        }
        __syncthreads();
        #pragma unroll 8
        for (int n = 0; n < 64; n++) {
            float4 k4 = *reinterpret_cast<float4*>(&Ks[n][d0]);
            float4 v4 = *reinterpret_cast<float4*>(&Vs[n][e0]);
            const float kk[4] = {k4.x, k4.y, k4.z, k4.w};
            const float vv[4] = {v4.x, v4.y, v4.z, v4.w};
            #pragma unroll
            for (int i = 0; i < 4; i++)
                #pragma unroll
                for (int j = 0; j < 4; j++)
                    acc[i][j] = fmaf(kk[i], vv[j], acc[i][j]);
        }
        __syncthreads();
    }
    float* p = part + ((size_t)(z * NHn + h) * 8 + chunk) * 1024;
    #pragma unroll
    for (int i = 0; i < 4; i++)
        #pragma unroll
        for (int j = 0; j < 4; j++)
            p[(d0 + i) * 32 + e0 + j] = acc[i][j];
}

// ------------- ctx finalize: sum partials, scale, softmax over d -----------
__global__ void ctx_final_k(const float* __restrict__ part, float* __restrict__ ctx1,
                            float* __restrict__ ctx2)
{
    __shared__ float S[32][33];
    const int bhg = blockIdx.x;        // [0,256): path*128 + bh
    float* ctx = (bhg < 128) ? ctx1 : ctx2;
    const int bh = bhg & 127;
    const int t  = threadIdx.x;
    const float* p = part + (size_t)bhg * 8 * 1024;
    for (int idx = t; idx < 1024; idx += 256) {
        float s = 0.f;
        #pragma unroll
        for (int c = 0; c < 8; c++) s += p[c * 1024 + idx];
        S[idx >> 5][idx & 31] = s * SCALE;
    }
    __syncthreads();
    if (t < 32) {
        float mx = -1e30f;
        #pragma unroll
        for (int d = 0; d < 32; d++) mx = fmaxf(mx, S[d][t]);
        float e[32], sum = 0.f;
        #pragma unroll
        for (int d = 0; d < 32; d++) { e[d] = expf(S[d][t] - mx); sum += e[d]; }
        const float inv = 1.f / sum;
        float* o = ctx + (size_t)bh * 1024;
        #pragma unroll
        for (int d = 0; d < 32; d++) o[d * 32 + t] = e[d] * inv;
    }
}

// ------------- build per-batch ep "M" weights: M[o, j] (split bf16) ---------
__global__ void __launch_bounds__(256)
ctxw_k(const float* __restrict__ ctx1, const float* __restrict__ ctx2,
       const float* __restrict__ ep1_w, const float* __restrict__ ep2_w,
       __nv_bfloat16* __restrict__ mwh, __nv_bfloat16* __restrict__ mwl)
{
    __shared__ float cs[8192];
    const int z = blockIdx.x;                 // path*16 + b
    const int path = z >> 4;
    const int b = z & 15;
    const float* ctx = path ? ctx1 : ctx2;
    const float* epw = path ? ep2_w : ep1_w;
    const int j = threadIdx.x;                // u-column 0..255
    for (int i = j; i < 8192; i += 256)
        cs[i] = ctx[(size_t)b * 8192 + i];
    __syncthreads();
    const int h = j >> 5, d = j & 31;
    float c[32];
    #pragma unroll
    for (int e = 0; e < 32; e++) c[e] = cs[h * 1024 + d * 32 + e];
    __nv_bfloat16* oh = mwh + (size_t)z * 65536;
    __nv_bfloat16* ol = mwl + (size_t)z * 65536;
    for (int o = 0; o < 256; o++) {
        const float* wr = epw + (size_t)o * 512 + 256 + h * 32;
        float a = 0.f;
        #pragma unroll
        for (int e = 0; e < 32; e++) a = fmaf(c[e], __ldg(wr + e), a);
        __nv_bfloat16 hh, ll; split2(a, hh, ll);
        oh[o * 256 + j] = hh; ol[o * 256 + j] = ll;
    }
}

// ------------- LayerNorm: MRG[:, mco..] = LN((Th+Tl) + EP)*g + b -------------
__global__ void __launch_bounds__(256)
ln_k(const __nv_bfloat16* __restrict__ T1h, const __nv_bfloat16* __restrict__ T1l,
     const __nv_bfloat16* __restrict__ T2h, const __nv_bfloat16* __restrict__ T2l,
     const float* __restrict__ EP1, const float* __restrict__ EP2,
     const float* __restrict__ g1, const float* __restrict__ b1,
     const float* __restrict__ g2, const float* __restrict__ b2,
     __nv_bfloat16* __restrict__ MH, __nv_bfloat16* __restrict__ ML)
{
    const int path = blockIdx.y;
    const __nv_bfloat16* Th = path ? T2h : T1h;
    const __nv_bfloat16* Tl = path ? T2l : T1l;
    const float* EP = path ? EP2 : EP1;
    const float* g  = path ? g2 : g1;
    const float* be = path ? b2 : b1;
    const int mco = path * 256;
    const int w    = blockIdx.x * 8 + (threadIdx.x >> 5);
    const int lane = threadIdx.x & 31;
    const __nv_bfloat16* th = Th + (size_t)w * 256;
    const __nv_bfloat16* tl = Tl + (size_t)w * 256;
    const float* er = EP + (size_t)w * 256;
    float v[8], sum = 0.f, sq = 0.f;
    #pragma unroll
    for (int i = 0; i < 8; i++) {
        const int c = lane + i * 32;
        const float x = __bfloat162float(th[c]) + __bfloat162float(tl[c]) + er[c];
        v[i] = x; sum += x; sq += x * x;
    }
    #pragma unroll
    for (int o = 16; o; o >>= 1) {
        sum += __shfl_xor_sync(0xffffffffu, sum, o);
        sq  += __shfl_xor_sync(0xffffffffu, sq,  o);
    }
    const float mean = sum * (1.f / 256.f);
    const float var  = sq * (1.f / 256.f) - mean * mean;
    const float rs   = rsqrtf(var + EPSF);
    const size_t ob = (size_t)w * 512 + mco;
    #pragma unroll
    for (int i = 0; i < 8; i++) {
        const int c = lane + i * 32;
        const float y = (v[i] - mean) * rs * g[c] + be[c];
        __nv_bfloat16 hh, ll; split2(y, hh, ll);
        MH[ob + c] = hh; ML[ob + c] = ll;
    }
}

// ------------- 3x3 depthwise conv on [M,ld] layout + bias + relu, split out --
__global__ void __launch_bounds__(256)
dw_k(const float* __restrict__ X, int ldx, const float* __restrict__ w9,
     const float* __restrict__ db, __nv_bfloat16* __restrict__ Yh,
     __nv_bfloat16* __restrict__ Yl)
{
    __shared__ float s[18 * 18 * 32];
    const int cc   = blockIdx.x;
    const int tile = blockIdx.y;
    const int b    = blockIdx.z;
    const int ty0 = (tile >> 2) * 16, tx0 = (tile & 3) * 16;
    const int c0 = cc * 32;
    const int tid = threadIdx.x;
    for (int i = tid; i < 18 * 18 * 32; i += 256) {
        const int c = i & 31;
        const int sp = i >> 5;
        const int x = sp % 18 - 1 + tx0;
        const int y = sp / 18 - 1 + ty0;
        float v = 0.f;
        if (x >= 0 && x < 64 && y >= 0 && y < 64)
            v = X[(size_t)(b * 4096 + y * 64 + x) * ldx + c0 + c];
        s[i] = v;
    }
    const int c = tid & 31;
    float kr[9];
    #pragma unroll
    for (int j = 0; j < 9; j++) kr[j] = w9[(c0 + c) * 9 + j];
    const float bb = db[c0 + c];
    __syncthreads();
    for (int o = tid; o < 8192; o += 256) {
        const int sp = o >> 5;
        const int x = sp & 15, y = sp >> 4;
        float a = 0.f;
        #pragma unroll
        for (int dy = 0; dy < 3; dy++)
            #pragma unroll
            for (int dx = 0; dx < 3; dx++)
                a = fmaf(s[((y + dy) * 18 + (x + dx)) * 32 + c], kr[dy * 3 + dx], a);
        a = fmaxf(a + bb, 0.f);
        const size_t idx = (size_t)(b * 4096 + (ty0 + y) * 64 + tx0 + x) * 256 + c0 + c;
        __nv_bfloat16 hh, ll; split2(a, hh, ll);
        Yh[idx] = hh; Yl[idx] = ll;
    }
}

// ------------- BN stats on [M,256] fp32: two-stage ---------------------------
__global__ void __launch_bounds__(256)
bn_part_k(const float* __restrict__ X, float* __restrict__ part)
{
    const int seg = blockIdx.x;
    const int c   = threadIdx.x;
    const float* p = X + (size_t)seg * 256 * 256;
    float s = 0.f, q = 0.f;
    #pragma unroll 8
    for (int r = 0; r < 256; r++) {
        const float v = p[(size_t)r * 256 + c];
        s += v; q = fmaf(v, v, q);
    }
    part[seg * 512 + c] = s;
    part[seg * 512 + 256 + c] = q;
}

__global__ void bn_fin_k(const float* __restrict__ part, const float* __restrict__ g,
                         const float* __restrict__ be, float* __restrict__ sc,
                         float* __restrict__ sh)
{
    const int c = threadIdx.x;
    float s = 0.f, q = 0.f;
    for (int seg = 0; seg < 256; seg++) {
        s += part[seg * 512 + c];
        q += part[seg * 512 + 256 + c];
    }
    const float inv = 1.f / 65536.f;
    const float m   = s * inv;
    const float var = q * inv - m * m;
    const float scv = g[c] * rsqrtf(var + EPSF);
    sc[c] = scv;
    sh[c] = be[c] - m * scv;
}

// ------------- F = RES(RC col0-255) + E*sc + sh ------------------------------
__global__ void addbn_k(const float* __restrict__ RC, const float* __restrict__ E,
                        const float* __restrict__ sc, const float* __restrict__ sh,
                        float* __restrict__ F)
{
    const int i4 = blockIdx.x * 256 + threadIdx.x;
    const int r  = i4 >> 6;
    const int c0 = (i4 & 63) * 4;
    const float4 s = *reinterpret_cast<const float4*>(sc + c0);
    const float4 h = *reinterpret_cast<const float4*>(sh + c0);
    const float4 rr = *reinterpret_cast<const float4*>(RC + (size_t)r * 512 + c0);
    const float4 e = reinterpret_cast<const float4*>(E)[i4];
    float4 f;
    f.x = fmaf(e.x, s.x, rr.x + h.x);
    f.y = fmaf(e.y, s.y, rr.y + h.y);
    f.z = fmaf(e.z, s.z, rr.z + h.z);
    f.w = fmaf(e.w, s.w, rr.w + h.w);
    reinterpret_cast<float4*>(F)[i4] = f;
}

// ------------- final: out NCHW = bn2(F) via transpose ------------------------
__global__ void bn_final_k(const float* __restrict__ F, const float* __restrict__ sc,
                           const float* __restrict__ sh, float* __restrict__ O)
{
    __shared__ float s[32][33];
    const int b  = blockIdx.z;
    const int c0 = blockIdx.y * 32;
    const int n0 = blockIdx.x * 32;
    const int tx = threadIdx.x, ty = threadIdx.y;
    #pragma unroll
    for (int i = 0; i < 32; i += 8)
        s[ty + i][tx] = F[((size_t)(b * 4096 + n0 + ty + i)) * 256 + c0 + tx];
    __syncthreads();
    #pragma unroll
    for (int i = 0; i < 32; i += 8) {
        const int c = c0 + ty + i;
        O[((size_t)(b * 256 + c)) * 4096 + n0 + tx] = s[tx][ty + i] * sc[c] + sh[c];
    }
}

// ===========================================================================
extern "C" void kernel_launch(void* const* d_in, const int* in_sizes, int n_in,
                              void* d_out, int out_size)
{
    (void)in_sizes; (void)n_in; (void)out_size;
    const float* x1    = (const float*)d_in[0];
    const float* x2    = (const float*)d_in[1];
    const float* cp1_w = (const float*)d_in[2];
    const float* cp1_b = (const float*)d_in[3];
    const float* cp2_w = (const float*)d_in[4];
    const float* cp2_b = (const float*)d_in[5];
    const float* kv1_w = (const float*)d_in[6];
    const float* kv2_w = (const float*)d_in[7];
    const float* ep1_w = (const float*)d_in[8];
    const float* ep1_b = (const float*)d_in[9];
    const float* ep2_w = (const float*)d_in[10];
    const float* ep2_b = (const float*)d_in[11];
    const float* ln1_g = (const float*)d_in[12];
    const float* ln1_b = (const float*)d_in[13];
    const float* ln2_g = (const float*)d_in[14];
    const float* ln2_b = (const float*)d_in[15];
    const float* res_w = (const float*)d_in[16];
    const float* ce1_w = (const float*)d_in[17];
    const float* ce1_b = (const float*)d_in[18];
    const float* dw_w  = (const float*)d_in[19];
    const float* dw_b  = (const float*)d_in[20];
    const float* ce3_w = (const float*)d_in[21];
    const float* ce3_b = (const float*)d_in[22];
    const float* bn1_g = (const float*)d_in[23];
    const float* bn1_b = (const float*)d_in[24];
    const float* bn2_g = (const float*)d_in[25];
    const float* bn2_b = (const float*)d_in[26];

    float *KV1, *KV2, *EP1, *EP2, *RC, *E, *F;
    float *PART, *CTX1, *CTX2, *CB, *BNP, *SC1, *SH1, *SC2, *SH2;
    __nv_bfloat16 *T1h, *T1l, *T2h, *T2l, *P1h, *P1l, *P2h, *P2l;
    __nv_bfloat16 *MRGh, *MRGl, *DWh, *DWl, *WH, *WL, *EPYh, *EPYl, *MWh, *MWl;
    cudaGetSymbolAddress((void**)&T1h, g_T1h);
    cudaGetSymbolAddress((void**)&T1l, g_T1l);
    cudaGetSymbolAddress((void**)&T2h, g_T2h);
    cudaGetSymbolAddress((void**)&T2l, g_T2l);
    cudaGetSymbolAddress((void**)&P1h, g_P1h);
    cudaGetSymbolAddress((void**)&P1l, g_P1l);
    cudaGetSymbolAddress((void**)&P2h, g_P2h);
    cudaGetSymbolAddress((void**)&P2l, g_P2l);
    cudaGetSymbolAddress((void**)&KV1, g_KV1);
    cudaGetSymbolAddress((void**)&KV2, g_KV2);
    cudaGetSymbolAddress((void**)&EP1, g_EP1);
    cudaGetSymbolAddress((void**)&EP2, g_EP2);
    cudaGetSymbolAddress((void**)&MRGh, g_MRGh);
    cudaGetSymbolAddress((void**)&MRGl, g_MRGl);
    cudaGetSymbolAddress((void**)&RC,  g_RC);
    cudaGetSymbolAddress((void**)&DWh, g_DWh);
    cudaGetSymbolAddress((void**)&DWl, g_DWl);
    cudaGetSymbolAddress((void**)&E,   g_E);
    cudaGetSymbolAddress((void**)&F,   g_F);
    cudaGetSymbolAddress((void**)&WH,  g_WH);
    cudaGetSymbolAddress((void**)&WL,  g_WL);
    cudaGetSymbolAddress((void**)&EPYh, g_EPYh);
    cudaGetSymbolAddress((void**)&EPYl, g_EPYl);
    cudaGetSymbolAddress((void**)&MWh, g_MWh);
    cudaGetSymbolAddress((void**)&MWl, g_MWl);
    cudaGetSymbolAddress((void**)&PART, g_PART);
    cudaGetSymbolAddress((void**)&CTX1, g_CTX1);
    cudaGetSymbolAddress((void**)&CTX2, g_CTX2);
    cudaGetSymbolAddress((void**)&CB,  g_CB);
    cudaGetSymbolAddress((void**)&BNP, g_BNP);
    cudaGetSymbolAddress((void**)&SC1, g_SC1);
    cudaGetSymbolAddress((void**)&SH1, g_SH1);
    cudaGetSymbolAddress((void**)&SC2, g_SC2);
    cudaGetSymbolAddress((void**)&SH2, g_SH2);

    cudaFuncSetAttribute(gemm_tc<true,  true,  false, true , false>,
                         cudaFuncAttributeMaxDynamicSharedMemorySize, DYN_SMEM);
    cudaFuncSetAttribute(gemm_tc<false, false, true,  false, false>,
                         cudaFuncAttributeMaxDynamicSharedMemorySize, DYN_SMEM);
    cudaFuncSetAttribute(gemm_tc<true,  false, true,  false, true >,
                         cudaFuncAttributeMaxDynamicSharedMemorySize, DYN_SMEM);
    cudaFuncSetAttribute(gemm_tc<true,  false, true,  false, false>,
                         cudaFuncAttributeMaxDynamicSharedMemorySize, DYN_SMEM);

    // weight slots in WH/WL (851968 total)
    const size_t oCP1 = 0, oCP2 = 131072, oKV1 = 262144, oKV2 = 393216;
    const size_t oRC = 524288, oCE3 = 786432;
    WsplitArgs wa;
    wa.src[0] = cp1_w; wa.src[1] = cp2_w; wa.src[2] = kv1_w; wa.src[3] = kv2_w;
    wa.src[4] = res_w; wa.src[5] = ce1_w; wa.src[6] = ce3_w;

    wsplit_all_k<<<3328, 256>>>(wa, WH, WL);
    wsplit_ep_k<<<dim3(256, 2), 256>>>(ep1_w, ep2_w, EPYh, EPYl);
    transpose_split_k<<<dim3(128, 8, 32), dim3(32, 8)>>>(x1, x2, T1h, T1l, T2h, T2l);

    const dim3 g512(4, 512);
    const dim3 g256(2, 512);

    // CrossPath P = relu(T @ cp_w^T + b) -> split bf16
    gemm_tc<true, true, false, true, false><<<g512, 256, DYN_SMEM>>>(
        T1h, T1l, 256, WH + oCP1, WL + oCP1, nullptr, nullptr, cp1_b,
        nullptr, P1h, P1l, 256, 512);
    gemm_tc<true, true, false, true, false><<<g512, 256, DYN_SMEM>>>(
        T2h, T2l, 256, WH + oCP2, WL + oCP2, nullptr, nullptr, cp2_b,
        nullptr, P2h, P2l, 256, 512);

    // KV = u @ kv_w^T -> fp32
    gemm_tc<false, false, true, false, false><<<g512, 256, DYN_SMEM>>>(
        P1h + 256, P1l + 256, 512, WH + oKV1, WL + oKV1, nullptr, nullptr, nullptr,
        KV1, nullptr, nullptr, 256, 512);
    gemm_tc<false, false, true, false, false><<<g512, 256, DYN_SMEM>>>(
        P2h + 256, P2l + 256, 512, WH + oKV2, WL + oKV2, nullptr, nullptr, nullptr,
        KV2, nullptr, nullptr, 256, 512);

    // ctx = softmax_d(scale * K^T V), both paths
    ctx_partial_k<<<dim3(8, 8, 32), 64>>>(KV1, KV2, PART);
    ctx_final_k<<<256, 256>>>(PART, CTX1, CTX2);

    // per-batch M weights for the fused ep GEMM (cross-wired)
    ctxw_k<<<32, 256>>>(CTX1, CTX2, ep1_w, ep2_w, MWh, MWl);

    // EP = y @ W1 + u @ M_b + bias (dual-source B)
    gemm_tc<true, false, true, false, true><<<g256, 256, DYN_SMEM>>>(
        P1h, P1l, 512, EPYh, EPYl, MWh, MWl, ep1_b,
        EP1, nullptr, nullptr, 512, 256);
    gemm_tc<true, false, true, false, true><<<g256, 256, DYN_SMEM>>>(
        P2h, P2l, 512, EPYh + 65536, EPYl + 65536, MWh + 16 * 65536, MWl + 16 * 65536,
        ep2_b, EP2, nullptr, nullptr, 512, 256);

    // LN both paths -> MRG split
    ln_k<<<dim3(8192, 2), 256>>>(T1h, T1l, T2h, T2l, EP1, EP2,
                                 ln1_g, ln1_b, ln2_g, ln2_b, MRGh, MRGl);

    // bias concat (0 | ce1_b)
    biascat_k<<<2, 256>>>(ce1_b, CB);

    // res|ce1 concatenated GEMM -> RC [M, 512]
    gemm_tc<true, false, true, false, false><<<g512, 256, DYN_SMEM>>>(
        MRGh, MRGl, 512, WH + oRC, WL + oRC, nullptr, nullptr, CB,
        RC, nullptr, nullptr, 512, 512);

    // 3x3 depthwise (+bias+relu) on CE1 half of RC -> DW split
    dw_k<<<dim3(8, 16, 16), 256>>>(RC + 256, 512, dw_w, dw_b, DWh, DWl);

    // ce3 GEMM -> E
    gemm_tc<true, false, true, false, false><<<g256, 256, DYN_SMEM>>>(
        DWh, DWl, 256, WH + oCE3, WL + oCE3, nullptr, nullptr, ce3_b,
        E, nullptr, nullptr, 256, 256);

    // bn1 -> residual add -> bn2 -> final NCHW
    bn_part_k<<<256, 256>>>(E, BNP);
    bn_fin_k<<<1, 256>>>(BNP, bn1_g, bn1_b, SC1, SH1);
    addbn_k<<<16384, 256>>>(RC, E, SC1, SH1, F);
    bn_part_k<<<256, 256>>>(F, BNP);
    bn_fin_k<<<1, 256>>>(BNP, bn2_g, bn2_b, SC2, SH2);
    bn_final_k<<<dim3(128, 8, 16), dim3(32, 8)>>>(F, SC2, SH2, (float*)d_out);
}

// round 6
// speedup vs baseline: 2.5065x; 1.0009x over previous
#include <cuda_runtime.h>
#include <cuda_bf16.h>
#include <math.h>
#include <stdint.h>

namespace {
constexpr int Bn  = 16;
constexpr int Cn  = 256;
constexpr int HWn = 4096;
constexpr int NHn = 8;
constexpr int Mn  = Bn * HWn;          // 65536 rows
constexpr float EPSF  = 1e-5f;
constexpr float SCALE = 0.17677669529663687f;  // 32^-0.5

constexpr int ROWB   = 80;             // bytes per 32-bf16 row in smem
constexpr int MATB   = 128 * ROWB;     // 10240 bytes per matrix tile
constexpr int STAGEB = 4 * MATB;       // AH | AL | BH | BL = 40960
constexpr int NSTAGE = 2;
constexpr int DYN_SMEM = NSTAGE * STAGEB;   // 81920 -> 2 CTAs/SM
}

// ---------------- workspace (device globals; no allocation allowed) --------
__device__ __nv_bfloat16 g_T1h[(size_t)Mn * Cn];
__device__ __nv_bfloat16 g_T1l[(size_t)Mn * Cn];
__device__ __nv_bfloat16 g_T2h[(size_t)Mn * Cn];
__device__ __nv_bfloat16 g_T2l[(size_t)Mn * Cn];
__device__ __nv_bfloat16 g_P1h[(size_t)Mn * 2 * Cn];
__device__ __nv_bfloat16 g_P1l[(size_t)Mn * 2 * Cn];
__device__ __nv_bfloat16 g_P2h[(size_t)Mn * 2 * Cn];
__device__ __nv_bfloat16 g_P2l[(size_t)Mn * 2 * Cn];
__device__ float g_KV1[(size_t)Mn * 2 * Cn];
__device__ float g_KV2[(size_t)Mn * 2 * Cn];
__device__ float g_EP1[(size_t)Mn * Cn];
__device__ float g_EP2[(size_t)Mn * Cn];
__device__ __nv_bfloat16 g_MRGh[(size_t)Mn * 2 * Cn];
__device__ __nv_bfloat16 g_MRGl[(size_t)Mn * 2 * Cn];
__device__ float g_RC [(size_t)Mn * 2 * Cn];      // cols 0-255 RES, 256-511 CE1
__device__ __nv_bfloat16 g_DWh[(size_t)Mn * Cn];
__device__ __nv_bfloat16 g_DWl[(size_t)Mn * Cn];
__device__ float g_E  [(size_t)Mn * Cn];
__device__ float g_F  [(size_t)Mn * Cn];
__device__ __nv_bfloat16 g_WH[900000];
__device__ __nv_bfloat16 g_WL[900000];
__device__ __nv_bfloat16 g_EPYh[2 * 65536];
__device__ __nv_bfloat16 g_EPYl[2 * 65536];
__device__ __nv_bfloat16 g_MWh[2 * 16 * 65536];
__device__ __nv_bfloat16 g_MWl[2 * 16 * 65536];
__device__ float g_PART[(size_t)2 * Bn * NHn * 8 * 32 * 32];
__device__ float g_CTX1[(size_t)Bn * NHn * 32 * 32];
__device__ float g_CTX2[(size_t)Bn * NHn * 32 * 32];
__device__ float g_CB[512];
__device__ float g_BNP[256 * 512];
__device__ float g_SC1[Cn];
__device__ float g_SH1[Cn];
__device__ float g_SC2[Cn];
__device__ float g_SH2[Cn];

// ---------------- PTX helpers ----------------------------------------------
__device__ __forceinline__ uint32_t smem_u32(const void* p) {
    uint32_t a;
    asm("{ .reg .u64 t; cvta.to.shared.u64 t, %1; cvt.u32.u64 %0, t; }"
        : "=r"(a) : "l"(p));
    return a;
}

__device__ __forceinline__ void cpasync16(uint32_t dst, const void* src) {
    asm volatile("cp.async.cg.shared.global [%0], [%1], 16;"
                 :: "r"(dst), "l"(src));
}

__device__ __forceinline__ void ldsm4(uint32_t* r, uint32_t addr) {
    asm volatile("ldmatrix.sync.aligned.m8n8.x4.shared.b16 {%0,%1,%2,%3}, [%4];"
                 : "=r"(r[0]), "=r"(r[1]), "=r"(r[2]), "=r"(r[3]) : "r"(addr));
}

__device__ __forceinline__ void mma16816(float* d, const uint32_t* a, const uint32_t* b) {
    asm volatile(
        "mma.sync.aligned.m16n8k16.row.col.f32.bf16.bf16.f32 "
        "{%0,%1,%2,%3}, {%4,%5,%6,%7}, {%8,%9}, {%0,%1,%2,%3};"
        : "+f"(d[0]), "+f"(d[1]), "+f"(d[2]), "+f"(d[3])
        : "r"(a[0]), "r"(a[1]), "r"(a[2]), "r"(a[3]), "r"(b[0]), "r"(b[1]));
}

__device__ __forceinline__ void split2(float v, __nv_bfloat16& h, __nv_bfloat16& l) {
    h = __float2bfloat16(v);
    l = __float2bfloat16(v - __bfloat162float(h));
}

// ---------------- weight split: all contiguous weights in one launch --------
struct WsplitArgs {
    const float* src[7];   // cp1, cp2, kv1, kv2, res, ce1, ce3
};
__global__ void wsplit_all_k(WsplitArgs a, __nv_bfloat16* __restrict__ h,
                             __nv_bfloat16* __restrict__ l)
{
    const int i = blockIdx.x * 256 + threadIdx.x;
    if (i >= 851968) return;
    int seg, off;
    if (i < 786432) { seg = i >> 17; off = i & 131071; }
    else            { seg = 6;       off = i - 786432; }
    __nv_bfloat16 hh, ll; split2(a.src[seg][off], hh, ll);
    h[i] = hh; l[i] = ll;
}

// ---------------- ep static (y-part) weight: strided split ------------------
__global__ void wsplit_ep_k(const float* __restrict__ ep1_w, const float* __restrict__ ep2_w,
                            __nv_bfloat16* __restrict__ h, __nv_bfloat16* __restrict__ l)
{
    const int o = blockIdx.x;            // 0..255
    const int path = blockIdx.y;
    const int k = threadIdx.x;           // 0..255
    const float* w = path ? ep2_w : ep1_w;
    __nv_bfloat16 hh, ll; split2(w[o * 512 + k], hh, ll);
    const int idx = path * 65536 + o * 256 + k;
    h[idx] = hh; l[idx] = ll;
}

// ---------------- bias concat for res|ce1 GEMM -------------------------------
__global__ void biascat_k(const float* __restrict__ ce1_b, float* __restrict__ cb)
{
    const int t = threadIdx.x + blockIdx.x * 256;
    cb[t] = (t < 256) ? 0.f : ce1_b[t - 256];
}

// ---------------- transpose + split: x [B,C,HW] -> hi/lo [B,HW,C] -----------
__global__ void transpose_split_k(const float* __restrict__ x1, const float* __restrict__ x2,
                                  __nv_bfloat16* __restrict__ t1h, __nv_bfloat16* __restrict__ t1l,
                                  __nv_bfloat16* __restrict__ t2h, __nv_bfloat16* __restrict__ t2l)
{
    __shared__ float s[32][33];
    const int z = blockIdx.z;
    const int path = z >> 4;
    const int b = z & 15;
    const float* x = path ? x2 : x1;
    __nv_bfloat16* th = path ? t2h : t1h;
    __nv_bfloat16* tl = path ? t2l : t1l;
    const int c0 = blockIdx.y * 32;
    const int n0 = blockIdx.x * 32;
    const float* xb = x + (size_t)b * Cn * HWn;
    const int tx = threadIdx.x, ty = threadIdx.y;  // 32 x 8
    #pragma unroll
    for (int i = 0; i < 32; i += 8)
        s[ty + i][tx] = xb[(size_t)(c0 + ty + i) * HWn + n0 + tx];
    __syncthreads();
    #pragma unroll
    for (int i = 0; i < 32; i += 8) {
        const size_t idx = ((size_t)b * HWn + n0 + ty + i) * Cn + c0 + tx;
        __nv_bfloat16 h, l; split2(s[tx][ty + i], h, l);
        th[idx] = h; tl[idx] = l;
    }
}

// ---------------- HMMA split-bf16 GEMM, 2 CTAs/SM, product-major MMA ---------
template<bool DUALB>
__device__ __forceinline__ void load_stage(
    uint32_t sb, int m0, int n0, int k0,
    const __nv_bfloat16* Ah, const __nv_bfloat16* Al, int lda,
    const __nv_bfloat16* W1h, const __nv_bfloat16* W1l,
    const __nv_bfloat16* W2h, const __nv_bfloat16* W2l,
    int K, int tid)
{
    #pragma unroll
    for (int j = 0; j < 2; j++) {                       // A tiles
        const int idx = j * 256 + tid;
        const int r = idx >> 2, c = idx & 3;
        const uint32_t dst = sb + r * ROWB + c * 16;
        const size_t so = (size_t)(m0 + r) * lda + k0 + c * 8;
        cpasync16(dst,        Ah + so);
        cpasync16(dst + MATB, Al + so);
    }
    #pragma unroll
    for (int j = 0; j < 2; j++) {                       // B tiles
        const int idx = j * 256 + tid;
        const int r = idx >> 2, c = idx & 3;
        const uint32_t dst = sb + 2 * MATB + r * ROWB + c * 16;
        if (!DUALB) {
            const size_t so = (size_t)(n0 + r) * K + k0 + c * 8;
            cpasync16(dst,        W1h + so);
            cpasync16(dst + MATB, W1l + so);
        } else if (k0 < 256) {
            const size_t so = (size_t)(n0 + r) * 256 + k0 + c * 8;
            cpasync16(dst,        W1h + so);
            cpasync16(dst + MATB, W1l + so);
        } else {
            const size_t so = (size_t)(n0 + r) * 256 + (k0 - 256) + c * 8;
            cpasync16(dst,        W2h + so);
            cpasync16(dst + MATB, W2l + so);
        }
    }
}

template<bool BIAS, bool RELU, bool OUTF, bool OUTB, bool DUALB>
__global__ void __launch_bounds__(256, 2)
gemm_tc(const __nv_bfloat16* __restrict__ Ah, const __nv_bfloat16* __restrict__ Al, int lda,
        const __nv_bfloat16* __restrict__ W1h, const __nv_bfloat16* __restrict__ W1l,
        const __nv_bfloat16* __restrict__ W2h, const __nv_bfloat16* __restrict__ W2l,
        const float* __restrict__ bias,
        float* __restrict__ outF,
        __nv_bfloat16* __restrict__ outH, __nv_bfloat16* __restrict__ outL,
        int K, int Nout)
{
    extern __shared__ char dyn_smem[];
    const int tid  = threadIdx.x;
    const int wid  = tid >> 5;
    const int lane = tid & 31;
    const int m0 = blockIdx.y * 128;
    const int n0 = blockIdx.x * 128;
    const int wm0 = (wid & 1) * 64;
    const int wn0 = (wid >> 1) * 32;

    if (DUALB) {
        const size_t boff = (size_t)(m0 >> 12) * 65536;
        W2h += boff; W2l += boff;
    }

    const uint32_t base = smem_u32(dyn_smem);

    float acc[4][4][4];
    #pragma unroll
    for (int i = 0; i < 4; i++)
        #pragma unroll
        for (int j = 0; j < 4; j++)
            #pragma unroll
            for (int q = 0; q < 4; q++) acc[i][j][q] = 0.f;

    const uint32_t aOff = (uint32_t)(wm0 + (lane & 15)) * ROWB + ((lane >> 4) * 16);
    const uint32_t bOff = (uint32_t)(wn0 + ((lane >> 4) * 8) + (lane & 7)) * ROWB
                        + (((lane >> 3) & 1) * 16);

    const int S = K / 32;
    load_stage<DUALB>(base, m0, n0, 0, Ah, Al, lda, W1h, W1l, W2h, W2l, K, tid);
    asm volatile("cp.async.commit_group;" ::: "memory");

    uint32_t buf = 0;
    for (int s = 0; s < S; s++) {
        asm volatile("cp.async.wait_group 0;" ::: "memory");
        __syncthreads();
        // prefetch next stage into the other buffer (safe: that buffer was
        // last read before the barrier above)
        if (s + 1 < S) {
            load_stage<DUALB>(base + (buf ^ 1) * STAGEB, m0, n0, (s + 1) * 32,
                              Ah, Al, lda, W1h, W1l, W2h, W2l, K, tid);
            asm volatile("cp.async.commit_group;" ::: "memory");
        }
        const uint32_t sb = base + buf * STAGEB;
        #pragma unroll
        for (int ks = 0; ks < 2; ks++) {
            const uint32_t kb = ks * 32;
            uint32_t bH[2][4], bL[2][4], af[4][4];
            #pragma unroll
            for (int np = 0; np < 2; np++) {
                const uint32_t bd = sb + 2 * MATB + bOff + np * 16 * ROWB + kb;
                ldsm4(bH[np], bd);
                ldsm4(bL[np], bd + MATB);
            }
            #pragma unroll
            for (int mi = 0; mi < 4; mi++)
                ldsm4(af[mi], sb + aOff + mi * 16 * ROWB + kb);
            // pass 1: Ah * Bh  (acc reuse distance = 16 MMAs)
            #pragma unroll
            for (int mi = 0; mi < 4; mi++)
                #pragma unroll
                for (int ni = 0; ni < 4; ni++)
                    mma16816(acc[mi][ni], af[mi], &bH[ni >> 1][(ni & 1) * 2]);
            // pass 2: Ah * Bl
            #pragma unroll
            for (int mi = 0; mi < 4; mi++)
                #pragma unroll
                for (int ni = 0; ni < 4; ni++)
                    mma16816(acc[mi][ni], af[mi], &bL[ni >> 1][(ni & 1) * 2]);
            // reload A frags with Al (reuses the same registers)
            #pragma unroll
            for (int mi = 0; mi < 4; mi++)
                ldsm4(af[mi], sb + MATB + aOff + mi * 16 * ROWB + kb);
            // pass 3: Al * Bh
            #pragma unroll
            for (int mi = 0; mi < 4; mi++)
                #pragma unroll
                for (int ni = 0; ni < 4; ni++)
                    mma16816(acc[mi][ni], af[mi], &bH[ni >> 1][(ni & 1) * 2]);
        }
        buf ^= 1;
    }

    // epilogue
    #pragma unroll
    for (int ni = 0; ni < 4; ni++) {
        const int cidx = n0 + wn0 + ni * 8 + (lane & 3) * 2;
        float b0 = 0.f, b1 = 0.f;
        if (BIAS) { b0 = bias[cidx]; b1 = bias[cidx + 1]; }
        #pragma unroll
        for (int mi = 0; mi < 4; mi++) {
            const int r0 = m0 + wm0 + mi * 16 + (lane >> 2);
            #pragma unroll
            for (int half = 0; half < 2; half++) {
                const int r = r0 + half * 8;
                float v0 = acc[mi][ni][half * 2 + 0];
                float v1 = acc[mi][ni][half * 2 + 1];
                if (BIAS) { v0 += b0; v1 += b1; }
                if (RELU) { v0 = fmaxf(v0, 0.f); v1 = fmaxf(v1, 0.f); }
                if (OUTF) {
                    float2 f2 = make_float2(v0, v1);
                    *reinterpret_cast<float2*>(outF + (size_t)r * Nout + cidx) = f2;
                }
                if (OUTB) {
                    __nv_bfloat16 h0, l0, h1, l1;
                    split2(v0, h0, l0); split2(v1, h1, l1);
                    __nv_bfloat162 hh; hh.x = h0; hh.y = h1;
                    __nv_bfloat162 ll; ll.x = l0; ll.y = l1;
                    *reinterpret_cast<__nv_bfloat162*>(outH + (size_t)r * Nout + cidx) = hh;
                    *reinterpret_cast<__nv_bfloat162*>(outL + (size_t)r * Nout + cidx) = ll;
                }
            }
        }
    }
}

// ------------- ctx partial: per (chunk,h,b,path) K^T V over 512 rows --------
__global__ void __launch_bounds__(64)
ctx_partial_k(const float* __restrict__ KV1, const float* __restrict__ KV2,
              float* __restrict__ part)
{
    __shared__ float Ks[64][32];
    __shared__ float Vs[64][32];
    const int chunk = blockIdx.x, h = blockIdx.y, z = blockIdx.z;
    const int b = z & 15;
    const float* KV = (z < 16) ? KV1 : KV2;
    const int t = threadIdx.x, lane = t & 31, w = t >> 5;
    const float* base = KV + (size_t)b * HWn * 512;
    const int d0 = (t >> 3) * 4, e0 = (t & 7) * 4;
    float acc[4][4] = {};
    for (int nb = 0; nb < 512; nb += 64) {
        const int row0 = chunk * 512 + nb;
        for (int r = w; r < 64; r += 2) {
            const float* rp = base + (size_t)(row0 + r) * 512 + h * 32;
            Ks[r][lane] = rp[lane];
            Vs[r][lane] = rp[256 + lane];
        }
        __syncthreads();
        #pragma unroll 8
        for (int n = 0; n < 64; n++) {
            float4 k4 = *reinterpret_cast<float4*>(&Ks[n][d0]);
            float4 v4 = *reinterpret_cast<float4*>(&Vs[n][e0]);
            const float kk[4] = {k4.x, k4.y, k4.z, k4.w};
            const float vv[4] = {v4.x, v4.y, v4.z, v4.w};
            #pragma unroll
            for (int i = 0; i < 4; i++)
                #pragma unroll
                for (int j = 0; j < 4; j++)
                    acc[i][j] = fmaf(kk[i], vv[j], acc[i][j]);
        }
        __syncthreads();
    }
    float* p = part + ((size_t)(z * NHn + h) * 8 + chunk) * 1024;
    #pragma unroll
    for (int i = 0; i < 4; i++)
        #pragma unroll
        for (int j = 0; j < 4; j++)
            p[(d0 + i) * 32 + e0 + j] = acc[i][j];
}

// ------------- ctx finalize: sum partials, scale, softmax over d -----------
__global__ void ctx_final_k(const float* __restrict__ part, float* __restrict__ ctx1,
                            float* __restrict__ ctx2)
{
    __shared__ float S[32][33];
    const int bhg = blockIdx.x;        // [0,256): path*128 + bh
    float* ctx = (bhg < 128) ? ctx1 : ctx2;
    const int bh = bhg & 127;
    const int t  = threadIdx.x;
    const float* p = part + (size_t)bhg * 8 * 1024;
    for (int idx = t; idx < 1024; idx += 256) {
        float s = 0.f;
        #pragma unroll
        for (int c = 0; c < 8; c++) s += p[c * 1024 + idx];
        S[idx >> 5][idx & 31] = s * SCALE;
    }
    __syncthreads();
    if (t < 32) {
        float mx = -1e30f;
        #pragma unroll
        for (int d = 0; d < 32; d++) mx = fmaxf(mx, S[d][t]);
        float e[32], sum = 0.f;
        #pragma unroll
        for (int d = 0; d < 32; d++) { e[d] = expf(S[d][t] - mx); sum += e[d]; }
        const float inv = 1.f / sum;
        float* o = ctx + (size_t)bh * 1024;
        #pragma unroll
        for (int d = 0; d < 32; d++) o[d * 32 + t] = e[d] * inv;
    }
}

// ------------- build per-batch ep "M" weights: M[o, j] (split bf16) ---------
__global__ void __launch_bounds__(256)
ctxw_k(const float* __restrict__ ctx1, const float* __restrict__ ctx2,
       const float* __restrict__ ep1_w, const float* __restrict__ ep2_w,
       __nv_bfloat16* __restrict__ mwh, __nv_bfloat16* __restrict__ mwl)
{
    __shared__ float cs[8192];
    const int z = blockIdx.x;                 // path*16 + b
    const int path = z >> 4;
    const int b = z & 15;
    const float* ctx = path ? ctx1 : ctx2;
    const float* epw = path ? ep2_w : ep1_w;
    const int j = threadIdx.x;                // u-column 0..255
    for (int i = j; i < 8192; i += 256)
        cs[i] = ctx[(size_t)b * 8192 + i];
    __syncthreads();
    const int h = j >> 5, d = j & 31;
    float c[32];
    #pragma unroll
    for (int e = 0; e < 32; e++) c[e] = cs[h * 1024 + d * 32 + e];
    __nv_bfloat16* oh = mwh + (size_t)z * 65536;
    __nv_bfloat16* ol = mwl + (size_t)z * 65536;
    for (int o = 0; o < 256; o++) {
        const float* wr = epw + (size_t)o * 512 + 256 + h * 32;
        float a = 0.f;
        #pragma unroll
        for (int e = 0; e < 32; e++) a = fmaf(c[e], __ldg(wr + e), a);
        __nv_bfloat16 hh, ll; split2(a, hh, ll);
        oh[o * 256 + j] = hh; ol[o * 256 + j] = ll;
    }
}

// ------------- LayerNorm: MRG[:, mco..] = LN((Th+Tl) + EP)*g + b -------------
__global__ void __launch_bounds__(256)
ln_k(const __nv_bfloat16* __restrict__ T1h, const __nv_bfloat16* __restrict__ T1l,
     const __nv_bfloat16* __restrict__ T2h, const __nv_bfloat16* __restrict__ T2l,
     const float* __restrict__ EP1, const float* __restrict__ EP2,
     const float* __restrict__ g1, const float* __restrict__ b1,
     const float* __restrict__ g2, const float* __restrict__ b2,
     __nv_bfloat16* __restrict__ MH, __nv_bfloat16* __restrict__ ML)
{
    const int path = blockIdx.y;
    const __nv_bfloat16* Th = path ? T2h : T1h;
    const __nv_bfloat16* Tl = path ? T2l : T1l;
    const float* EP = path ? EP2 : EP1;
    const float* g  = path ? g2 : g1;
    const float* be = path ? b2 : b1;
    const int mco = path * 256;
    const int w    = blockIdx.x * 8 + (threadIdx.x >> 5);
    const int lane = threadIdx.x & 31;
    const __nv_bfloat16* th = Th + (size_t)w * 256;
    const __nv_bfloat16* tl = Tl + (size_t)w * 256;
    const float* er = EP + (size_t)w * 256;
    float v[8], sum = 0.f, sq = 0.f;
    #pragma unroll
    for (int i = 0; i < 8; i++) {
        const int c = lane + i * 32;
        const float x = __bfloat162float(th[c]) + __bfloat162float(tl[c]) + er[c];
        v[i] = x; sum += x; sq += x * x;
    }
    #pragma unroll
    for (int o = 16; o; o >>= 1) {
        sum += __shfl_xor_sync(0xffffffffu, sum, o);
        sq  += __shfl_xor_sync(0xffffffffu, sq,  o);
    }
    const float mean = sum * (1.f / 256.f);
    const float var  = sq * (1.f / 256.f) - mean * mean;
    const float rs   = rsqrtf(var + EPSF);
    const size_t ob = (size_t)w * 512 + mco;
    #pragma unroll
    for (int i = 0; i < 8; i++) {
        const int c = lane + i * 32;
        const float y = (v[i] - mean) * rs * g[c] + be[c];
        __nv_bfloat16 hh, ll; split2(y, hh, ll);
        MH[ob + c] = hh; ML[ob + c] = ll;
    }
}

// ------------- 3x3 depthwise conv on [M,ld] layout + bias + relu, split out --
__global__ void __launch_bounds__(256)
dw_k(const float* __restrict__ X, int ldx, const float* __restrict__ w9,
     const float* __restrict__ db, __nv_bfloat16* __restrict__ Yh,
     __nv_bfloat16* __restrict__ Yl)
{
    __shared__ float s[18 * 18 * 32];
    const int cc   = blockIdx.x;
    const int tile = blockIdx.y;
    const int b    = blockIdx.z;
    const int ty0 = (tile >> 2) * 16, tx0 = (tile & 3) * 16;
    const int c0 = cc * 32;
    const int tid = threadIdx.x;
    for (int i = tid; i < 18 * 18 * 32; i += 256) {
        const int c = i & 31;
        const int sp = i >> 5;
        const int x = sp % 18 - 1 + tx0;
        const int y = sp / 18 - 1 + ty0;
        float v = 0.f;
        if (x >= 0 && x < 64 && y >= 0 && y < 64)
            v = X[(size_t)(b * 4096 + y * 64 + x) * ldx + c0 + c];
        s[i] = v;
    }
    const int c = tid & 31;
    float kr[9];
    #pragma unroll
    for (int j = 0; j < 9; j++) kr[j] = w9[(c0 + c) * 9 + j];
    const float bb = db[c0 + c];
    __syncthreads();
    for (int o = tid; o < 8192; o += 256) {
        const int sp = o >> 5;
        const int x = sp & 15, y = sp >> 4;
        float a = 0.f;
        #pragma unroll
        for (int dy = 0; dy < 3; dy++)
            #pragma unroll
            for (int dx = 0; dx < 3; dx++)
                a = fmaf(s[((y + dy) * 18 + (x + dx)) * 32 + c], kr[dy * 3 + dx], a);
        a = fmaxf(a + bb, 0.f);
        const size_t idx = (size_t)(b * 4096 + (ty0 + y) * 64 + tx0 + x) * 256 + c0 + c;
        __nv_bfloat16 hh, ll; split2(a, hh, ll);
        Yh[idx] = hh; Yl[idx] = ll;
    }
}

// ------------- BN stats on [M,256] fp32: two-stage ---------------------------
__global__ void __launch_bounds__(256)
bn_part_k(const float* __restrict__ X, float* __restrict__ part)
{
    const int seg = blockIdx.x;
    const int c   = threadIdx.x;
    const float* p = X + (size_t)seg * 256 * 256;
    float s = 0.f, q = 0.f;
    #pragma unroll 8
    for (int r = 0; r < 256; r++) {
        const float v = p[(size_t)r * 256 + c];
        s += v; q = fmaf(v, v, q);
    }
    part[seg * 512 + c] = s;
    part[seg * 512 + 256 + c] = q;
}

__global__ void bn_fin_k(const float* __restrict__ part, const float* __restrict__ g,
                         const float* __restrict__ be, float* __restrict__ sc,
                         float* __restrict__ sh)
{
    const int c = threadIdx.x;
    float s = 0.f, q = 0.f;
    for (int seg = 0; seg < 256; seg++) {
        s += part[seg * 512 + c];
        q += part[seg * 512 + 256 + c];
    }
    const float inv = 1.f / 65536.f;
    const float m   = s * inv;
    const float var = q * inv - m * m;
    const float scv = g[c] * rsqrtf(var + EPSF);
    sc[c] = scv;
    sh[c] = be[c] - m * scv;
}

// ------------- F = RES(RC col0-255) + E*sc + sh ------------------------------
__global__ void addbn_k(const float* __restrict__ RC, const float* __restrict__ E,
                        const float* __restrict__ sc, const float* __restrict__ sh,
                        float* __restrict__ F)
{
    const int i4 = blockIdx.x * 256 + threadIdx.x;
    const int r  = i4 >> 6;
    const int c0 = (i4 & 63) * 4;
    const float4 s = *reinterpret_cast<const float4*>(sc + c0);
    const float4 h = *reinterpret_cast<const float4*>(sh + c0);
    const float4 rr = *reinterpret_cast<const float4*>(RC + (size_t)r * 512 + c0);
    const float4 e = reinterpret_cast<const float4*>(E)[i4];
    float4 f;
    f.x = fmaf(e.x, s.x, rr.x + h.x);
    f.y = fmaf(e.y, s.y, rr.y + h.y);
    f.z = fmaf(e.z, s.z, rr.z + h.z);
    f.w = fmaf(e.w, s.w, rr.w + h.w);
    reinterpret_cast<float4*>(F)[i4] = f;
}

// ------------- final: out NCHW = bn2(F) via transpose ------------------------
__global__ void bn_final_k(const float* __restrict__ F, const float* __restrict__ sc,
                           const float* __restrict__ sh, float* __restrict__ O)
{
    __shared__ float s[32][33];
    const int b  = blockIdx.z;
    const int c0 = blockIdx.y * 32;
    const int n0 = blockIdx.x * 32;
    const int tx = threadIdx.x, ty = threadIdx.y;
    #pragma unroll
    for (int i = 0; i < 32; i += 8)
        s[ty + i][tx] = F[((size_t)(b * 4096 + n0 + ty + i)) * 256 + c0 + tx];
    __syncthreads();
    #pragma unroll
    for (int i = 0; i < 32; i += 8) {
        const int c = c0 + ty + i;
        O[((size_t)(b * 256 + c)) * 4096 + n0 + tx] = s[tx][ty + i] * sc[c] + sh[c];
    }
}

// ===========================================================================
extern "C" void kernel_launch(void* const* d_in, const int* in_sizes, int n_in,
                              void* d_out, int out_size)
{
    (void)in_sizes; (void)n_in; (void)out_size;
    const float* x1    = (const float*)d_in[0];
    const float* x2    = (const float*)d_in[1];
    const float* cp1_w = (const float*)d_in[2];
    const float* cp1_b = (const float*)d_in[3];
    const float* cp2_w = (const float*)d_in[4];
    const float* cp2_b = (const float*)d_in[5];
    const float* kv1_w = (const float*)d_in[6];
    const float* kv2_w = (const float*)d_in[7];
    const float* ep1_w = (const float*)d_in[8];
    const float* ep1_b = (const float*)d_in[9];
    const float* ep2_w = (const float*)d_in[10];
    const float* ep2_b = (const float*)d_in[11];
    const float* ln1_g = (const float*)d_in[12];
    const float* ln1_b = (const float*)d_in[13];
    const float* ln2_g = (const float*)d_in[14];
    const float* ln2_b = (const float*)d_in[15];
    const float* res_w = (const float*)d_in[16];
    const float* ce1_w = (const float*)d_in[17];
    const float* ce1_b = (const float*)d_in[18];
    const float* dw_w  = (const float*)d_in[19];
    const float* dw_b  = (const float*)d_in[20];
    const float* ce3_w = (const float*)d_in[21];
    const float* ce3_b = (const float*)d_in[22];
    const float* bn1_g = (const float*)d_in[23];
    const float* bn1_b = (const float*)d_in[24];
    const float* bn2_g = (const float*)d_in[25];
    const float* bn2_b = (const float*)d_in[26];

    float *KV1, *KV2, *EP1, *EP2, *RC, *E, *F;
    float *PART, *CTX1, *CTX2, *CB, *BNP, *SC1, *SH1, *SC2, *SH2;
    __nv_bfloat16 *T1h, *T1l, *T2h, *T2l, *P1h, *P1l, *P2h, *P2l;
    __nv_bfloat16 *MRGh, *MRGl, *DWh, *DWl, *WH, *WL, *EPYh, *EPYl, *MWh, *MWl;
    cudaGetSymbolAddress((void**)&T1h, g_T1h);
    cudaGetSymbolAddress((void**)&T1l, g_T1l);
    cudaGetSymbolAddress((void**)&T2h, g_T2h);
    cudaGetSymbolAddress((void**)&T2l, g_T2l);
    cudaGetSymbolAddress((void**)&P1h, g_P1h);
    cudaGetSymbolAddress((void**)&P1l, g_P1l);
    cudaGetSymbolAddress((void**)&P2h, g_P2h);
    cudaGetSymbolAddress((void**)&P2l, g_P2l);
    cudaGetSymbolAddress((void**)&KV1, g_KV1);
    cudaGetSymbolAddress((void**)&KV2, g_KV2);
    cudaGetSymbolAddress((void**)&EP1, g_EP1);
    cudaGetSymbolAddress((void**)&EP2, g_EP2);
    cudaGetSymbolAddress((void**)&MRGh, g_MRGh);
    cudaGetSymbolAddress((void**)&MRGl, g_MRGl);
    cudaGetSymbolAddress((void**)&RC,  g_RC);
    cudaGetSymbolAddress((void**)&DWh, g_DWh);
    cudaGetSymbolAddress((void**)&DWl, g_DWl);
    cudaGetSymbolAddress((void**)&E,   g_E);
    cudaGetSymbolAddress((void**)&F,   g_F);
    cudaGetSymbolAddress((void**)&WH,  g_WH);
    cudaGetSymbolAddress((void**)&WL,  g_WL);
    cudaGetSymbolAddress((void**)&EPYh, g_EPYh);
    cudaGetSymbolAddress((void**)&EPYl, g_EPYl);
    cudaGetSymbolAddress((void**)&MWh, g_MWh);
    cudaGetSymbolAddress((void**)&MWl, g_MWl);
    cudaGetSymbolAddress((void**)&PART, g_PART);
    cudaGetSymbolAddress((void**)&CTX1, g_CTX1);
    cudaGetSymbolAddress((void**)&CTX2, g_CTX2);
    cudaGetSymbolAddress((void**)&CB,  g_CB);
    cudaGetSymbolAddress((void**)&BNP, g_BNP);
    cudaGetSymbolAddress((void**)&SC1, g_SC1);
    cudaGetSymbolAddress((void**)&SH1, g_SH1);
    cudaGetSymbolAddress((void**)&SC2, g_SC2);
    cudaGetSymbolAddress((void**)&SH2, g_SH2);

    cudaFuncSetAttribute(gemm_tc<true,  true,  false, true , false>,
                         cudaFuncAttributeMaxDynamicSharedMemorySize, DYN_SMEM);
    cudaFuncSetAttribute(gemm_tc<false, false, true,  false, false>,
                         cudaFuncAttributeMaxDynamicSharedMemorySize, DYN_SMEM);
    cudaFuncSetAttribute(gemm_tc<true,  false, true,  false, true >,
                         cudaFuncAttributeMaxDynamicSharedMemorySize, DYN_SMEM);
    cudaFuncSetAttribute(gemm_tc<true,  false, true,  false, false>,
                         cudaFuncAttributeMaxDynamicSharedMemorySize, DYN_SMEM);

    // weight slots in WH/WL (851968 total)
    const size_t oCP1 = 0, oCP2 = 131072, oKV1 = 262144, oKV2 = 393216;
    const size_t oRC = 524288, oCE3 = 786432;
    WsplitArgs wa;
    wa.src[0] = cp1_w; wa.src[1] = cp2_w; wa.src[2] = kv1_w; wa.src[3] = kv2_w;
    wa.src[4] = res_w; wa.src[5] = ce1_w; wa.src[6] = ce3_w;

    wsplit_all_k<<<3328, 256>>>(wa, WH, WL);
    wsplit_ep_k<<<dim3(256, 2), 256>>>(ep1_w, ep2_w, EPYh, EPYl);
    transpose_split_k<<<dim3(128, 8, 32), dim3(32, 8)>>>(x1, x2, T1h, T1l, T2h, T2l);

    const dim3 g512(4, 512);
    const dim3 g256(2, 512);

    // CrossPath P = relu(T @ cp_w^T + b) -> split bf16
    gemm_tc<true, true, false, true, false><<<g512, 256, DYN_SMEM>>>(
        T1h, T1l, 256, WH + oCP1, WL + oCP1, nullptr, nullptr, cp1_b,
        nullptr, P1h, P1l, 256, 512);
    gemm_tc<true, true, false, true, false><<<g512, 256, DYN_SMEM>>>(
        T2h, T2l, 256, WH + oCP2, WL + oCP2, nullptr, nullptr, cp2_b,
        nullptr, P2h, P2l, 256, 512);

    // KV = u @ kv_w^T -> fp32
    gemm_tc<false, false, true, false, false><<<g512, 256, DYN_SMEM>>>(
        P1h + 256, P1l + 256, 512, WH + oKV1, WL + oKV1, nullptr, nullptr, nullptr,
        KV1, nullptr, nullptr, 256, 512);
    gemm_tc<false, false, true, false, false><<<g512, 256, DYN_SMEM>>>(
        P2h + 256, P2l + 256, 512, WH + oKV2, WL + oKV2, nullptr, nullptr, nullptr,
        KV2, nullptr, nullptr, 256, 512);

    // ctx = softmax_d(scale * K^T V), both paths
    ctx_partial_k<<<dim3(8, 8, 32), 64>>>(KV1, KV2, PART);
    ctx_final_k<<<256, 256>>>(PART, CTX1, CTX2);

    // per-batch M weights for the fused ep GEMM (cross-wired)
    ctxw_k<<<32, 256>>>(CTX1, CTX2, ep1_w, ep2_w, MWh, MWl);

    // EP = y @ W1 + u @ M_b + bias (dual-source B)
    gemm_tc<true, false, true, false, true><<<g256, 256, DYN_SMEM>>>(
        P1h, P1l, 512, EPYh, EPYl, MWh, MWl, ep1_b,
        EP1, nullptr, nullptr, 512, 256);
    gemm_tc<true, false, true, false, true><<<g256, 256, DYN_SMEM>>>(
        P2h, P2l, 512, EPYh + 65536, EPYl + 65536, MWh + 16 * 65536, MWl + 16 * 65536,
        ep2_b, EP2, nullptr, nullptr, 512, 256);

    // LN both paths -> MRG split
    ln_k<<<dim3(8192, 2), 256>>>(T1h, T1l, T2h, T2l, EP1, EP2,
                                 ln1_g, ln1_b, ln2_g, ln2_b, MRGh, MRGl);

    // bias concat (0 | ce1_b)
    biascat_k<<<2, 256>>>(ce1_b, CB);

    // res|ce1 concatenated GEMM -> RC [M, 512]
    gemm_tc<true, false, true, false, false><<<g512, 256, DYN_SMEM>>>(
        MRGh, MRGl, 512, WH + oRC, WL + oRC, nullptr, nullptr, CB,
        RC, nullptr, nullptr, 512, 512);

    // 3x3 depthwise (+bias+relu) on CE1 half of RC -> DW split
    dw_k<<<dim3(8, 16, 16), 256>>>(RC + 256, 512, dw_w, dw_b, DWh, DWl);

    // ce3 GEMM -> E
    gemm_tc<true, false, true, false, false><<<g256, 256, DYN_SMEM>>>(
        DWh, DWl, 256, WH + oCE3, WL + oCE3, nullptr, nullptr, ce3_b,
        E, nullptr, nullptr, 256, 256);

    // bn1 -> residual add -> bn2 -> final NCHW
    bn_part_k<<<256, 256>>>(E, BNP);
    bn_fin_k<<<1, 256>>>(BNP, bn1_g, bn1_b, SC1, SH1);
    addbn_k<<<16384, 256>>>(RC, E, SC1, SH1, F);
    bn_part_k<<<256, 256>>>(F, BNP);
    bn_fin_k<<<1, 256>>>(BNP, bn2_g, bn2_b, SC2, SH2);
    bn_final_k<<<dim3(128, 8, 16), dim3(32, 8)>>>(F, SC2, SH2, (float*)d_out);
}

// round 7
// speedup vs baseline: 3.2297x; 1.2885x over previous
#include <cuda_runtime.h>
#include <cuda_fp16.h>
#include <math.h>
#include <stdint.h>

namespace {
constexpr int Bn  = 16;
constexpr int Cn  = 256;
constexpr int HWn = 4096;
constexpr int NHn = 8;
constexpr int Mn  = Bn * HWn;          // 65536 rows
constexpr float EPSF  = 1e-5f;
constexpr float SCALE = 0.17677669529663687f;  // 32^-0.5
constexpr float WSC   = 64.f;          // weight pre-scale (keeps Wl normal-range)
constexpr float IWSC  = 0.015625f;     // 1/64 epilogue unscale

constexpr int ROWB   = 80;             // bytes per 32-fp16 row in smem
constexpr int MATB   = 128 * ROWB;     // 10240 bytes per matrix tile
constexpr int STAGEB = 3 * MATB;       // A | BH | BL = 30720
constexpr int NSTAGE = 3;
constexpr int DYN_SMEM = NSTAGE * STAGEB;   // 92160 -> 2 CTAs/SM (184KB)
}

// ---------------- workspace (device globals; no allocation allowed) --------
__device__ __half g_T1 [(size_t)Mn * Cn];
__device__ __half g_T2 [(size_t)Mn * Cn];
__device__ __half g_P1 [(size_t)Mn * 2 * Cn];
__device__ __half g_P2 [(size_t)Mn * 2 * Cn];
__device__ float g_KV1[(size_t)Mn * 2 * Cn];
__device__ float g_KV2[(size_t)Mn * 2 * Cn];
__device__ float g_EP1[(size_t)Mn * Cn];
__device__ float g_EP2[(size_t)Mn * Cn];
__device__ __half g_MRG[(size_t)Mn * 2 * Cn];
__device__ float g_RC [(size_t)Mn * 2 * Cn];      // cols 0-255 RES, 256-511 CE1
__device__ __half g_DW [(size_t)Mn * Cn];
__device__ float g_E  [(size_t)Mn * Cn];
__device__ float g_F  [(size_t)Mn * Cn];
__device__ __half g_WH[900000];
__device__ __half g_WL[900000];
__device__ __half g_EPYh[2 * 65536];
__device__ __half g_EPYl[2 * 65536];
__device__ __half g_MWh[2 * 16 * 65536];
__device__ __half g_MWl[2 * 16 * 65536];
__device__ float g_PART[(size_t)2 * Bn * NHn * 8 * 32 * 32];
__device__ float g_CTX1[(size_t)Bn * NHn * 32 * 32];
__device__ float g_CTX2[(size_t)Bn * NHn * 32 * 32];
__device__ float g_CB[512];
__device__ float g_BNP[256 * 512];
__device__ float g_SC1[Cn];
__device__ float g_SH1[Cn];
__device__ float g_SC2[Cn];
__device__ float g_SH2[Cn];

// ---------------- PTX helpers ----------------------------------------------
__device__ __forceinline__ uint32_t smem_u32(const void* p) {
    uint32_t a;
    asm("{ .reg .u64 t; cvta.to.shared.u64 t, %1; cvt.u32.u64 %0, t; }"
        : "=r"(a) : "l"(p));
    return a;
}

__device__ __forceinline__ void cpasync16(uint32_t dst, const void* src) {
    asm volatile("cp.async.cg.shared.global [%0], [%1], 16;"
                 :: "r"(dst), "l"(src));
}

__device__ __forceinline__ void ldsm4(uint32_t* r, uint32_t addr) {
    asm volatile("ldmatrix.sync.aligned.m8n8.x4.shared.b16 {%0,%1,%2,%3}, [%4];"
                 : "=r"(r[0]), "=r"(r[1]), "=r"(r[2]), "=r"(r[3]) : "r"(addr));
}

__device__ __forceinline__ void mma16816(float* d, const uint32_t* a, const uint32_t* b) {
    asm volatile(
        "mma.sync.aligned.m16n8k16.row.col.f32.f16.f16.f32 "
        "{%0,%1,%2,%3}, {%4,%5,%6,%7}, {%8,%9}, {%0,%1,%2,%3};"
        : "+f"(d[0]), "+f"(d[1]), "+f"(d[2]), "+f"(d[3])
        : "r"(a[0]), "r"(a[1]), "r"(a[2]), "r"(a[3]), "r"(b[0]), "r"(b[1]));
}

// split scaled weight into fp16 hi/lo (value pre-multiplied by WSC)
__device__ __forceinline__ void wsplit2(float w, __half& h, __half& l) {
    const float ws = w * WSC;
    h = __float2half(ws);
    l = __float2half(ws - __half2float(h));
}

// ---------------- weight split: all contiguous weights in one launch --------
struct WsplitArgs {
    const float* src[7];   // cp1, cp2, kv1, kv2, res, ce1, ce3
};
__global__ void wsplit_all_k(WsplitArgs a, __half* __restrict__ h,
                             __half* __restrict__ l)
{
    const int i = blockIdx.x * 256 + threadIdx.x;
    if (i >= 851968) return;
    int seg, off;
    if (i < 786432) { seg = i >> 17; off = i & 131071; }
    else            { seg = 6;       off = i - 786432; }
    __half hh, ll; wsplit2(a.src[seg][off], hh, ll);
    h[i] = hh; l[i] = ll;
}

// ---------------- ep static (y-part) weight: strided split ------------------
__global__ void wsplit_ep_k(const float* __restrict__ ep1_w, const float* __restrict__ ep2_w,
                            __half* __restrict__ h, __half* __restrict__ l)
{
    const int o = blockIdx.x;            // 0..255
    const int path = blockIdx.y;
    const int k = threadIdx.x;           // 0..255
    const float* w = path ? ep2_w : ep1_w;
    __half hh, ll; wsplit2(w[o * 512 + k], hh, ll);
    const int idx = path * 65536 + o * 256 + k;
    h[idx] = hh; l[idx] = ll;
}

// ---------------- bias concat for res|ce1 GEMM -------------------------------
__global__ void biascat_k(const float* __restrict__ ce1_b, float* __restrict__ cb)
{
    const int t = threadIdx.x + blockIdx.x * 256;
    cb[t] = (t < 256) ? 0.f : ce1_b[t - 256];
}

// ---------------- transpose: x [B,C,HW] -> fp16 [B,HW,C] ---------------------
__global__ void transpose_split_k(const float* __restrict__ x1, const float* __restrict__ x2,
                                  __half* __restrict__ t1, __half* __restrict__ t2)
{
    __shared__ float s[32][33];
    const int z = blockIdx.z;
    const int path = z >> 4;
    const int b = z & 15;
    const float* x = path ? x2 : x1;
    __half* th = path ? t2 : t1;
    const int c0 = blockIdx.y * 32;
    const int n0 = blockIdx.x * 32;
    const float* xb = x + (size_t)b * Cn * HWn;
    const int tx = threadIdx.x, ty = threadIdx.y;  // 32 x 8
    #pragma unroll
    for (int i = 0; i < 32; i += 8)
        s[ty + i][tx] = xb[(size_t)(c0 + ty + i) * HWn + n0 + tx];
    __syncthreads();
    #pragma unroll
    for (int i = 0; i < 32; i += 8) {
        const size_t idx = ((size_t)b * HWn + n0 + ty + i) * Cn + c0 + tx;
        th[idx] = __float2half(s[tx][ty + i]);
    }
}

// ---------------- HMMA fp16 GEMM: A single, B split, 2-product ---------------
// out = (A @ (64*W)^T) / 64 [+bias][relu]
template<bool DUALB>
__device__ __forceinline__ void load_stage(
    uint32_t sb, int m0, int n0, int k0,
    const __half* A, int lda,
    const __half* W1h, const __half* W1l,
    const __half* W2h, const __half* W2l,
    int K, int tid)
{
    #pragma unroll
    for (int j = 0; j < 2; j++) {                       // A tile (single)
        const int idx = j * 256 + tid;
        const int r = idx >> 2, c = idx & 3;
        cpasync16(sb + r * ROWB + c * 16,
                  A + (size_t)(m0 + r) * lda + k0 + c * 8);
    }
    #pragma unroll
    for (int j = 0; j < 2; j++) {                       // B tiles (hi+lo)
        const int idx = j * 256 + tid;
        const int r = idx >> 2, c = idx & 3;
        const uint32_t dst = sb + MATB + r * ROWB + c * 16;
        if (!DUALB) {
            const size_t so = (size_t)(n0 + r) * K + k0 + c * 8;
            cpasync16(dst,        W1h + so);
            cpasync16(dst + MATB, W1l + so);
        } else if (k0 < 256) {
            const size_t so = (size_t)(n0 + r) * 256 + k0 + c * 8;
            cpasync16(dst,        W1h + so);
            cpasync16(dst + MATB, W1l + so);
        } else {
            const size_t so = (size_t)(n0 + r) * 256 + (k0 - 256) + c * 8;
            cpasync16(dst,        W2h + so);
            cpasync16(dst + MATB, W2l + so);
        }
    }
}

template<bool BIAS, bool RELU, bool OUTF, bool OUTB, bool DUALB>
__global__ void __launch_bounds__(256, 2)
gemm_tc(const __half* __restrict__ A, int lda,
        const __half* __restrict__ W1h, const __half* __restrict__ W1l,
        const __half* __restrict__ W2h, const __half* __restrict__ W2l,
        const float* __restrict__ bias,
        float* __restrict__ outF, __half* __restrict__ outH,
        int K, int Nout)
{
    extern __shared__ char dyn_smem[];
    const int tid  = threadIdx.x;
    const int wid  = tid >> 5;
    const int lane = tid & 31;
    const int m0 = blockIdx.y * 128;
    const int n0 = blockIdx.x * 128;
    const int wm0 = (wid & 1) * 64;
    const int wn0 = (wid >> 1) * 32;

    if (DUALB) {
        const size_t boff = (size_t)(m0 >> 12) * 65536;
        W2h += boff; W2l += boff;
    }

    const uint32_t base = smem_u32(dyn_smem);

    float acc[4][4][4];
    #pragma unroll
    for (int i = 0; i < 4; i++)
        #pragma unroll
        for (int j = 0; j < 4; j++)
            #pragma unroll
            for (int q = 0; q < 4; q++) acc[i][j][q] = 0.f;

    const uint32_t aOff = (uint32_t)(wm0 + (lane & 15)) * ROWB + ((lane >> 4) * 16);
    const uint32_t bOff = (uint32_t)(wn0 + ((lane >> 4) * 8) + (lane & 7)) * ROWB
                        + (((lane >> 3) & 1) * 16);

    const int S = K / 32;
    load_stage<DUALB>(base, m0, n0, 0, A, lda, W1h, W1l, W2h, W2l, K, tid);
    asm volatile("cp.async.commit_group;" ::: "memory");
    load_stage<DUALB>(base + STAGEB, m0, n0, 32, A, lda, W1h, W1l, W2h, W2l, K, tid);
    asm volatile("cp.async.commit_group;" ::: "memory");

    int buf = 0;
    for (int s = 0; s < S; s++) {
        if (s + 1 < S)
            asm volatile("cp.async.wait_group 1;" ::: "memory");
        else
            asm volatile("cp.async.wait_group 0;" ::: "memory");
        __syncthreads();
        if (s + 2 < S) {
            int nb = buf + 2; if (nb >= NSTAGE) nb -= NSTAGE;
            load_stage<DUALB>(base + nb * STAGEB, m0, n0, (s + 2) * 32,
                              A, lda, W1h, W1l, W2h, W2l, K, tid);
            asm volatile("cp.async.commit_group;" ::: "memory");
        }
        const uint32_t sb = base + buf * STAGEB;
        #pragma unroll
        for (int ks = 0; ks < 2; ks++) {
            const uint32_t kb = ks * 32;
            uint32_t bH[2][4], bL[2][4], af[4][4];
            #pragma unroll
            for (int np = 0; np < 2; np++) {
                const uint32_t bd = sb + MATB + bOff + np * 16 * ROWB + kb;
                ldsm4(bH[np], bd);
                ldsm4(bL[np], bd + MATB);
            }
            #pragma unroll
            for (int mi = 0; mi < 4; mi++)
                ldsm4(af[mi], sb + aOff + mi * 16 * ROWB + kb);
            // pass 1: A * Bh
            #pragma unroll
            for (int mi = 0; mi < 4; mi++)
                #pragma unroll
                for (int ni = 0; ni < 4; ni++)
                    mma16816(acc[mi][ni], af[mi], &bH[ni >> 1][(ni & 1) * 2]);
            // pass 2: A * Bl
            #pragma unroll
            for (int mi = 0; mi < 4; mi++)
                #pragma unroll
                for (int ni = 0; ni < 4; ni++)
                    mma16816(acc[mi][ni], af[mi], &bL[ni >> 1][(ni & 1) * 2]);
        }
        buf++; if (buf >= NSTAGE) buf = 0;
    }

    // epilogue: unscale by 1/64, bias, relu
    #pragma unroll
    for (int ni = 0; ni < 4; ni++) {
        const int cidx = n0 + wn0 + ni * 8 + (lane & 3) * 2;
        float b0 = 0.f, b1 = 0.f;
        if (BIAS) { b0 = bias[cidx]; b1 = bias[cidx + 1]; }
        #pragma unroll
        for (int mi = 0; mi < 4; mi++) {
            const int r0 = m0 + wm0 + mi * 16 + (lane >> 2);
            #pragma unroll
            for (int half = 0; half < 2; half++) {
                const int r = r0 + half * 8;
                float v0 = acc[mi][ni][half * 2 + 0] * IWSC;
                float v1 = acc[mi][ni][half * 2 + 1] * IWSC;
                if (BIAS) { v0 += b0; v1 += b1; }
                if (RELU) { v0 = fmaxf(v0, 0.f); v1 = fmaxf(v1, 0.f); }
                if (OUTF) {
                    float2 f2 = make_float2(v0, v1);
                    *reinterpret_cast<float2*>(outF + (size_t)r * Nout + cidx) = f2;
                }
                if (OUTB) {
                    __half2 hh = __halves2half2(__float2half(v0), __float2half(v1));
                    *reinterpret_cast<__half2*>(outH + (size_t)r * Nout + cidx) = hh;
                }
            }
        }
    }
}

// ------------- ctx partial: per (chunk,h,b,path) K^T V over 512 rows --------
__global__ void __launch_bounds__(64)
ctx_partial_k(const float* __restrict__ KV1, const float* __restrict__ KV2,
              float* __restrict__ part)
{
    __shared__ float Ks[64][32];
    __shared__ float Vs[64][32];
    const int chunk = blockIdx.x, h = blockIdx.y, z = blockIdx.z;
    const int b = z & 15;
    const float* KV = (z < 16) ? KV1 : KV2;
    const int t = threadIdx.x, lane = t & 31, w = t >> 5;
    const float* base = KV + (size_t)b * HWn * 512;
    const int d0 = (t >> 3) * 4, e0 = (t & 7) * 4;
    float acc[4][4] = {};
    for (int nb = 0; nb < 512; nb += 64) {
        const int row0 = chunk * 512 + nb;
        for (int r = w; r < 64; r += 2) {
            const float* rp = base + (size_t)(row0 + r) * 512 + h * 32;
            Ks[r][lane] = rp[lane];
            Vs[r][lane] = rp[256 + lane];
        }
        __syncthreads();
        #pragma unroll 8
        for (int n = 0; n < 64; n++) {
            float4 k4 = *reinterpret_cast<float4*>(&Ks[n][d0]);
            float4 v4 = *reinterpret_cast<float4*>(&Vs[n][e0]);
            const float kk[4] = {k4.x, k4.y, k4.z, k4.w};
            const float vv[4] = {v4.x, v4.y, v4.z, v4.w};
            #pragma unroll
            for (int i = 0; i < 4; i++)
                #pragma unroll
                for (int j = 0; j < 4; j++)
                    acc[i][j] = fmaf(kk[i], vv[j], acc[i][j]);
        }
        __syncthreads();
    }
    float* p = part + ((size_t)(z * NHn + h) * 8 + chunk) * 1024;
    #pragma unroll
    for (int i = 0; i < 4; i++)
        #pragma unroll
        for (int j = 0; j < 4; j++)
            p[(d0 + i) * 32 + e0 + j] = acc[i][j];
}

// ------------- ctx finalize: sum partials, scale, softmax over d -----------
__global__ void ctx_final_k(const float* __restrict__ part, float* __restrict__ ctx1,
                            float* __restrict__ ctx2)
{
    __shared__ float S[32][33];
    const int bhg = blockIdx.x;        // [0,256): path*128 + bh
    float* ctx = (bhg < 128) ? ctx1 : ctx2;
    const int bh = bhg & 127;
    const int t  = threadIdx.x;
    const float* p = part + (size_t)bhg * 8 * 1024;
    for (int idx = t; idx < 1024; idx += 256) {
        float s = 0.f;
        #pragma unroll
        for (int c = 0; c < 8; c++) s += p[c * 1024 + idx];
        S[idx >> 5][idx & 31] = s * SCALE;
    }
    __syncthreads();
    if (t < 32) {
        float mx = -1e30f;
        #pragma unroll
        for (int d = 0; d < 32; d++) mx = fmaxf(mx, S[d][t]);
        float e[32], sum = 0.f;
        #pragma unroll
        for (int d = 0; d < 32; d++) { e[d] = expf(S[d][t] - mx); sum += e[d]; }
        const float inv = 1.f / sum;
        float* o = ctx + (size_t)bh * 1024;
        #pragma unroll
        for (int d = 0; d < 32; d++) o[d * 32 + t] = e[d] * inv;
    }
}

// ------------- build per-batch ep "M" weights: M[o, j] (scaled split fp16) --
__global__ void __launch_bounds__(256)
ctxw_k(const float* __restrict__ ctx1, const float* __restrict__ ctx2,
       const float* __restrict__ ep1_w, const float* __restrict__ ep2_w,
       __half* __restrict__ mwh, __half* __restrict__ mwl)
{
    __shared__ float cs[8192];
    const int z = blockIdx.x;                 // path*16 + b
    const int path = z >> 4;
    const int b = z & 15;
    const float* ctx = path ? ctx1 : ctx2;
    const float* epw = path ? ep2_w : ep1_w;
    const int j = threadIdx.x;                // u-column 0..255
    for (int i = j; i < 8192; i += 256)
        cs[i] = ctx[(size_t)b * 8192 + i];
    __syncthreads();
    const int h = j >> 5, d = j & 31;
    float c[32];
    #pragma unroll
    for (int e = 0; e < 32; e++) c[e] = cs[h * 1024 + d * 32 + e];
    __half* oh = mwh + (size_t)z * 65536;
    __half* ol = mwl + (size_t)z * 65536;
    for (int o = 0; o < 256; o++) {
        const float* wr = epw + (size_t)o * 512 + 256 + h * 32;
        float a = 0.f;
        #pragma unroll
        for (int e = 0; e < 32; e++) a = fmaf(c[e], __ldg(wr + e), a);
        __half hh, ll; wsplit2(a, hh, ll);
        oh[o * 256 + j] = hh; ol[o * 256 + j] = ll;
    }
}

// ------------- LayerNorm: MRG[:, mco..] = LN(T + EP)*g + b (fp16 out) --------
__global__ void __launch_bounds__(256)
ln_k(const __half* __restrict__ T1, const __half* __restrict__ T2,
     const float* __restrict__ EP1, const float* __restrict__ EP2,
     const float* __restrict__ g1, const float* __restrict__ b1,
     const float* __restrict__ g2, const float* __restrict__ b2,
     __half* __restrict__ MH)
{
    const int path = blockIdx.y;
    const __half* Th = path ? T2 : T1;
    const float* EP = path ? EP2 : EP1;
    const float* g  = path ? g2 : g1;
    const float* be = path ? b2 : b1;
    const int mco = path * 256;
    const int w    = blockIdx.x * 8 + (threadIdx.x >> 5);
    const int lane = threadIdx.x & 31;
    const __half* th = Th + (size_t)w * 256;
    const float* er = EP + (size_t)w * 256;
    float v[8], sum = 0.f, sq = 0.f;
    #pragma unroll
    for (int i = 0; i < 8; i++) {
        const int c = lane + i * 32;
        const float x = __half2float(th[c]) + er[c];
        v[i] = x; sum += x; sq += x * x;
    }
    #pragma unroll
    for (int o = 16; o; o >>= 1) {
        sum += __shfl_xor_sync(0xffffffffu, sum, o);
        sq  += __shfl_xor_sync(0xffffffffu, sq,  o);
    }
    const float mean = sum * (1.f / 256.f);
    const float var  = sq * (1.f / 256.f) - mean * mean;
    const float rs   = rsqrtf(var + EPSF);
    const size_t ob = (size_t)w * 512 + mco;
    #pragma unroll
    for (int i = 0; i < 8; i++) {
        const int c = lane + i * 32;
        MH[ob + c] = __float2half((v[i] - mean) * rs * g[c] + be[c]);
    }
}

// ------------- 3x3 depthwise conv on [M,ld] layout + bias + relu (fp16 out) --
__global__ void __launch_bounds__(256)
dw_k(const float* __restrict__ X, int ldx, const float* __restrict__ w9,
     const float* __restrict__ db, __half* __restrict__ Y)
{
    __shared__ float s[18 * 18 * 32];
    const int cc   = blockIdx.x;
    const int tile = blockIdx.y;
    const int b    = blockIdx.z;
    const int ty0 = (tile >> 2) * 16, tx0 = (tile & 3) * 16;
    const int c0 = cc * 32;
    const int tid = threadIdx.x;
    for (int i = tid; i < 18 * 18 * 32; i += 256) {
        const int c = i & 31;
        const int sp = i >> 5;
        const int x = sp % 18 - 1 + tx0;
        const int y = sp / 18 - 1 + ty0;
        float v = 0.f;
        if (x >= 0 && x < 64 && y >= 0 && y < 64)
            v = X[(size_t)(b * 4096 + y * 64 + x) * ldx + c0 + c];
        s[i] = v;
    }
    const int c = tid & 31;
    float kr[9];
    #pragma unroll
    for (int j = 0; j < 9; j++) kr[j] = w9[(c0 + c) * 9 + j];
    const float bb = db[c0 + c];
    __syncthreads();
    for (int o = tid; o < 8192; o += 256) {
        const int sp = o >> 5;
        const int x = sp & 15, y = sp >> 4;
        float a = 0.f;
        #pragma unroll
        for (int dy = 0; dy < 3; dy++)
            #pragma unroll
            for (int dx = 0; dx < 3; dx++)
                a = fmaf(s[((y + dy) * 18 + (x + dx)) * 32 + c], kr[dy * 3 + dx], a);
        a = fmaxf(a + bb, 0.f);
        const size_t idx = (size_t)(b * 4096 + (ty0 + y) * 64 + tx0 + x) * 256 + c0 + c;
        Y[idx] = __float2half(a);
    }
}

// ------------- BN stats on [M,256] fp32: two-stage ---------------------------
__global__ void __launch_bounds__(256)
bn_part_k(const float* __restrict__ X, float* __restrict__ part)
{
    const int seg = blockIdx.x;
    const int c   = threadIdx.x;
    const float* p = X + (size_t)seg * 256 * 256;
    float s = 0.f, q = 0.f;
    #pragma unroll 8
    for (int r = 0; r < 256; r++) {
        const float v = p[(size_t)r * 256 + c];
        s += v; q = fmaf(v, v, q);
    }
    part[seg * 512 + c] = s;
    part[seg * 512 + 256 + c] = q;
}

__global__ void bn_fin_k(const float* __restrict__ part, const float* __restrict__ g,
                         const float* __restrict__ be, float* __restrict__ sc,
                         float* __restrict__ sh)
{
    const int c = threadIdx.x;
    float s = 0.f, q = 0.f;
    for (int seg = 0; seg < 256; seg++) {
        s += part[seg * 512 + c];
        q += part[seg * 512 + 256 + c];
    }
    const float inv = 1.f / 65536.f;
    const float m   = s * inv;
    const float var = q * inv - m * m;
    const float scv = g[c] * rsqrtf(var + EPSF);
    sc[c] = scv;
    sh[c] = be[c] - m * scv;
}

// ------------- F = RES(RC col0-255) + E*sc + sh ------------------------------
__global__ void addbn_k(const float* __restrict__ RC, const float* __restrict__ E,
                        const float* __restrict__ sc, const float* __restrict__ sh,
                        float* __restrict__ F)
{
    const int i4 = blockIdx.x * 256 + threadIdx.x;
    const int r  = i4 >> 6;
    const int c0 = (i4 & 63) * 4;
    const float4 s = *reinterpret_cast<const float4*>(sc + c0);
    const float4 h = *reinterpret_cast<const float4*>(sh + c0);
    const float4 rr = *reinterpret_cast<const float4*>(RC + (size_t)r * 512 + c0);
    const float4 e = reinterpret_cast<const float4*>(E)[i4];
    float4 f;
    f.x = fmaf(e.x, s.x, rr.x + h.x);
    f.y = fmaf(e.y, s.y, rr.y + h.y);
    f.z = fmaf(e.z, s.z, rr.z + h.z);
    f.w = fmaf(e.w, s.w, rr.w + h.w);
    reinterpret_cast<float4*>(F)[i4] = f;
}

// ------------- final: out NCHW = bn2(F) via transpose ------------------------
__global__ void bn_final_k(const float* __restrict__ F, const float* __restrict__ sc,
                           const float* __restrict__ sh, float* __restrict__ O)
{
    __shared__ float s[32][33];
    const int b  = blockIdx.z;
    const int c0 = blockIdx.y * 32;
    const int n0 = blockIdx.x * 32;
    const int tx = threadIdx.x, ty = threadIdx.y;
    #pragma unroll
    for (int i = 0; i < 32; i += 8)
        s[ty + i][tx] = F[((size_t)(b * 4096 + n0 + ty + i)) * 256 + c0 + tx];
    __syncthreads();
    #pragma unroll
    for (int i = 0; i < 32; i += 8) {
        const int c = c0 + ty + i;
        O[((size_t)(b * 256 + c)) * 4096 + n0 + tx] = s[tx][ty + i] * sc[c] + sh[c];
    }
}

// ===========================================================================
extern "C" void kernel_launch(void* const* d_in, const int* in_sizes, int n_in,
                              void* d_out, int out_size)
{
    (void)in_sizes; (void)n_in; (void)out_size;
    const float* x1    = (const float*)d_in[0];
    const float* x2    = (const float*)d_in[1];
    const float* cp1_w = (const float*)d_in[2];
    const float* cp1_b = (const float*)d_in[3];
    const float* cp2_w = (const float*)d_in[4];
    const float* cp2_b = (const float*)d_in[5];
    const float* kv1_w = (const float*)d_in[6];
    const float* kv2_w = (const float*)d_in[7];
    const float* ep1_w = (const float*)d_in[8];
    const float* ep1_b = (const float*)d_in[9];
    const float* ep2_w = (const float*)d_in[10];
    const float* ep2_b = (const float*)d_in[11];
    const float* ln1_g = (const float*)d_in[12];
    const float* ln1_b = (const float*)d_in[13];
    const float* ln2_g = (const float*)d_in[14];
    const float* ln2_b = (const float*)d_in[15];
    const float* res_w = (const float*)d_in[16];
    const float* ce1_w = (const float*)d_in[17];
    const float* ce1_b = (const float*)d_in[18];
    const float* dw_w  = (const float*)d_in[19];
    const float* dw_b  = (const float*)d_in[20];
    const float* ce3_w = (const float*)d_in[21];
    const float* ce3_b = (const float*)d_in[22];
    const float* bn1_g = (const float*)d_in[23];
    const float* bn1_b = (const float*)d_in[24];
    const float* bn2_g = (const float*)d_in[25];
    const float* bn2_b = (const float*)d_in[26];

    float *KV1, *KV2, *EP1, *EP2, *RC, *E, *F;
    float *PART, *CTX1, *CTX2, *CB, *BNP, *SC1, *SH1, *SC2, *SH2;
    __half *T1, *T2, *P1, *P2, *MRG, *DW, *WH, *WL, *EPYh, *EPYl, *MWh, *MWl;
    cudaGetSymbolAddress((void**)&T1,  g_T1);
    cudaGetSymbolAddress((void**)&T2,  g_T2);
    cudaGetSymbolAddress((void**)&P1,  g_P1);
    cudaGetSymbolAddress((void**)&P2,  g_P2);
    cudaGetSymbolAddress((void**)&KV1, g_KV1);
    cudaGetSymbolAddress((void**)&KV2, g_KV2);
    cudaGetSymbolAddress((void**)&EP1, g_EP1);
    cudaGetSymbolAddress((void**)&EP2, g_EP2);
    cudaGetSymbolAddress((void**)&MRG, g_MRG);
    cudaGetSymbolAddress((void**)&RC,  g_RC);
    cudaGetSymbolAddress((void**)&DW,  g_DW);
    cudaGetSymbolAddress((void**)&E,   g_E);
    cudaGetSymbolAddress((void**)&F,   g_F);
    cudaGetSymbolAddress((void**)&WH,  g_WH);
    cudaGetSymbolAddress((void**)&WL,  g_WL);
    cudaGetSymbolAddress((void**)&EPYh, g_EPYh);
    cudaGetSymbolAddress((void**)&EPYl, g_EPYl);
    cudaGetSymbolAddress((void**)&MWh, g_MWh);
    cudaGetSymbolAddress((void**)&MWl, g_MWl);
    cudaGetSymbolAddress((void**)&PART, g_PART);
    cudaGetSymbolAddress((void**)&CTX1, g_CTX1);
    cudaGetSymbolAddress((void**)&CTX2, g_CTX2);
    cudaGetSymbolAddress((void**)&CB,  g_CB);
    cudaGetSymbolAddress((void**)&BNP, g_BNP);
    cudaGetSymbolAddress((void**)&SC1, g_SC1);
    cudaGetSymbolAddress((void**)&SH1, g_SH1);
    cudaGetSymbolAddress((void**)&SC2, g_SC2);
    cudaGetSymbolAddress((void**)&SH2, g_SH2);

    cudaFuncSetAttribute(gemm_tc<true,  true,  false, true , false>,
                         cudaFuncAttributeMaxDynamicSharedMemorySize, DYN_SMEM);
    cudaFuncSetAttribute(gemm_tc<false, false, true,  false, false>,
                         cudaFuncAttributeMaxDynamicSharedMemorySize, DYN_SMEM);
    cudaFuncSetAttribute(gemm_tc<true,  false, true,  false, true >,
                         cudaFuncAttributeMaxDynamicSharedMemorySize, DYN_SMEM);
    cudaFuncSetAttribute(gemm_tc<true,  false, true,  false, false>,
                         cudaFuncAttributeMaxDynamicSharedMemorySize, DYN_SMEM);

    // weight slots in WH/WL (851968 total)
    const size_t oCP1 = 0, oCP2 = 131072, oKV1 = 262144, oKV2 = 393216;
    const size_t oRC = 524288, oCE3 = 786432;
    WsplitArgs wa;
    wa.src[0] = cp1_w; wa.src[1] = cp2_w; wa.src[2] = kv1_w; wa.src[3] = kv2_w;
    wa.src[4] = res_w; wa.src[5] = ce1_w; wa.src[6] = ce3_w;

    wsplit_all_k<<<3328, 256>>>(wa, WH, WL);
    wsplit_ep_k<<<dim3(256, 2), 256>>>(ep1_w, ep2_w, EPYh, EPYl);
    transpose_split_k<<<dim3(128, 8, 32), dim3(32, 8)>>>(x1, x2, T1, T2);

    const dim3 g512(4, 512);
    const dim3 g256(2, 512);

    // CrossPath P = relu(T @ cp_w^T + b) -> fp16
    gemm_tc<true, true, false, true, false><<<g512, 256, DYN_SMEM>>>(
        T1, 256, WH + oCP1, WL + oCP1, nullptr, nullptr, cp1_b,
        nullptr, P1, 256, 512);
    gemm_tc<true, true, false, true, false><<<g512, 256, DYN_SMEM>>>(
        T2, 256, WH + oCP2, WL + oCP2, nullptr, nullptr, cp2_b,
        nullptr, P2, 256, 512);

    // KV = u @ kv_w^T -> fp32
    gemm_tc<false, false, true, false, false><<<g512, 256, DYN_SMEM>>>(
        P1 + 256, 512, WH + oKV1, WL + oKV1, nullptr, nullptr, nullptr,
        KV1, nullptr, 256, 512);
    gemm_tc<false, false, true, false, false><<<g512, 256, DYN_SMEM>>>(
        P2 + 256, 512, WH + oKV2, WL + oKV2, nullptr, nullptr, nullptr,
        KV2, nullptr, 256, 512);

    // ctx = softmax_d(scale * K^T V), both paths
    ctx_partial_k<<<dim3(8, 8, 32), 64>>>(KV1, KV2, PART);
    ctx_final_k<<<256, 256>>>(PART, CTX1, CTX2);

    // per-batch M weights for the fused ep GEMM (cross-wired)
    ctxw_k<<<32, 256>>>(CTX1, CTX2, ep1_w, ep2_w, MWh, MWl);

    // EP = y @ W1 + u @ M_b + bias (dual-source B)
    gemm_tc<true, false, true, false, true><<<g256, 256, DYN_SMEM>>>(
        P1, 512, EPYh, EPYl, MWh, MWl, ep1_b,
        EP1, nullptr, 512, 256);
    gemm_tc<true, false, true, false, true><<<g256, 256, DYN_SMEM>>>(
        P2, 512, EPYh + 65536, EPYl + 65536, MWh + 16 * 65536, MWl + 16 * 65536,
        ep2_b, EP2, nullptr, 512, 256);

    // LN both paths -> MRG fp16
    ln_k<<<dim3(8192, 2), 256>>>(T1, T2, EP1, EP2,
                                 ln1_g, ln1_b, ln2_g, ln2_b, MRG);

    // bias concat (0 | ce1_b)
    biascat_k<<<2, 256>>>(ce1_b, CB);

    // res|ce1 concatenated GEMM -> RC [M, 512]
    gemm_tc<true, false, true, false, false><<<g512, 256, DYN_SMEM>>>(
        MRG, 512, WH + oRC, WL + oRC, nullptr, nullptr, CB,
        RC, nullptr, 512, 512);

    // 3x3 depthwise (+bias+relu) on CE1 half of RC -> DW fp16
    dw_k<<<dim3(8, 16, 16), 256>>>(RC + 256, 512, dw_w, dw_b, DW);

    // ce3 GEMM -> E
    gemm_tc<true, false, true, false, false><<<g256, 256, DYN_SMEM>>>(
        DW, 256, WH + oCE3, WL + oCE3, nullptr, nullptr, ce3_b,
        E, nullptr, 256, 256);

    // bn1 -> residual add -> bn2 -> final NCHW
    bn_part_k<<<256, 256>>>(E, BNP);
    bn_fin_k<<<1, 256>>>(BNP, bn1_g, bn1_b, SC1, SH1);
    addbn_k<<<16384, 256>>>(RC, E, SC1, SH1, F);
    bn_part_k<<<256, 256>>>(F, BNP);
    bn_fin_k<<<1, 256>>>(BNP, bn2_g, bn2_b, SC2, SH2);
    bn_final_k<<<dim3(128, 8, 16), dim3(32, 8)>>>(F, SC2, SH2, (float*)d_out);
}